// round 2
// baseline (speedup 1.0000x reference)
#include <cuda_runtime.h>
#include <math.h>

// Problem constants (fixed by the reference): B=2, C=256, N=65536.
#define NE 65536
#define NB 2

// ---------------- scratch (device globals; no allocations) ----------------
// x_all stored TRANSPOSED: g_Xt[b][e][c], c=0..127  (gathers become 512B contiguous rows)
__device__ float g_Xt[(size_t)NB * NE * 128];
// stacked pre-activation: rows 0..255 = a-branch, 256..511 = b-branch: g_pre[b][r][e]
__device__ float g_pre[(size_t)NB * 512 * NE];
// folded weights: g_Wf[k][r][c], k=0..4 (k0 folds local+self, k1..4 the symmetric features)
__device__ float g_Wf[5 * 512 * 128];
__device__ float g_Cf[512];
__device__ float g_mean[NB * 512];
__device__ float g_rstd[NB * 512];

// ---------------- kernel 0a: fold weight matrices ----------------
// A0 = Waf[:, :128] @ Wal + Waf[:,128:] @ Wat[:,:,0]
// Ak = Waf[:,128:] @ Wat[:,:,k]  (k=1..4);   b-branch likewise, rows 256..511
__global__ void fold_w_kernel(const float* __restrict__ Waf, const float* __restrict__ Wal,
                              const float* __restrict__ Wat,
                              const float* __restrict__ Wbf, const float* __restrict__ Wbl,
                              const float* __restrict__ Wbt) {
    int r = blockIdx.x;       // 0..511
    int c = threadIdx.x;      // 0..127
    const float *F, *L, *T;
    if (r < 256) { F = Waf; L = Wal; T = Wat; } else { F = Wbf; L = Wbl; T = Wbt; }
    int rr = r & 255;
    float a0 = 0.f, a1 = 0.f, a2 = 0.f, a3 = 0.f, a4 = 0.f;
    for (int j = 0; j < 128; j++) {
        float fl = F[rr * 256 + j];
        float fr = F[rr * 256 + 128 + j];
        a0 += fl * L[j * 128 + c];
        const float* t = &T[(j * 128 + c) * 5];
        a0 += fr * t[0];
        a1 += fr * t[1];
        a2 += fr * t[2];
        a3 += fr * t[3];
        a4 += fr * t[4];
    }
    g_Wf[(0 * 512 + r) * 128 + c] = a0;
    g_Wf[(1 * 512 + r) * 128 + c] = a1;
    g_Wf[(2 * 512 + r) * 128 + c] = a2;
    g_Wf[(3 * 512 + r) * 128 + c] = a3;
    g_Wf[(4 * 512 + r) * 128 + c] = a4;
}

// ---------------- kernel 0b: fold bias ----------------
// c = Waf_L @ bal + Waf_R @ bat + baf  (b-branch likewise)
__global__ void fold_c_kernel(const float* __restrict__ Waf, const float* __restrict__ bal,
                              const float* __restrict__ bat, const float* __restrict__ baf,
                              const float* __restrict__ Wbf, const float* __restrict__ bbl,
                              const float* __restrict__ bbt, const float* __restrict__ bbf) {
    int r = threadIdx.x;  // 0..511 (one block of 512)
    const float *F, *lb, *tb, *fb;
    if (r < 256) { F = Waf; lb = bal; tb = bat; fb = baf; }
    else         { F = Wbf; lb = bbl; tb = bbt; fb = bbf; }
    int rr = r & 255;
    float s = fb[rr];
    for (int j = 0; j < 128; j++)
        s += F[rr * 256 + j] * lb[j] + F[rr * 256 + 128 + j] * tb[j];
    g_Cf[r] = s;
}

// ---------------- kernel 1: x_all = [Wa@x0+ba ; Wb@x1+bb], stored transposed ----------------
// grid (NE/64, batch, half); block 256. Tile M=64 rows, E=64 edges, K=256 in 4 chunks.
__global__ __launch_bounds__(256) void stage1_kernel(
    const float* __restrict__ x0, const float* __restrict__ x1,
    const float* __restrict__ Wa, const float* __restrict__ ba,
    const float* __restrict__ Wb, const float* __restrict__ bb) {
    __shared__ float Ws[64][64];
    __shared__ float xs[64][65];

    int e0 = blockIdx.x * 64;
    int b = blockIdx.y;
    int half = blockIdx.z;
    const float* X = (half == 0) ? x0 : x1;
    const float* W = (half == 0) ? Wa : Wb;
    const float* bias = (half == 0) ? ba : bb;
    X += (size_t)b * 256 * NE;

    int tid = threadIdx.x;
    int er = tid & 15;   // 4 edges each
    int mr = tid >> 4;   // 4 rows each

    float acc[4][4];
#pragma unroll
    for (int i = 0; i < 4; i++)
#pragma unroll
        for (int e = 0; e < 4; e++) acc[i][e] = 0.f;

    for (int kc = 0; kc < 4; kc++) {
        __syncthreads();
        // load W chunk (64 rows x 64 k), rows contiguous in k
        for (int i = tid; i < 64 * 16; i += 256) {
            int r = i >> 4, kq = i & 15;
            *(float4*)&Ws[r][kq * 4] = *(const float4*)&W[r * 256 + kc * 64 + kq * 4];
        }
        // load x chunk (64 k x 64 e), coalesced along e
        for (int i = tid; i < 64 * 64; i += 256) {
            int kk = i >> 6, e = i & 63;
            xs[kk][e] = X[(size_t)(kc * 64 + kk) * NE + e0 + e];
        }
        __syncthreads();
#pragma unroll
        for (int kk = 0; kk < 64; kk += 4) {
            float xv[4][4];
#pragma unroll
            for (int j = 0; j < 4; j++)
#pragma unroll
                for (int ei = 0; ei < 4; ei++) xv[j][ei] = xs[kk + j][er * 4 + ei];
#pragma unroll
            for (int i = 0; i < 4; i++) {
                float4 w = *(float4*)&Ws[mr * 4 + i][kk];
#pragma unroll
                for (int ei = 0; ei < 4; ei++)
                    acc[i][ei] += w.x * xv[0][ei] + w.y * xv[1][ei] + w.z * xv[2][ei] + w.w * xv[3][ei];
            }
        }
    }

    float bv[4];
#pragma unroll
    for (int i = 0; i < 4; i++) bv[i] = bias[mr * 4 + i];

    float* dst = g_Xt + (size_t)b * NE * 128;
#pragma unroll
    for (int ei = 0; ei < 4; ei++) {
        int e = e0 + er * 4 + ei;
        float4 v = make_float4(acc[0][ei] + bv[0], acc[1][ei] + bv[1],
                               acc[2][ei] + bv[2], acc[3][ei] + bv[3]);
        *(float4*)&dst[(size_t)e * 128 + half * 64 + mr * 4] = v;
    }
}

// ---------------- kernel 2: fused mesh+local+fuse GEMM ----------------
// pre[b][r][e] = Cf[r] + W0@x_all + W1@(f1+f3) + W2@(f2+f4) + W3@|f1-f3| + W4@|f2-f4|
// grid (NE/64, batch, mhalf); block 256. Tile: M=256 rows, E=64 edges, per-thread 16r x 4e.
#define GS(buf, c, e) Gsm[(buf) * (128 * 65) + (c) * 65 + (e)]

__global__ __launch_bounds__(256, 1) void stage2_kernel(const int* __restrict__ gemm) {
    extern __shared__ float sm[];
    float* Wsm = sm;            // 256 x 128
    float* Gsm = sm + 256 * 128; // 2 x 128 x 65
    __shared__ int nidx[64][4];

    int e0 = blockIdx.x * 64;
    int b = blockIdx.y;
    int mh = blockIdx.z;
    int tid = threadIdx.x;
    int er = tid & 15;   // 4 edges
    int mr = tid >> 4;   // 16 rows

    const float* Xt = g_Xt + (size_t)b * NE * 128;

    // neighbor indices for the tile
    nidx[tid >> 2][tid & 3] = gemm[((size_t)b * NE + e0 + (tid >> 2)) * 4 + (tid & 3)];

    float acc[16][4];
#pragma unroll
    for (int i = 0; i < 16; i++)
#pragma unroll
        for (int e = 0; e < 4; e++) acc[i][e] = 0.f;

    // ---- helpers expanded inline ----
#define LOAD_W(g)                                                                    \
    {                                                                                \
        const float4* src = (const float4*)(g_Wf + ((size_t)(g) * 512 + mh * 256) * 128); \
        float4* dstw = (float4*)Wsm;                                                 \
        for (int i = tid; i < 256 * 32; i += 256) dstw[i] = src[i];                  \
    }

#define LOAD_SELF()                                                                  \
    {                                                                                \
        for (int i = tid; i < 64 * 32; i += 256) {                                   \
            int e = i >> 5, cq = i & 31;                                             \
            float4 v = *(const float4*)&Xt[(size_t)(e0 + e) * 128 + cq * 4];         \
            GS(0, cq * 4 + 0, e) = v.x;                                              \
            GS(0, cq * 4 + 1, e) = v.y;                                              \
            GS(0, cq * 4 + 2, e) = v.z;                                              \
            GS(0, cq * 4 + 3, e) = v.w;                                              \
        }                                                                            \
    }

#define LOAD_PAIR(p)                                                                 \
    {                                                                                \
        for (int i = tid; i < 64 * 32; i += 256) {                                   \
            int e = i >> 5, cq = i & 31;                                             \
            int na = nidx[e][(p)];                                                   \
            int nc = nidx[e][(p) + 2];                                               \
            float4 va = *(const float4*)&Xt[(size_t)na * 128 + cq * 4];              \
            float4 vb = *(const float4*)&Xt[(size_t)nc * 128 + cq * 4];              \
            GS(0, cq * 4 + 0, e) = va.x + vb.x;                                      \
            GS(0, cq * 4 + 1, e) = va.y + vb.y;                                      \
            GS(0, cq * 4 + 2, e) = va.z + vb.z;                                      \
            GS(0, cq * 4 + 3, e) = va.w + vb.w;                                      \
            GS(1, cq * 4 + 0, e) = fabsf(va.x - vb.x);                               \
            GS(1, cq * 4 + 1, e) = fabsf(va.y - vb.y);                               \
            GS(1, cq * 4 + 2, e) = fabsf(va.z - vb.z);                               \
            GS(1, cq * 4 + 3, e) = fabsf(va.w - vb.w);                               \
        }                                                                            \
    }

#define GEMM_ACC(buf)                                                                \
    {                                                                                \
        _Pragma("unroll 1") for (int kk = 0; kk < 128; kk += 4) {                    \
            float gv[4][4];                                                          \
            _Pragma("unroll") for (int j = 0; j < 4; j++)                            \
                _Pragma("unroll") for (int ei = 0; ei < 4; ei++)                     \
                    gv[j][ei] = GS(buf, kk + j, er * 4 + ei);                        \
            _Pragma("unroll") for (int i = 0; i < 16; i++) {                         \
                float4 w = *(float4*)&Wsm[(mr * 16 + i) * 128 + kk];                 \
                _Pragma("unroll") for (int ei = 0; ei < 4; ei++)                     \
                    acc[i][ei] += w.x * gv[0][ei] + w.y * gv[1][ei] +                \
                                  w.z * gv[2][ei] + w.w * gv[3][ei];                 \
            }                                                                        \
        }                                                                            \
    }

    // group 0: self feature
    LOAD_SELF();
    LOAD_W(0);
    __syncthreads();
    GEMM_ACC(0);
    __syncthreads();

    // pair 0 -> features k=1 (sum) and k=3 (absdiff)
    LOAD_PAIR(0);
    LOAD_W(1);
    __syncthreads();
    GEMM_ACC(0);
    __syncthreads();
    LOAD_W(3);
    __syncthreads();
    GEMM_ACC(1);
    __syncthreads();

    // pair 1 -> features k=2 and k=4
    LOAD_PAIR(1);
    LOAD_W(2);
    __syncthreads();
    GEMM_ACC(0);
    __syncthreads();
    LOAD_W(4);
    __syncthreads();
    GEMM_ACC(1);

    // bias + store
    int rbase = mh * 256 + mr * 16;
#pragma unroll
    for (int i = 0; i < 16; i++) {
        float cr = g_Cf[rbase + i];
        float4 v = make_float4(acc[i][0] + cr, acc[i][1] + cr, acc[i][2] + cr, acc[i][3] + cr);
        *(float4*)&g_pre[((size_t)b * 512 + rbase + i) * NE + e0 + er * 4] = v;
    }
}

// ---------------- kernel 3: instance-norm statistics ----------------
__global__ __launch_bounds__(256) void stats_kernel() {
    int br = blockIdx.x;  // 0..1023 = b*512 + r
    const float4* p = (const float4*)(g_pre + (size_t)br * NE);
    int tid = threadIdx.x;
    float s = 0.f, s2 = 0.f;
    for (int i = tid; i < NE / 4; i += 256) {
        float4 v = p[i];
        s += v.x + v.y + v.z + v.w;
        s2 += v.x * v.x + v.y * v.y + v.z * v.z + v.w * v.w;
    }
    __shared__ float ss[256], sq[256];
    ss[tid] = s; sq[tid] = s2;
    __syncthreads();
    for (int st = 128; st > 0; st >>= 1) {
        if (tid < st) { ss[tid] += ss[tid + st]; sq[tid] += sq[tid + st]; }
        __syncthreads();
    }
    if (tid == 0) {
        float mean = ss[0] / (float)NE;
        float var = sq[0] / (float)NE - mean * mean;
        g_mean[br] = mean;
        g_rstd[br] = rsqrtf(var + 1e-5f);
    }
}

// ---------------- kernel 4: fused norm + sigmoid + softmax blend ----------------
__global__ __launch_bounds__(256) void final_kernel(const float* __restrict__ x0,
                                                    const float* __restrict__ x1,
                                                    float* __restrict__ out) {
    size_t idx = (size_t)blockIdx.x * 256 + threadIdx.x;  // float4 index; total = 2*256*NE/4
    int e4 = (int)(idx & (NE / 4 - 1));
    int c = (int)((idx >> 14) & 255);
    int b = (int)(idx >> 22);

    float4 pa = ((const float4*)g_pre)[((size_t)b * 512 + c) * (NE / 4) + e4];
    float4 pb = ((const float4*)g_pre)[((size_t)b * 512 + 256 + c) * (NE / 4) + e4];
    float4 a0 = ((const float4*)x0)[idx];
    float4 a1 = ((const float4*)x1)[idx];

    float ma = g_mean[b * 512 + c], ra = g_rstd[b * 512 + c];
    float mb = g_mean[b * 512 + 256 + c], rb = g_rstd[b * 512 + 256 + c];

    float4 o;
#define BLEND(fld)                                              \
    {                                                           \
        float za = (pa.fld - ma) * ra;                          \
        float zb = (pb.fld - mb) * rb;                          \
        float wa = 1.f / (1.f + expf(-za));                     \
        float wb = 1.f / (1.f + expf(-zb));                     \
        float w0 = 1.f / (1.f + expf(wb - wa));                 \
        o.fld = a0.fld * w0 + a1.fld * (1.f - w0);              \
    }
    BLEND(x); BLEND(y); BLEND(z); BLEND(w);
#undef BLEND
    ((float4*)out)[idx] = o;
}

// ---------------- launch ----------------
extern "C" void kernel_launch(void* const* d_in, const int* in_sizes, int n_in,
                              void* d_out, int out_size) {
    const float* x0  = (const float*)d_in[0];
    const float* x1  = (const float*)d_in[1];
    const int*   gm  = (const int*)d_in[2];
    const float* Wa  = (const float*)d_in[3];
    const float* ba  = (const float*)d_in[4];
    const float* Wb  = (const float*)d_in[5];
    const float* bb  = (const float*)d_in[6];
    const float* Wal = (const float*)d_in[7];
    const float* bal = (const float*)d_in[8];
    const float* Wbl = (const float*)d_in[9];
    const float* bbl = (const float*)d_in[10];
    const float* Wat = (const float*)d_in[11];
    const float* bat = (const float*)d_in[12];
    const float* Wbt = (const float*)d_in[13];
    const float* bbt = (const float*)d_in[14];
    const float* Waf = (const float*)d_in[15];
    const float* baf = (const float*)d_in[16];
    const float* Wbf = (const float*)d_in[17];
    const float* bbf = (const float*)d_in[18];
    float* out = (float*)d_out;

    // fold weights (cheap, recomputed every call for determinism)
    fold_w_kernel<<<512, 128>>>(Waf, Wal, Wat, Wbf, Wbl, Wbt);
    fold_c_kernel<<<1, 512>>>(Waf, bal, bat, baf, Wbf, bbl, bbt, bbf);

    // stage 1: x_all (transposed)
    stage1_kernel<<<dim3(NE / 64, NB, 2), 256>>>(x0, x1, Wa, ba, Wb, bb);

    // stage 2: fused GEMM (dynamic smem 193 KB)
    int smem2 = (256 * 128 + 2 * 128 * 65) * (int)sizeof(float);
    cudaFuncSetAttribute(stage2_kernel, cudaFuncAttributeMaxDynamicSharedMemorySize, smem2);
    stage2_kernel<<<dim3(NE / 64, NB, 2), 256, smem2>>>(gm);

    // stage 3: instance norm stats
    stats_kernel<<<NB * 512, 256>>>();

    // stage 4: fused epilogue
    final_kernel<<<(NB * 256 * (NE / 4)) / 256, 256>>>(x0, x1, out);
}

// round 5
// speedup vs baseline: 2.1016x; 2.1016x over previous
#include <cuda_runtime.h>
#include <cuda_bf16.h>
#include <math.h>
#include <stdint.h>

// Problem constants: B=2, C=256, N=65536.
#define NE 65536
#define NB 2

// ---------------- scratch (device globals; no allocations) ----------------
__device__ float g_Xt[(size_t)NB * NE * 128];          // x_all transposed [b][e][c]
__device__ float g_pre[(size_t)NB * 512 * NE];         // pre-activations [b][r][e]
__device__ __align__(16) __nv_bfloat16 g_Wh[5 * 512 * 128];  // folded W, bf16 hi
__device__ __align__(16) __nv_bfloat16 g_Wl[5 * 512 * 128];  // folded W, bf16 lo
__device__ float g_Cf[512];
__device__ float g_mean[NB * 512];
__device__ float g_rstd[NB * 512];

// ================= helpers =================
__device__ __forceinline__ uint32_t smem_u32(const void* p) {
    uint32_t a;
    asm("{ .reg .u64 t; cvta.to.shared.u64 t, %1; cvt.u32.u64 %0, t; }" : "=r"(a) : "l"(p));
    return a;
}

__device__ __forceinline__ void ldsm4(uint32_t* r, uint32_t addr) {
    asm volatile("ldmatrix.sync.aligned.m8n8.x4.shared.b16 {%0, %1, %2, %3}, [%4];"
                 : "=r"(r[0]), "=r"(r[1]), "=r"(r[2]), "=r"(r[3]) : "r"(addr));
}
__device__ __forceinline__ void ldsm2(uint32_t* r, uint32_t addr) {
    asm volatile("ldmatrix.sync.aligned.m8n8.x2.shared.b16 {%0, %1}, [%2];"
                 : "=r"(r[0]), "=r"(r[1]) : "r"(addr));
}
__device__ __forceinline__ void mma_bf16(float* d, const uint32_t* a, const uint32_t* b) {
    asm volatile(
        "mma.sync.aligned.m16n8k16.row.col.f32.bf16.bf16.f32 "
        "{%0,%1,%2,%3}, {%4,%5,%6,%7}, {%8,%9}, {%0,%1,%2,%3};"
        : "+f"(d[0]), "+f"(d[1]), "+f"(d[2]), "+f"(d[3])
        : "r"(a[0]), "r"(a[1]), "r"(a[2]), "r"(a[3]), "r"(b[0]), "r"(b[1]));
}

#define CPA(dst, src) \
    asm volatile("cp.async.ca.shared.global [%0], [%1], 16;" :: "r"(dst), "l"(src))
#define CPA_COMMIT() asm volatile("cp.async.commit_group;" ::: "memory")
#define CPA_WAIT() asm volatile("cp.async.wait_group 0;" ::: "memory")

// pack 8 floats -> 8 bf16 hi + 8 bf16 lo (residual)
__device__ __forceinline__ void pack8(const float* f, uint4& h, uint4& l) {
    unsigned hw[4], lw[4];
#pragma unroll
    for (int j = 0; j < 4; j++) {
        __nv_bfloat16 h0 = __float2bfloat16(f[2 * j]);
        __nv_bfloat16 h1 = __float2bfloat16(f[2 * j + 1]);
        __nv_bfloat16 l0 = __float2bfloat16(f[2 * j] - __bfloat162float(h0));
        __nv_bfloat16 l1 = __float2bfloat16(f[2 * j + 1] - __bfloat162float(h1));
        hw[j] = (unsigned)__bfloat16_as_ushort(h0) | ((unsigned)__bfloat16_as_ushort(h1) << 16);
        lw[j] = (unsigned)__bfloat16_as_ushort(l0) | ((unsigned)__bfloat16_as_ushort(l1) << 16);
    }
    h = make_uint4(hw[0], hw[1], hw[2], hw[3]);
    l = make_uint4(lw[0], lw[1], lw[2], lw[3]);
}

// ---------------- kernel 0a: fold weight matrices (emit bf16 hi/lo) ----------------
__global__ void fold_w_kernel(const float* __restrict__ Waf, const float* __restrict__ Wal,
                              const float* __restrict__ Wat,
                              const float* __restrict__ Wbf, const float* __restrict__ Wbl,
                              const float* __restrict__ Wbt) {
    int r = blockIdx.x;   // 0..511
    int c = threadIdx.x;  // 0..127
    const float *F, *L, *T;
    if (r < 256) { F = Waf; L = Wal; T = Wat; } else { F = Wbf; L = Wbl; T = Wbt; }
    int rr = r & 255;
    float a[5] = {0.f, 0.f, 0.f, 0.f, 0.f};
    for (int j = 0; j < 128; j++) {
        float fl = F[rr * 256 + j];
        float fr = F[rr * 256 + 128 + j];
        a[0] += fl * L[j * 128 + c];
        const float* t = &T[(j * 128 + c) * 5];
        a[0] += fr * t[0];
        a[1] += fr * t[1];
        a[2] += fr * t[2];
        a[3] += fr * t[3];
        a[4] += fr * t[4];
    }
#pragma unroll
    for (int g = 0; g < 5; g++) {
        int idx = (g * 512 + r) * 128 + c;
        __nv_bfloat16 h = __float2bfloat16(a[g]);
        g_Wh[idx] = h;
        g_Wl[idx] = __float2bfloat16(a[g] - __bfloat162float(h));
    }
}

// ---------------- kernel 0b: fold bias ----------------
__global__ void fold_c_kernel(const float* __restrict__ Waf, const float* __restrict__ bal,
                              const float* __restrict__ bat, const float* __restrict__ baf,
                              const float* __restrict__ Wbf, const float* __restrict__ bbl,
                              const float* __restrict__ bbt, const float* __restrict__ bbf) {
    int r = threadIdx.x;
    const float *F, *lb, *tb, *fb;
    if (r < 256) { F = Waf; lb = bal; tb = bat; fb = baf; }
    else         { F = Wbf; lb = bbl; tb = bbt; fb = bbf; }
    int rr = r & 255;
    float s = fb[rr];
    for (int j = 0; j < 128; j++)
        s += F[rr * 256 + j] * lb[j] + F[rr * 256 + 128 + j] * tb[j];
    g_Cf[r] = s;
}

// ---------------- kernel 1: x_all = [Wa@x0+ba ; Wb@x1+bb], stored transposed ----------------
__global__ __launch_bounds__(256) void stage1_kernel(
    const float* __restrict__ x0, const float* __restrict__ x1,
    const float* __restrict__ Wa, const float* __restrict__ ba,
    const float* __restrict__ Wb, const float* __restrict__ bb) {
    __shared__ float Ws[64][64];
    __shared__ float xs[64][65];

    int e0 = blockIdx.x * 64;
    int b = blockIdx.y;
    int half = blockIdx.z;
    const float* X = (half == 0) ? x0 : x1;
    const float* W = (half == 0) ? Wa : Wb;
    const float* bias = (half == 0) ? ba : bb;
    X += (size_t)b * 256 * NE;

    int tid = threadIdx.x;
    int er = tid & 15;
    int mr = tid >> 4;

    float acc[4][4];
#pragma unroll
    for (int i = 0; i < 4; i++)
#pragma unroll
        for (int e = 0; e < 4; e++) acc[i][e] = 0.f;

    for (int kc = 0; kc < 4; kc++) {
        __syncthreads();
        for (int i = tid; i < 64 * 16; i += 256) {
            int r = i >> 4, kq = i & 15;
            *(float4*)&Ws[r][kq * 4] = *(const float4*)&W[r * 256 + kc * 64 + kq * 4];
        }
        for (int i = tid; i < 64 * 64; i += 256) {
            int kk = i >> 6, e = i & 63;
            xs[kk][e] = X[(size_t)(kc * 64 + kk) * NE + e0 + e];
        }
        __syncthreads();
#pragma unroll
        for (int kk = 0; kk < 64; kk += 4) {
            float xv[4][4];
#pragma unroll
            for (int j = 0; j < 4; j++)
#pragma unroll
                for (int ei = 0; ei < 4; ei++) xv[j][ei] = xs[kk + j][er * 4 + ei];
#pragma unroll
            for (int i = 0; i < 4; i++) {
                float4 w = *(float4*)&Ws[mr * 4 + i][kk];
#pragma unroll
                for (int ei = 0; ei < 4; ei++)
                    acc[i][ei] += w.x * xv[0][ei] + w.y * xv[1][ei] + w.z * xv[2][ei] + w.w * xv[3][ei];
            }
        }
    }

    float bv[4];
#pragma unroll
    for (int i = 0; i < 4; i++) bv[i] = bias[mr * 4 + i];

    float* dst = g_Xt + (size_t)b * NE * 128;
#pragma unroll
    for (int ei = 0; ei < 4; ei++) {
        int e = e0 + er * 4 + ei;
        float4 v = make_float4(acc[0][ei] + bv[0], acc[1][ei] + bv[1],
                               acc[2][ei] + bv[2], acc[3][ei] + bv[3]);
        *(float4*)&dst[(size_t)e * 128 + half * 64 + mr * 4] = v;
    }
}

// ---------------- kernel 2: fused mesh+local+fuse GEMM (mma.sync bf16 hi/lo) ----------------
// Block: 512 threads (16 warps, 4x4). Tile M=128 (mh quarter of 512) x N=128 edges.
// Warp tile 32x32. 3 split passes per feature, 5 features (self, sum0, diff0, sum1, diff1).
// smem rows padded to 272 B (conflict-free ldmatrix).
#define SM_NIDX  0
#define SM_A_HI  2048
#define SM_A_LO  (SM_A_HI + 34816)
#define SM_BS_HI (SM_A_LO + 34816)
#define SM_BS_LO (SM_BS_HI + 34816)
#define SM_BD_HI (SM_BS_LO + 34816)
#define SM_BD_LO (SM_BD_HI + 34816)
#define SM_TOTAL (SM_BD_LO + 34816)   // 210944 bytes

__global__ __launch_bounds__(512, 1) void stage2_kernel(const int* __restrict__ gemm) {
    extern __shared__ char sm2[];
    uint32_t sb = smem_u32(sm2);
    int tid = threadIdx.x;
    int lane = tid & 31, wid = tid >> 5;
    int wm = wid >> 2, wn = wid & 3;
    int e0 = blockIdx.x * 128;
    int b = blockIdx.y, mh = blockIdx.z;

    int4* nidx = (int4*)(sm2 + SM_NIDX);
    if (tid < 128) nidx[tid] = ((const int4*)gemm)[(size_t)b * NE + e0 + tid];

    const float* Xt = g_Xt + (size_t)b * NE * 128;

    float acc[2][4][4];
#pragma unroll
    for (int mi = 0; mi < 2; mi++)
#pragma unroll
        for (int ni = 0; ni < 4; ni++)
#pragma unroll
            for (int j = 0; j < 4; j++) acc[mi][ni][j] = 0.f;

    // fragment base addresses
    uint32_t aBase = sb + SM_A_HI +
                     (uint32_t)((wm * 32 + (lane & 15)) * 272 + (lane >> 4) * 16);
    uint32_t bOff = (uint32_t)((wn * 32 + (lane & 7)) * 272 + ((lane >> 3) & 1) * 16);

#define LOAD_A_ASYNC(g)                                                               \
    {                                                                                 \
        const __nv_bfloat16* srcH = g_Wh + ((size_t)(g) * 512 + mh * 128) * 128;      \
        const __nv_bfloat16* srcL = g_Wl + ((size_t)(g) * 512 + mh * 128) * 128;      \
        for (int i = tid; i < 2048; i += 512) {                                       \
            int row = i >> 4, cq = i & 15;                                            \
            CPA(sb + SM_A_HI + row * 272 + cq * 16, srcH + row * 128 + cq * 8);       \
            CPA(sb + SM_A_LO + row * 272 + cq * 16, srcL + row * 128 + cq * 8);       \
        }                                                                             \
        CPA_COMMIT();                                                                 \
    }

#define GATHER_SELF()                                                                 \
    {                                                                                 \
        for (int i = tid; i < 2048; i += 512) {                                       \
            int e = i >> 4, cq = i & 15;                                              \
            float f[8];                                                               \
            *(float4*)f = *(const float4*)&Xt[(size_t)(e0 + e) * 128 + cq * 8];       \
            *(float4*)(f + 4) = *(const float4*)&Xt[(size_t)(e0 + e) * 128 + cq * 8 + 4]; \
            uint4 h, l;                                                               \
            pack8(f, h, l);                                                           \
            *(uint4*)(sm2 + SM_BS_HI + e * 272 + cq * 16) = h;                        \
            *(uint4*)(sm2 + SM_BS_LO + e * 272 + cq * 16) = l;                        \
        }                                                                             \
    }

#define GATHER_PAIR(P)                                                                \
    {                                                                                 \
        for (int i = tid; i < 2048; i += 512) {                                       \
            int e = i >> 4, cq = i & 15;                                              \
            int4 nn = nidx[e];                                                        \
            int na = (P) ? nn.y : nn.x;                                               \
            int nc = (P) ? nn.w : nn.z;                                               \
            float fa[8], fb[8];                                                       \
            *(float4*)fa = *(const float4*)&Xt[(size_t)na * 128 + cq * 8];            \
            *(float4*)(fa + 4) = *(const float4*)&Xt[(size_t)na * 128 + cq * 8 + 4];  \
            *(float4*)fb = *(const float4*)&Xt[(size_t)nc * 128 + cq * 8];            \
            *(float4*)(fb + 4) = *(const float4*)&Xt[(size_t)nc * 128 + cq * 8 + 4];  \
            float fs[8], fd[8];                                                       \
            _Pragma("unroll") for (int j = 0; j < 8; j++) {                           \
                fs[j] = fa[j] + fb[j];                                                \
                fd[j] = fabsf(fa[j] - fb[j]);                                         \
            }                                                                         \
            uint4 h, l;                                                               \
            pack8(fs, h, l);                                                          \
            *(uint4*)(sm2 + SM_BS_HI + e * 272 + cq * 16) = h;                        \
            *(uint4*)(sm2 + SM_BS_LO + e * 272 + cq * 16) = l;                        \
            pack8(fd, h, l);                                                          \
            *(uint4*)(sm2 + SM_BD_HI + e * 272 + cq * 16) = h;                        \
            *(uint4*)(sm2 + SM_BD_LO + e * 272 + cq * 16) = l;                        \
        }                                                                             \
    }

#define MMA_FEATURE(BHI, BLO)                                                         \
    {                                                                                 \
        _Pragma("unroll") for (int k16 = 0; k16 < 8; k16++) {                         \
            uint32_t ah[2][4], al[2][4];                                              \
            _Pragma("unroll") for (int mi = 0; mi < 2; mi++) {                        \
                ldsm4(ah[mi], aBase + mi * (16 * 272) + k16 * 32);                    \
                ldsm4(al[mi], aBase + 34816 + mi * (16 * 272) + k16 * 32);            \
            }                                                                         \
            uint32_t bh[4][2], bl[4][2];                                              \
            _Pragma("unroll") for (int ni = 0; ni < 4; ni++) {                        \
                ldsm2(bh[ni], sb + (BHI) + bOff + ni * (8 * 272) + k16 * 32);         \
                ldsm2(bl[ni], sb + (BLO) + bOff + ni * (8 * 272) + k16 * 32);         \
            }                                                                         \
            _Pragma("unroll") for (int mi = 0; mi < 2; mi++)                          \
                _Pragma("unroll") for (int ni = 0; ni < 4; ni++) {                    \
                    mma_bf16(acc[mi][ni], ah[mi], bh[ni]);                            \
                    mma_bf16(acc[mi][ni], ah[mi], bl[ni]);                            \
                    mma_bf16(acc[mi][ni], al[mi], bh[ni]);                            \
                }                                                                     \
        }                                                                             \
    }

    // ---- feature 0: self ----
    LOAD_A_ASYNC(0);
    GATHER_SELF();
    CPA_WAIT();
    __syncthreads();
    MMA_FEATURE(SM_BS_HI, SM_BS_LO);
    __syncthreads();

    // ---- pair 0: sum (W1), diff (W3) ----
    LOAD_A_ASYNC(1);
    GATHER_PAIR(0);
    CPA_WAIT();
    __syncthreads();
    MMA_FEATURE(SM_BS_HI, SM_BS_LO);
    __syncthreads();
    LOAD_A_ASYNC(3);
    CPA_WAIT();
    __syncthreads();
    MMA_FEATURE(SM_BD_HI, SM_BD_LO);
    __syncthreads();

    // ---- pair 1: sum (W2), diff (W4) ----
    LOAD_A_ASYNC(2);
    GATHER_PAIR(1);
    CPA_WAIT();
    __syncthreads();
    MMA_FEATURE(SM_BS_HI, SM_BS_LO);
    __syncthreads();
    LOAD_A_ASYNC(4);
    CPA_WAIT();
    __syncthreads();
    MMA_FEATURE(SM_BD_HI, SM_BD_LO);

    // ---- epilogue: bias + store ----
    int rbase = mh * 128 + wm * 32;
    int colLocal = wn * 32 + (lane & 3) * 2;
#pragma unroll
    for (int mi = 0; mi < 2; mi++) {
        int r0 = rbase + mi * 16 + (lane >> 2);
        int r1 = r0 + 8;
        float c0 = g_Cf[r0], c1 = g_Cf[r1];
        float* d0 = g_pre + ((size_t)b * 512 + r0) * NE + e0 + colLocal;
        float* d1 = g_pre + ((size_t)b * 512 + r1) * NE + e0 + colLocal;
#pragma unroll
        for (int ni = 0; ni < 4; ni++) {
            *(float2*)(d0 + ni * 8) = make_float2(acc[mi][ni][0] + c0, acc[mi][ni][1] + c0);
            *(float2*)(d1 + ni * 8) = make_float2(acc[mi][ni][2] + c1, acc[mi][ni][3] + c1);
        }
    }
}

// ---------------- kernel 3: instance-norm statistics ----------------
__global__ __launch_bounds__(256) void stats_kernel() {
    int br = blockIdx.x;
    const float4* p = (const float4*)(g_pre + (size_t)br * NE);
    int tid = threadIdx.x;
    float s = 0.f, s2 = 0.f;
    for (int i = tid; i < NE / 4; i += 256) {
        float4 v = p[i];
        s += v.x + v.y + v.z + v.w;
        s2 += v.x * v.x + v.y * v.y + v.z * v.z + v.w * v.w;
    }
    __shared__ float ss[256], sq[256];
    ss[tid] = s; sq[tid] = s2;
    __syncthreads();
    for (int st = 128; st > 0; st >>= 1) {
        if (tid < st) { ss[tid] += ss[tid + st]; sq[tid] += sq[tid + st]; }
        __syncthreads();
    }
    if (tid == 0) {
        float mean = ss[0] / (float)NE;
        float var = sq[0] / (float)NE - mean * mean;
        g_mean[br] = mean;
        g_rstd[br] = rsqrtf(var + 1e-5f);
    }
}

// ---------------- kernel 4: fused norm + sigmoid + softmax blend ----------------
__global__ __launch_bounds__(256) void final_kernel(const float* __restrict__ x0,
                                                    const float* __restrict__ x1,
                                                    float* __restrict__ out) {
    size_t idx = (size_t)blockIdx.x * 256 + threadIdx.x;
    int e4 = (int)(idx & (NE / 4 - 1));
    int c = (int)((idx >> 14) & 255);
    int b = (int)(idx >> 22);

    float4 pa = ((const float4*)g_pre)[((size_t)b * 512 + c) * (NE / 4) + e4];
    float4 pb = ((const float4*)g_pre)[((size_t)b * 512 + 256 + c) * (NE / 4) + e4];
    float4 a0 = ((const float4*)x0)[idx];
    float4 a1 = ((const float4*)x1)[idx];

    float ma = g_mean[b * 512 + c], ra = g_rstd[b * 512 + c];
    float mb = g_mean[b * 512 + 256 + c], rb = g_rstd[b * 512 + 256 + c];

    float4 o;
#define BLEND(fld)                                              \
    {                                                           \
        float za = (pa.fld - ma) * ra;                          \
        float zb = (pb.fld - mb) * rb;                          \
        float wa = 1.f / (1.f + expf(-za));                     \
        float wb = 1.f / (1.f + expf(-zb));                     \
        float w0 = 1.f / (1.f + expf(wb - wa));                 \
        o.fld = a0.fld * w0 + a1.fld * (1.f - w0);              \
    }
    BLEND(x); BLEND(y); BLEND(z); BLEND(w);
#undef BLEND
    ((float4*)out)[idx] = o;
}

// ---------------- launch ----------------
extern "C" void kernel_launch(void* const* d_in, const int* in_sizes, int n_in,
                              void* d_out, int out_size) {
    const float* x0  = (const float*)d_in[0];
    const float* x1  = (const float*)d_in[1];
    const int*   gm  = (const int*)d_in[2];
    const float* Wa  = (const float*)d_in[3];
    const float* ba  = (const float*)d_in[4];
    const float* Wb  = (const float*)d_in[5];
    const float* bb  = (const float*)d_in[6];
    const float* Wal = (const float*)d_in[7];
    const float* bal = (const float*)d_in[8];
    const float* Wbl = (const float*)d_in[9];
    const float* bbl = (const float*)d_in[10];
    const float* Wat = (const float*)d_in[11];
    const float* bat = (const float*)d_in[12];
    const float* Wbt = (const float*)d_in[13];
    const float* bbt = (const float*)d_in[14];
    const float* Waf = (const float*)d_in[15];
    const float* baf = (const float*)d_in[16];
    const float* Wbf = (const float*)d_in[17];
    const float* bbf = (const float*)d_in[18];
    float* out = (float*)d_out;

    fold_w_kernel<<<512, 128>>>(Waf, Wal, Wat, Wbf, Wbl, Wbt);
    fold_c_kernel<<<1, 512>>>(Waf, bal, bat, baf, Wbf, bbl, bbt, bbf);

    stage1_kernel<<<dim3(NE / 64, NB, 2), 256>>>(x0, x1, Wa, ba, Wb, bb);

    cudaFuncSetAttribute(stage2_kernel, cudaFuncAttributeMaxDynamicSharedMemorySize, SM_TOTAL);
    stage2_kernel<<<dim3(NE / 128, NB, 4), 512, SM_TOTAL>>>(gm);

    stats_kernel<<<NB * 512, 256>>>();

    final_kernel<<<(NB * 256 * (NE / 4)) / 256, 256>>>(x0, x1, out);
}

// round 6
// speedup vs baseline: 2.5351x; 1.2062x over previous
#include <cuda_runtime.h>
#include <cuda_bf16.h>
#include <math.h>
#include <stdint.h>

// Problem constants: B=2, C=256, N=65536.
#define NE 65536
#define NB 2

// ---------------- scratch (device globals; no allocations) ----------------
__device__ float g_Xt[(size_t)NB * NE * 128];          // x_all transposed [b][e][c]
__device__ float g_pre[(size_t)NB * 512 * NE];         // pre-activations [b][r][e]
__device__ __align__(16) __nv_bfloat16 g_Wh[5 * 512 * 128];  // folded W, bf16 hi
__device__ __align__(16) __nv_bfloat16 g_Wl[5 * 512 * 128];  // folded W, bf16 lo
__device__ float g_Cf[512];
__device__ float g_S[NB * 512];    // row sums (atomic)
__device__ float g_S2[NB * 512];   // row sumsq (atomic)
__device__ float g_mean[NB * 512];
__device__ float g_rstd[NB * 512];

// ================= helpers =================
__device__ __forceinline__ uint32_t smem_u32(const void* p) {
    uint32_t a;
    asm("{ .reg .u64 t; cvta.to.shared.u64 t, %1; cvt.u32.u64 %0, t; }" : "=r"(a) : "l"(p));
    return a;
}
__device__ __forceinline__ void ldsm4(uint32_t* r, uint32_t addr) {
    asm volatile("ldmatrix.sync.aligned.m8n8.x4.shared.b16 {%0, %1, %2, %3}, [%4];"
                 : "=r"(r[0]), "=r"(r[1]), "=r"(r[2]), "=r"(r[3]) : "r"(addr));
}
__device__ __forceinline__ void ldsm2(uint32_t* r, uint32_t addr) {
    asm volatile("ldmatrix.sync.aligned.m8n8.x2.shared.b16 {%0, %1}, [%2];"
                 : "=r"(r[0]), "=r"(r[1]) : "r"(addr));
}
__device__ __forceinline__ void mma_bf16(float* d, const uint32_t* a, const uint32_t* b) {
    asm volatile(
        "mma.sync.aligned.m16n8k16.row.col.f32.bf16.bf16.f32 "
        "{%0,%1,%2,%3}, {%4,%5,%6,%7}, {%8,%9}, {%0,%1,%2,%3};"
        : "+f"(d[0]), "+f"(d[1]), "+f"(d[2]), "+f"(d[3])
        : "r"(a[0]), "r"(a[1]), "r"(a[2]), "r"(a[3]), "r"(b[0]), "r"(b[1]));
}
#define CPA(dst, src) \
    asm volatile("cp.async.ca.shared.global [%0], [%1], 16;" :: "r"(dst), "l"(src))
#define CPA_COMMIT() asm volatile("cp.async.commit_group;" ::: "memory")
#define CPA_WAIT() asm volatile("cp.async.wait_group 0;" ::: "memory")

// pack 8 floats -> 8 bf16 hi + 8 bf16 lo (residual)
__device__ __forceinline__ void pack8(const float* f, uint4& h, uint4& l) {
    unsigned hw[4], lw[4];
#pragma unroll
    for (int j = 0; j < 4; j++) {
        __nv_bfloat16 h0 = __float2bfloat16(f[2 * j]);
        __nv_bfloat16 h1 = __float2bfloat16(f[2 * j + 1]);
        __nv_bfloat16 l0 = __float2bfloat16(f[2 * j] - __bfloat162float(h0));
        __nv_bfloat16 l1 = __float2bfloat16(f[2 * j + 1] - __bfloat162float(h1));
        hw[j] = (unsigned)__bfloat16_as_ushort(h0) | ((unsigned)__bfloat16_as_ushort(h1) << 16);
        lw[j] = (unsigned)__bfloat16_as_ushort(l0) | ((unsigned)__bfloat16_as_ushort(l1) << 16);
    }
    h = make_uint4(hw[0], hw[1], hw[2], hw[3]);
    l = make_uint4(lw[0], lw[1], lw[2], lw[3]);
}

// ---------------- kernel 0a: fold weight matrices (emit bf16 hi/lo) ----------------
__global__ void fold_w_kernel(const float* __restrict__ Waf, const float* __restrict__ Wal,
                              const float* __restrict__ Wat,
                              const float* __restrict__ Wbf, const float* __restrict__ Wbl,
                              const float* __restrict__ Wbt) {
    int r = blockIdx.x;
    int c = threadIdx.x;
    const float *F, *L, *T;
    if (r < 256) { F = Waf; L = Wal; T = Wat; } else { F = Wbf; L = Wbl; T = Wbt; }
    int rr = r & 255;
    float a[5] = {0.f, 0.f, 0.f, 0.f, 0.f};
    for (int j = 0; j < 128; j++) {
        float fl = F[rr * 256 + j];
        float fr = F[rr * 256 + 128 + j];
        a[0] += fl * L[j * 128 + c];
        const float* t = &T[(j * 128 + c) * 5];
        a[0] += fr * t[0];
        a[1] += fr * t[1];
        a[2] += fr * t[2];
        a[3] += fr * t[3];
        a[4] += fr * t[4];
    }
#pragma unroll
    for (int g = 0; g < 5; g++) {
        int idx = (g * 512 + r) * 128 + c;
        __nv_bfloat16 h = __float2bfloat16(a[g]);
        g_Wh[idx] = h;
        g_Wl[idx] = __float2bfloat16(a[g] - __bfloat162float(h));
    }
}

// ---------------- kernel 0b: fold bias + zero stats accumulators ----------------
__global__ void fold_c_kernel(const float* __restrict__ Waf, const float* __restrict__ bal,
                              const float* __restrict__ bat, const float* __restrict__ baf,
                              const float* __restrict__ Wbf, const float* __restrict__ bbl,
                              const float* __restrict__ bbt, const float* __restrict__ bbf) {
    int r = threadIdx.x;
    const float *F, *lb, *tb, *fb;
    if (r < 256) { F = Waf; lb = bal; tb = bat; fb = baf; }
    else         { F = Wbf; lb = bbl; tb = bbt; fb = bbf; }
    int rr = r & 255;
    float s = fb[rr];
    for (int j = 0; j < 128; j++)
        s += F[rr * 256 + j] * lb[j] + F[rr * 256 + 128 + j] * tb[j];
    g_Cf[r] = s;
    g_S[r] = 0.f; g_S[r + 512] = 0.f;
    g_S2[r] = 0.f; g_S2[r + 512] = 0.f;
}

// ---------------- kernel 1: x_all via mma.sync, stored transposed ----------------
// Block 256 (8 warps 2x4). Tile M=64 rows x N=128 edges, K=256 in 4 chunks of 64.
#define S1_AH  0
#define S1_AL  33792            // A: 64 rows x 528B
#define S1_B0H 67584            // B: 128 e x 144B
#define S1_B0L 86016
#define S1_B1H 104448
#define S1_B1L 122880
#define S1_TOT 141312

__global__ __launch_bounds__(256, 1) void stage1_kernel(
    const float* __restrict__ x0, const float* __restrict__ x1,
    const float* __restrict__ Wa, const float* __restrict__ ba,
    const float* __restrict__ Wb, const float* __restrict__ bb) {
    extern __shared__ char sm1[];
    uint32_t sb = smem_u32(sm1);
    int tid = threadIdx.x;
    int lane = tid & 31, wid = tid >> 5;
    int wm = wid >> 2, wn = wid & 3;
    int e0 = blockIdx.x * 128;
    int b = blockIdx.y, half = blockIdx.z;
    const float* X = ((half == 0) ? x0 : x1) + (size_t)b * 256 * NE;
    const float* W = (half == 0) ? Wa : Wb;
    const float* bias = (half == 0) ? ba : bb;

    int eIdx = tid & 127;
    int kbase = (tid >> 7) * 32;

    float acc[2][4][4];
#pragma unroll
    for (int mi = 0; mi < 2; mi++)
#pragma unroll
        for (int ni = 0; ni < 4; ni++)
#pragma unroll
            for (int j = 0; j < 4; j++) acc[mi][ni][j] = 0.f;

    uint32_t aOff = (uint32_t)((wm * 32 + (lane & 15)) * 528 + (lane >> 4) * 16);
    uint32_t bOff = (uint32_t)((wn * 32 + (lane & 7)) * 144 + ((lane >> 3) & 1) * 16);

    // prologue: A (weights) hi/lo
    for (int i = tid; i < 2048; i += 256) {
        int r = i >> 5, kq = i & 31;
        float f[8];
        *(float4*)f = *(const float4*)&W[r * 256 + kq * 8];
        *(float4*)(f + 4) = *(const float4*)&W[r * 256 + kq * 8 + 4];
        uint4 h, l;
        pack8(f, h, l);
        *(uint4*)(sm1 + S1_AH + r * 528 + kq * 16) = h;
        *(uint4*)(sm1 + S1_AL + r * 528 + kq * 16) = l;
    }

#define S1_LDG(KC, G, DST)                                                            \
    {                                                                                 \
        _Pragma("unroll") for (int j = 0; j < 8; j++)                                 \
            DST[j] = X[(size_t)((KC) * 64 + kbase + (G) * 8 + j) * NE + e0 + eIdx];   \
    }
#define S1_PST(BH, BL, G, SRC)                                                        \
    {                                                                                 \
        uint4 h_, l_;                                                                 \
        pack8(SRC, h_, l_);                                                           \
        int k0_ = kbase + (G) * 8;                                                    \
        *(uint4*)(sm1 + (BH) + eIdx * 144 + k0_ * 2) = h_;                            \
        *(uint4*)(sm1 + (BL) + eIdx * 144 + k0_ * 2) = l_;                            \
    }
#define S1_MMA(BH, KC, KK)                                                            \
    {                                                                                 \
        uint32_t ah_[2][4], al_[2][4], bh_[4][2], bl_[4][2];                          \
        _Pragma("unroll") for (int mi = 0; mi < 2; mi++) {                            \
            ldsm4(ah_[mi], sb + S1_AH + aOff + mi * (16 * 528) + (KC) * 128 + (KK) * 32); \
            ldsm4(al_[mi], sb + S1_AL + aOff + mi * (16 * 528) + (KC) * 128 + (KK) * 32); \
        }                                                                             \
        _Pragma("unroll") for (int ni = 0; ni < 4; ni++) {                            \
            ldsm2(bh_[ni], sb + (BH) + bOff + ni * (8 * 144) + (KK) * 32);            \
            ldsm2(bl_[ni], sb + (BH) + 18432 + bOff + ni * (8 * 144) + (KK) * 32);    \
        }                                                                             \
        _Pragma("unroll") for (int mi = 0; mi < 2; mi++)                              \
            _Pragma("unroll") for (int ni = 0; ni < 4; ni++) {                        \
                mma_bf16(acc[mi][ni], ah_[mi], bh_[ni]);                              \
                mma_bf16(acc[mi][ni], ah_[mi], bl_[ni]);                              \
                mma_bf16(acc[mi][ni], al_[mi], bh_[ni]);                              \
            }                                                                         \
    }

    // prologue: B chunk 0
    {
        float gf[8];
#pragma unroll
        for (int g = 0; g < 4; g++) {
            S1_LDG(0, g, gf);
            S1_PST(S1_B0H, S1_B0L, g, gf);
        }
    }
    __syncthreads();

    float gfA[8], gfB[8];
#pragma unroll
    for (int kc = 0; kc < 4; kc++) {
        uint32_t BH = (kc & 1) ? S1_B1H : S1_B0H;
        uint32_t BnH = (kc & 1) ? S1_B0H : S1_B1H;
        uint32_t BnL = BnH + 18432;
        if (kc < 3) { S1_LDG(kc + 1, 0, gfA); S1_LDG(kc + 1, 1, gfB); }
        S1_MMA(BH, kc, 0);
        S1_MMA(BH, kc, 1);
        if (kc < 3) {
            S1_PST(BnH, BnL, 0, gfA); S1_PST(BnH, BnL, 1, gfB);
            S1_LDG(kc + 1, 2, gfA); S1_LDG(kc + 1, 3, gfB);
        }
        S1_MMA(BH, kc, 2);
        S1_MMA(BH, kc, 3);
        if (kc < 3) { S1_PST(BnH, BnL, 2, gfA); S1_PST(BnH, BnL, 3, gfB); }
        __syncthreads();
    }

    // epilogue: bias, transpose through smem, coalesced store
    float* T = (float*)(sm1 + S1_B0H);  // [r][e] stride 132 floats
#pragma unroll
    for (int mi = 0; mi < 2; mi++) {
        int r0 = wm * 32 + mi * 16 + (lane >> 2);
        int r1 = r0 + 8;
        float c0 = bias[r0], c1 = bias[r1];
#pragma unroll
        for (int ni = 0; ni < 4; ni++) {
            int ecol = wn * 32 + ni * 8 + (lane & 3) * 2;
            T[r0 * 132 + ecol] = acc[mi][ni][0] + c0;
            T[r0 * 132 + ecol + 1] = acc[mi][ni][1] + c0;
            T[r1 * 132 + ecol] = acc[mi][ni][2] + c1;
            T[r1 * 132 + ecol + 1] = acc[mi][ni][3] + c1;
        }
    }
    __syncthreads();
    float* dst = g_Xt + (size_t)b * NE * 128;
    for (int i = tid; i < 2048; i += 256) {
        int e = i >> 4, seg = i & 15;
        float4 v = make_float4(T[(seg * 4 + 0) * 132 + e], T[(seg * 4 + 1) * 132 + e],
                               T[(seg * 4 + 2) * 132 + e], T[(seg * 4 + 3) * 132 + e]);
        *(float4*)&dst[(size_t)(e0 + e) * 128 + half * 64 + seg * 4] = v;
    }
}

// ---------------- kernel 2: pipelined fused GEMM + stats ----------------
// Block 512 (16 warps 4x4). Tile M=128 x N=128 edges. 10 phases (5 features x 2 khalves).
// A chunks 128x64k double-buffered via cp.async; B (gathered) ping-pong, LDG hoisted over MMA.
#define SM_NIDX 0
#define SM_A0H  2048
#define SM_A0L  20480
#define SM_A1H  38912
#define SM_A1L  57344
#define SM_B0H  75776
#define SM_B0L  110592
#define SM_B1H  145408
#define SM_B1L  180224
#define SM_TOT  215040

__global__ __launch_bounds__(512, 1) void stage2_kernel(const int* __restrict__ gemm) {
    extern __shared__ char sm2[];
    uint32_t sb = smem_u32(sm2);
    int tid = threadIdx.x;
    int lane = tid & 31, wid = tid >> 5;
    int wm = wid >> 2, wn = wid & 3;
    int e0 = blockIdx.x * 128;
    int b = blockIdx.y, mh = blockIdx.z;

    int4* nidx = (int4*)(sm2 + SM_NIDX);
    const float* Xt = g_Xt + (size_t)b * NE * 128;

    float acc[2][4][4];
#pragma unroll
    for (int mi = 0; mi < 2; mi++)
#pragma unroll
        for (int ni = 0; ni < 4; ni++)
#pragma unroll
            for (int j = 0; j < 4; j++) acc[mi][ni][j] = 0.f;

    uint32_t aOff = (uint32_t)((wm * 32 + (lane & 15)) * 144 + (lane >> 4) * 16);
    uint32_t bOff = (uint32_t)((wn * 32 + (lane & 7)) * 272 + ((lane >> 3) & 1) * 16);

#define CPA_A2(G, KHP, ABASE)                                                         \
    {                                                                                 \
        const __nv_bfloat16* sH_ = g_Wh + ((size_t)(G) * 512 + mh * 128) * 128 + (KHP) * 64; \
        const __nv_bfloat16* sL_ = g_Wl + ((size_t)(G) * 512 + mh * 128) * 128 + (KHP) * 64; \
        _Pragma("unroll") for (int i_ = 0; i_ < 2; i_++) {                            \
            int ii_ = tid + i_ * 512;                                                 \
            int row_ = ii_ >> 3, cg_ = ii_ & 7;                                       \
            CPA(sb + (ABASE) + row_ * 144 + cg_ * 16, sH_ + (size_t)row_ * 128 + cg_ * 8); \
            CPA(sb + (ABASE) + 18432 + row_ * 144 + cg_ * 16, sL_ + (size_t)row_ * 128 + cg_ * 8); \
        }                                                                             \
        CPA_COMMIT();                                                                 \
    }

#define LDG_PAIR(P, IT)                                                               \
    {                                                                                 \
        int idx_ = tid + (IT) * 512;                                                  \
        int e_ = idx_ >> 4, cq_ = idx_ & 15;                                          \
        int4 nn_ = nidx[e_];                                                          \
        int na_ = (P) ? nn_.y : nn_.x;                                                \
        int nc_ = (P) ? nn_.w : nn_.z;                                                \
        const float4* A4_ = (const float4*)&Xt[(size_t)na_ * 128 + cq_ * 8];          \
        const float4* B4_ = (const float4*)&Xt[(size_t)nc_ * 128 + cq_ * 8];          \
        ga0 = A4_[0]; ga1 = A4_[1]; gb0 = B4_[0]; gb1 = B4_[1];                       \
    }

#define PST_SUM(BHI, BLO, IT)                                                         \
    {                                                                                 \
        int idx_ = tid + (IT) * 512;                                                  \
        int e_ = idx_ >> 4, cq_ = idx_ & 15;                                          \
        float fs_[8] = {ga0.x + gb0.x, ga0.y + gb0.y, ga0.z + gb0.z, ga0.w + gb0.w,   \
                        ga1.x + gb1.x, ga1.y + gb1.y, ga1.z + gb1.z, ga1.w + gb1.w};  \
        uint4 h_, l_;                                                                 \
        pack8(fs_, h_, l_);                                                           \
        *(uint4*)(sm2 + (BHI) + e_ * 272 + cq_ * 16) = h_;                            \
        *(uint4*)(sm2 + (BLO) + e_ * 272 + cq_ * 16) = l_;                            \
    }

#define PST_DIFF(BHI, BLO, IT)                                                        \
    {                                                                                 \
        int idx_ = tid + (IT) * 512;                                                  \
        int e_ = idx_ >> 4, cq_ = idx_ & 15;                                          \
        float fs_[8] = {fabsf(ga0.x - gb0.x), fabsf(ga0.y - gb0.y), fabsf(ga0.z - gb0.z), \
                        fabsf(ga0.w - gb0.w), fabsf(ga1.x - gb1.x), fabsf(ga1.y - gb1.y), \
                        fabsf(ga1.z - gb1.z), fabsf(ga1.w - gb1.w)};                  \
        uint4 h_, l_;                                                                 \
        pack8(fs_, h_, l_);                                                           \
        *(uint4*)(sm2 + (BHI) + e_ * 272 + cq_ * 16) = h_;                            \
        *(uint4*)(sm2 + (BLO) + e_ * 272 + cq_ * 16) = l_;                            \
    }

#define MMA_STEP2(ABASE, BH, KBA, KBB)                                                \
    {                                                                                 \
        uint32_t ah_[2][4], al_[2][4], bh_[4][2], bl_[4][2];                          \
        _Pragma("unroll") for (int mi = 0; mi < 2; mi++) {                            \
            ldsm4(ah_[mi], sb + (ABASE) + aOff + mi * (16 * 144) + (KBA));            \
            ldsm4(al_[mi], sb + (ABASE) + 18432 + aOff + mi * (16 * 144) + (KBA));    \
        }                                                                             \
        _Pragma("unroll") for (int ni = 0; ni < 4; ni++) {                            \
            ldsm2(bh_[ni], sb + (BH) + bOff + ni * (8 * 272) + (KBB));                \
            ldsm2(bl_[ni], sb + (BH) + 34816 + bOff + ni * (8 * 272) + (KBB));        \
        }                                                                             \
        _Pragma("unroll") for (int mi = 0; mi < 2; mi++)                              \
            _Pragma("unroll") for (int ni = 0; ni < 4; ni++) {                        \
                mma_bf16(acc[mi][ni], ah_[mi], bh_[ni]);                              \
                mma_bf16(acc[mi][ni], ah_[mi], bl_[ni]);                              \
                mma_bf16(acc[mi][ni], al_[mi], bh_[ni]);                              \
            }                                                                         \
    }

    float4 ga0, ga1, gb0, gb1;

    // ---- prologue: A(feature0, kh0) -> A0; nidx; self gather -> B0 ----
    CPA_A2(0, 0, SM_A0H);
    if (tid < 128) nidx[tid] = ((const int4*)gemm)[(size_t)b * NE + e0 + tid];
#pragma unroll
    for (int it = 0; it < 4; it++) {
        int idx_ = tid + it * 512;
        int e_ = idx_ >> 4, cq_ = idx_ & 15;
        const float4* S4 = (const float4*)&Xt[(size_t)(e0 + e_) * 128 + cq_ * 8];
        float fs_[8];
        *(float4*)fs_ = S4[0];
        *(float4*)(fs_ + 4) = S4[1];
        uint4 h_, l_;
        pack8(fs_, h_, l_);
        *(uint4*)(sm2 + SM_B0H + e_ * 272 + cq_ * 16) = h_;
        *(uint4*)(sm2 + SM_B0L + e_ * 272 + cq_ * 16) = l_;
    }
    CPA_WAIT();
    __syncthreads();

    // phase macro: one khalf of one feature
#define PHASE(PRE, BH, KH, G0, G1, G2, G3)                                            \
    PRE                                                                               \
    G0                                                                                \
    MMA_STEP2((KH) ? SM_A1H : SM_A0H, BH, 0, ((KH) * 4 + 0) * 32);                    \
    MMA_STEP2((KH) ? SM_A1H : SM_A0H, BH, 32, ((KH) * 4 + 1) * 32);                   \
    G1 G2                                                                             \
    MMA_STEP2((KH) ? SM_A1H : SM_A0H, BH, 64, ((KH) * 4 + 2) * 32);                   \
    MMA_STEP2((KH) ? SM_A1H : SM_A0H, BH, 96, ((KH) * 4 + 3) * 32);                   \
    G3                                                                                \
    CPA_WAIT();                                                                       \
    __syncthreads();

    // feature 0 (W0 x B0self), gather SUM pair0 -> B1
    PHASE(CPA_A2(0, 1, SM_A1H);, SM_B0H, 0,
          LDG_PAIR(0, 0);, PST_SUM(SM_B1H, SM_B1L, 0);, LDG_PAIR(0, 1);, PST_SUM(SM_B1H, SM_B1L, 1);)
    PHASE(CPA_A2(1, 0, SM_A0H);, SM_B0H, 1,
          LDG_PAIR(0, 2);, PST_SUM(SM_B1H, SM_B1L, 2);, LDG_PAIR(0, 3);, PST_SUM(SM_B1H, SM_B1L, 3);)
    // feature 1 (W1 x B1sum0), gather DIFF pair0 -> B0
    PHASE(CPA_A2(1, 1, SM_A1H);, SM_B1H, 0,
          LDG_PAIR(0, 0);, PST_DIFF(SM_B0H, SM_B0L, 0);, LDG_PAIR(0, 1);, PST_DIFF(SM_B0H, SM_B0L, 1);)
    PHASE(CPA_A2(3, 0, SM_A0H);, SM_B1H, 1,
          LDG_PAIR(0, 2);, PST_DIFF(SM_B0H, SM_B0L, 2);, LDG_PAIR(0, 3);, PST_DIFF(SM_B0H, SM_B0L, 3);)
    // feature 2 (W3 x B0diff0), gather SUM pair1 -> B1
    PHASE(CPA_A2(3, 1, SM_A1H);, SM_B0H, 0,
          LDG_PAIR(1, 0);, PST_SUM(SM_B1H, SM_B1L, 0);, LDG_PAIR(1, 1);, PST_SUM(SM_B1H, SM_B1L, 1);)
    PHASE(CPA_A2(2, 0, SM_A0H);, SM_B0H, 1,
          LDG_PAIR(1, 2);, PST_SUM(SM_B1H, SM_B1L, 2);, LDG_PAIR(1, 3);, PST_SUM(SM_B1H, SM_B1L, 3);)
    // feature 3 (W2 x B1sum1), gather DIFF pair1 -> B0
    PHASE(CPA_A2(2, 1, SM_A1H);, SM_B1H, 0,
          LDG_PAIR(1, 0);, PST_DIFF(SM_B0H, SM_B0L, 0);, LDG_PAIR(1, 1);, PST_DIFF(SM_B0H, SM_B0L, 1);)
    PHASE(CPA_A2(4, 0, SM_A0H);, SM_B1H, 1,
          LDG_PAIR(1, 2);, PST_DIFF(SM_B0H, SM_B0L, 2);, LDG_PAIR(1, 3);, PST_DIFF(SM_B0H, SM_B0L, 3);)
    // feature 4 (W4 x B0diff1), no gather
    PHASE(CPA_A2(4, 1, SM_A1H);, SM_B0H, 0, ;, ;, ;, ;)
    PHASE(;, SM_B0H, 1, ;, ;, ;, ;)

    // ---- epilogue: bias + store + row stats ----
    float* sAcc = (float*)sm2;  // reuse nidx region: 128 rows x {sum, sumsq}
    for (int i = tid; i < 256; i += 512) sAcc[i] = 0.f;
    __syncthreads();

    int rbase = mh * 128 + wm * 32;
    int colLocal = wn * 32 + (lane & 3) * 2;
#pragma unroll
    for (int mi = 0; mi < 2; mi++) {
        int r0 = rbase + mi * 16 + (lane >> 2);
        int r1 = r0 + 8;
        float c0 = g_Cf[r0], c1 = g_Cf[r1];
        float* d0 = g_pre + ((size_t)b * 512 + r0) * NE + e0 + colLocal;
        float* d1 = g_pre + ((size_t)b * 512 + r1) * NE + e0 + colLocal;
        float s0 = 0.f, q0 = 0.f, s1 = 0.f, q1 = 0.f;
#pragma unroll
        for (int ni = 0; ni < 4; ni++) {
            float v00 = acc[mi][ni][0] + c0, v01 = acc[mi][ni][1] + c0;
            float v10 = acc[mi][ni][2] + c1, v11 = acc[mi][ni][3] + c1;
            *(float2*)(d0 + ni * 8) = make_float2(v00, v01);
            *(float2*)(d1 + ni * 8) = make_float2(v10, v11);
            s0 += v00 + v01; q0 += v00 * v00 + v01 * v01;
            s1 += v10 + v11; q1 += v10 * v10 + v11 * v11;
        }
#pragma unroll
        for (int o = 1; o <= 2; o <<= 1) {
            s0 += __shfl_xor_sync(0xFFFFFFFFu, s0, o);
            q0 += __shfl_xor_sync(0xFFFFFFFFu, q0, o);
            s1 += __shfl_xor_sync(0xFFFFFFFFu, s1, o);
            q1 += __shfl_xor_sync(0xFFFFFFFFu, q1, o);
        }
        if ((lane & 3) == 0) {
            int rl0 = wm * 32 + mi * 16 + (lane >> 2);
            atomicAdd(&sAcc[rl0 * 2], s0);
            atomicAdd(&sAcc[rl0 * 2 + 1], q0);
            atomicAdd(&sAcc[(rl0 + 8) * 2], s1);
            atomicAdd(&sAcc[(rl0 + 8) * 2 + 1], q1);
        }
    }
    __syncthreads();
    for (int i = tid; i < 256; i += 512) {
        int rowl = i >> 1;
        int gidx = b * 512 + mh * 128 + rowl;
        if (i & 1) atomicAdd(&g_S2[gidx], sAcc[i]);
        else       atomicAdd(&g_S[gidx], sAcc[i]);
    }
}

// ---------------- kernel 3: finalize instance-norm stats ----------------
__global__ void stats_finalize() {
    int i = blockIdx.x * 256 + threadIdx.x;  // 0..1023
    float mean = g_S[i] / (float)NE;
    float var = g_S2[i] / (float)NE - mean * mean;
    g_mean[i] = mean;
    g_rstd[i] = rsqrtf(var + 1e-5f);
}

// ---------------- kernel 4: fused norm + sigmoid + softmax blend ----------------
__global__ __launch_bounds__(256) void final_kernel(const float* __restrict__ x0,
                                                    const float* __restrict__ x1,
                                                    float* __restrict__ out) {
    size_t idx = (size_t)blockIdx.x * 256 + threadIdx.x;
    int e4 = (int)(idx & (NE / 4 - 1));
    int c = (int)((idx >> 14) & 255);
    int b = (int)(idx >> 22);

    float4 pa = ((const float4*)g_pre)[((size_t)b * 512 + c) * (NE / 4) + e4];
    float4 pb = ((const float4*)g_pre)[((size_t)b * 512 + 256 + c) * (NE / 4) + e4];
    float4 a0 = ((const float4*)x0)[idx];
    float4 a1 = ((const float4*)x1)[idx];

    float ma = g_mean[b * 512 + c], ra = g_rstd[b * 512 + c];
    float mb = g_mean[b * 512 + 256 + c], rb = g_rstd[b * 512 + 256 + c];

    float4 o;
#define BLEND(fld)                                              \
    {                                                           \
        float za = (pa.fld - ma) * ra;                          \
        float zb = (pb.fld - mb) * rb;                          \
        float wa = 1.f / (1.f + expf(-za));                     \
        float wb = 1.f / (1.f + expf(-zb));                     \
        float w0 = 1.f / (1.f + expf(wb - wa));                 \
        o.fld = a0.fld * w0 + a1.fld * (1.f - w0);              \
    }
    BLEND(x); BLEND(y); BLEND(z); BLEND(w);
#undef BLEND
    ((float4*)out)[idx] = o;
}

// ---------------- launch ----------------
extern "C" void kernel_launch(void* const* d_in, const int* in_sizes, int n_in,
                              void* d_out, int out_size) {
    const float* x0  = (const float*)d_in[0];
    const float* x1  = (const float*)d_in[1];
    const int*   gm  = (const int*)d_in[2];
    const float* Wa  = (const float*)d_in[3];
    const float* ba  = (const float*)d_in[4];
    const float* Wb  = (const float*)d_in[5];
    const float* bb  = (const float*)d_in[6];
    const float* Wal = (const float*)d_in[7];
    const float* bal = (const float*)d_in[8];
    const float* Wbl = (const float*)d_in[9];
    const float* bbl = (const float*)d_in[10];
    const float* Wat = (const float*)d_in[11];
    const float* bat = (const float*)d_in[12];
    const float* Wbt = (const float*)d_in[13];
    const float* bbt = (const float*)d_in[14];
    const float* Waf = (const float*)d_in[15];
    const float* baf = (const float*)d_in[16];
    const float* Wbf = (const float*)d_in[17];
    const float* bbf = (const float*)d_in[18];
    float* out = (float*)d_out;

    fold_w_kernel<<<512, 128>>>(Waf, Wal, Wat, Wbf, Wbl, Wbt);
    fold_c_kernel<<<1, 512>>>(Waf, bal, bat, baf, Wbf, bbl, bbt, bbf);

    cudaFuncSetAttribute(stage1_kernel, cudaFuncAttributeMaxDynamicSharedMemorySize, S1_TOT);
    stage1_kernel<<<dim3(NE / 128, NB, 2), 256, S1_TOT>>>(x0, x1, Wa, ba, Wb, bb);

    cudaFuncSetAttribute(stage2_kernel, cudaFuncAttributeMaxDynamicSharedMemorySize, SM_TOT);
    stage2_kernel<<<dim3(NE / 128, NB, 4), 512, SM_TOT>>>(gm);

    stats_finalize<<<4, 256>>>();

    final_kernel<<<(NB * 256 * (NE / 4)) / 256, 256>>>(x0, x1, out);
}

// round 7
// speedup vs baseline: 4.6222x; 1.8233x over previous
#include <cuda_runtime.h>
#include <cuda_fp16.h>
#include <math.h>
#include <stdint.h>

// Problem constants: B=2, C=256, N=65536.
#define NE 65536
#define NB 2

// ---------------- scratch (device globals; no allocations) ----------------
__device__ __align__(16) __half g_XtH[(size_t)NB * NE * 128];   // x_all transposed fp16 [b][e][c]
__device__ __align__(16) __half g_preH[(size_t)NB * 512 * NE];  // pre-activations fp16 [b][r][e]
__device__ __align__(16) __half g_Wh[5 * 512 * 128];            // folded W fp16
__device__ float g_Cf[512];
__device__ float g_S[NB * 512];
__device__ float g_S2[NB * 512];
__device__ float g_mean[NB * 512];
__device__ float g_rstd[NB * 512];

// ================= helpers =================
__device__ __forceinline__ uint32_t smem_u32(const void* p) {
    uint32_t a;
    asm("{ .reg .u64 t; cvta.to.shared.u64 t, %1; cvt.u32.u64 %0, t; }" : "=r"(a) : "l"(p));
    return a;
}
__device__ __forceinline__ void ldsm4(uint32_t* r, uint32_t addr) {
    asm volatile("ldmatrix.sync.aligned.m8n8.x4.shared.b16 {%0, %1, %2, %3}, [%4];"
                 : "=r"(r[0]), "=r"(r[1]), "=r"(r[2]), "=r"(r[3]) : "r"(addr));
}
__device__ __forceinline__ void ldsm2(uint32_t* r, uint32_t addr) {
    asm volatile("ldmatrix.sync.aligned.m8n8.x2.shared.b16 {%0, %1}, [%2];"
                 : "=r"(r[0]), "=r"(r[1]) : "r"(addr));
}
__device__ __forceinline__ void mma_f16(float* d, const uint32_t* a, const uint32_t* b) {
    asm volatile(
        "mma.sync.aligned.m16n8k16.row.col.f32.f16.f16.f32 "
        "{%0,%1,%2,%3}, {%4,%5,%6,%7}, {%8,%9}, {%0,%1,%2,%3};"
        : "+f"(d[0]), "+f"(d[1]), "+f"(d[2]), "+f"(d[3])
        : "r"(a[0]), "r"(a[1]), "r"(a[2]), "r"(a[3]), "r"(b[0]), "r"(b[1]));
}
#define CPA(dst, src) \
    asm volatile("cp.async.ca.shared.global [%0], [%1], 16;" :: "r"(dst), "l"(src))
#define CPA_COMMIT() asm volatile("cp.async.commit_group;" ::: "memory")
#define CPA_WAIT() asm volatile("cp.async.wait_group 0;" ::: "memory")

// pack 8 floats -> 8 fp16 (one uint4)
__device__ __forceinline__ uint4 pack8h(const float* f) {
    uint4 o;
    __half2 h;
    h = __floats2half2_rn(f[0], f[1]); o.x = *reinterpret_cast<unsigned*>(&h);
    h = __floats2half2_rn(f[2], f[3]); o.y = *reinterpret_cast<unsigned*>(&h);
    h = __floats2half2_rn(f[4], f[5]); o.z = *reinterpret_cast<unsigned*>(&h);
    h = __floats2half2_rn(f[6], f[7]); o.w = *reinterpret_cast<unsigned*>(&h);
    return o;
}

// ---------------- kernel 0a: fold weight matrices (emit fp16) ----------------
__global__ void fold_w_kernel(const float* __restrict__ Waf, const float* __restrict__ Wal,
                              const float* __restrict__ Wat,
                              const float* __restrict__ Wbf, const float* __restrict__ Wbl,
                              const float* __restrict__ Wbt) {
    int r = blockIdx.x;
    int c = threadIdx.x;
    const float *F, *L, *T;
    if (r < 256) { F = Waf; L = Wal; T = Wat; } else { F = Wbf; L = Wbl; T = Wbt; }
    int rr = r & 255;
    float a[5] = {0.f, 0.f, 0.f, 0.f, 0.f};
    for (int j = 0; j < 128; j++) {
        float fl = F[rr * 256 + j];
        float fr = F[rr * 256 + 128 + j];
        a[0] += fl * L[j * 128 + c];
        const float* t = &T[(j * 128 + c) * 5];
        a[0] += fr * t[0];
        a[1] += fr * t[1];
        a[2] += fr * t[2];
        a[3] += fr * t[3];
        a[4] += fr * t[4];
    }
#pragma unroll
    for (int g = 0; g < 5; g++)
        g_Wh[(g * 512 + r) * 128 + c] = __float2half_rn(a[g]);
}

// ---------------- kernel 0b: fold bias + zero stats accumulators ----------------
__global__ void fold_c_kernel(const float* __restrict__ Waf, const float* __restrict__ bal,
                              const float* __restrict__ bat, const float* __restrict__ baf,
                              const float* __restrict__ Wbf, const float* __restrict__ bbl,
                              const float* __restrict__ bbt, const float* __restrict__ bbf) {
    int r = threadIdx.x;
    const float *F, *lb, *tb, *fb;
    if (r < 256) { F = Waf; lb = bal; tb = bat; fb = baf; }
    else         { F = Wbf; lb = bbl; tb = bbt; fb = bbf; }
    int rr = r & 255;
    float s = fb[rr];
    for (int j = 0; j < 128; j++)
        s += F[rr * 256 + j] * lb[j] + F[rr * 256 + 128 + j] * tb[j];
    g_Cf[r] = s;
    g_S[r] = 0.f; g_S[r + 512] = 0.f;
    g_S2[r] = 0.f; g_S2[r + 512] = 0.f;
}

// ---------------- kernel 1: x_all via mma.sync fp16, stored transposed fp16 ----------------
// Block 256 (8 warps 2x4). Tile M=64 rows x N=128 edges, K=256 in 4 chunks of 64.
#define S1_AH  0            // 64 x 528B
#define S1_B0  33792        // 128 x 144B
#define S1_B1  52224
#define S1_TOT 70656

__global__ __launch_bounds__(256) void stage1_kernel(
    const float* __restrict__ x0, const float* __restrict__ x1,
    const float* __restrict__ Wa, const float* __restrict__ ba,
    const float* __restrict__ Wb, const float* __restrict__ bb) {
    extern __shared__ char sm1[];
    uint32_t sb = smem_u32(sm1);
    int tid = threadIdx.x;
    int lane = tid & 31, wid = tid >> 5;
    int wm = wid >> 2, wn = wid & 3;
    int e0 = blockIdx.x * 128;
    int b = blockIdx.y, half = blockIdx.z;
    const float* X = ((half == 0) ? x0 : x1) + (size_t)b * 256 * NE;
    const float* W = (half == 0) ? Wa : Wb;
    const float* bias = (half == 0) ? ba : bb;

    int eIdx = tid & 127;
    int kbase = (tid >> 7) * 32;

    float acc[2][4][4];
#pragma unroll
    for (int mi = 0; mi < 2; mi++)
#pragma unroll
        for (int ni = 0; ni < 4; ni++)
#pragma unroll
            for (int j = 0; j < 4; j++) acc[mi][ni][j] = 0.f;

    uint32_t aOff = (uint32_t)((wm * 32 + (lane & 15)) * 528 + (lane >> 4) * 16);
    uint32_t bOff = (uint32_t)((wn * 32 + (lane & 7)) * 144 + ((lane >> 3) & 1) * 16);

    // prologue: A (weights) fp16
    for (int i = tid; i < 2048; i += 256) {
        int r = i >> 5, kq = i & 31;
        float f[8];
        *(float4*)f = *(const float4*)&W[r * 256 + kq * 8];
        *(float4*)(f + 4) = *(const float4*)&W[r * 256 + kq * 8 + 4];
        *(uint4*)(sm1 + S1_AH + r * 528 + kq * 16) = pack8h(f);
    }

#define S1_LDG(KC, G, DST)                                                            \
    {                                                                                 \
        _Pragma("unroll") for (int j = 0; j < 8; j++)                                 \
            DST[j] = X[(size_t)((KC) * 64 + kbase + (G) * 8 + j) * NE + e0 + eIdx];   \
    }
#define S1_PST(BH, G, SRC)                                                            \
    {                                                                                 \
        int k0_ = kbase + (G) * 8;                                                    \
        *(uint4*)(sm1 + (BH) + eIdx * 144 + k0_ * 2) = pack8h(SRC);                   \
    }
#define S1_MMA(BH, KC, KK)                                                            \
    {                                                                                 \
        uint32_t ah_[2][4], bh_[4][2];                                                \
        _Pragma("unroll") for (int mi = 0; mi < 2; mi++)                              \
            ldsm4(ah_[mi], sb + S1_AH + aOff + mi * (16 * 528) + (KC) * 128 + (KK) * 32); \
        _Pragma("unroll") for (int ni = 0; ni < 4; ni++)                              \
            ldsm2(bh_[ni], sb + (BH) + bOff + ni * (8 * 144) + (KK) * 32);            \
        _Pragma("unroll") for (int mi = 0; mi < 2; mi++)                              \
            _Pragma("unroll") for (int ni = 0; ni < 4; ni++)                          \
                mma_f16(acc[mi][ni], ah_[mi], bh_[ni]);                               \
    }

    // prologue: B chunk 0
    {
        float gf[8];
#pragma unroll
        for (int g = 0; g < 4; g++) {
            S1_LDG(0, g, gf);
            S1_PST(S1_B0, g, gf);
        }
    }
    __syncthreads();

    float gfA[8], gfB[8];
#pragma unroll
    for (int kc = 0; kc < 4; kc++) {
        uint32_t BH = (kc & 1) ? S1_B1 : S1_B0;
        uint32_t BnH = (kc & 1) ? S1_B0 : S1_B1;
        if (kc < 3) { S1_LDG(kc + 1, 0, gfA); S1_LDG(kc + 1, 1, gfB); }
        S1_MMA(BH, kc, 0);
        S1_MMA(BH, kc, 1);
        if (kc < 3) {
            S1_PST(BnH, 0, gfA); S1_PST(BnH, 1, gfB);
            S1_LDG(kc + 1, 2, gfA); S1_LDG(kc + 1, 3, gfB);
        }
        S1_MMA(BH, kc, 2);
        S1_MMA(BH, kc, 3);
        if (kc < 3) { S1_PST(BnH, 2, gfA); S1_PST(BnH, 3, gfB); }
        __syncthreads();
    }

    // epilogue: bias, transpose through smem (fp32), pack fp16, coalesced store
    float* T = (float*)(sm1 + S1_B0);  // [r][e] stride 132 floats, 64x132x4 = 33792B
#pragma unroll
    for (int mi = 0; mi < 2; mi++) {
        int r0 = wm * 32 + mi * 16 + (lane >> 2);
        int r1 = r0 + 8;
        float c0 = bias[r0], c1 = bias[r1];
#pragma unroll
        for (int ni = 0; ni < 4; ni++) {
            int ecol = wn * 32 + ni * 8 + (lane & 3) * 2;
            T[r0 * 132 + ecol] = acc[mi][ni][0] + c0;
            T[r0 * 132 + ecol + 1] = acc[mi][ni][1] + c0;
            T[r1 * 132 + ecol] = acc[mi][ni][2] + c1;
            T[r1 * 132 + ecol + 1] = acc[mi][ni][3] + c1;
        }
    }
    __syncthreads();
    __half* dst = g_XtH + (size_t)b * NE * 128;
    for (int i = tid; i < 1024; i += 256) {
        int e = i >> 3, seg = i & 7;
        float v[8];
#pragma unroll
        for (int j = 0; j < 8; j++) v[j] = T[(seg * 8 + j) * 132 + e];
        *(uint4*)&dst[(size_t)(e0 + e) * 128 + half * 64 + seg * 8] = pack8h(v);
    }
}

// ---------------- kernel 2: pipelined fused GEMM + stats (fp16 single-pass) ----------------
// Block 512 (16 warps 4x4). Tile M=128 x N=128 edges. 10 phases (5 features x 2 khalves).
// 4 B buffers: BA=self (reused as diff1), BB=sum0, BC=diff0, BD=sum1. Pairs gathered ONCE.
#define SM_NIDX 0
#define SM_A0   2048
#define SM_A1   20480
#define SM_BA   38912
#define SM_BB   73728
#define SM_BC   108544
#define SM_BD   143360
#define SM_TOT  178176

__global__ __launch_bounds__(512, 1) void stage2_kernel(const int* __restrict__ gemm) {
    extern __shared__ char sm2[];
    uint32_t sb = smem_u32(sm2);
    int tid = threadIdx.x;
    int lane = tid & 31, wid = tid >> 5;
    int wm = wid >> 2, wn = wid & 3;
    int e0 = blockIdx.x * 128;
    int b = blockIdx.y, mh = blockIdx.z;

    int4* nidx = (int4*)(sm2 + SM_NIDX);
    const __half* XtH = g_XtH + (size_t)b * NE * 128;

    float acc[2][4][4];
#pragma unroll
    for (int mi = 0; mi < 2; mi++)
#pragma unroll
        for (int ni = 0; ni < 4; ni++)
#pragma unroll
            for (int j = 0; j < 4; j++) acc[mi][ni][j] = 0.f;

    uint32_t aOff = (uint32_t)((wm * 32 + (lane & 15)) * 144 + (lane >> 4) * 16);
    uint32_t bOff = (uint32_t)((wn * 32 + (lane & 7)) * 272 + ((lane >> 3) & 1) * 16);

#define CPA_A(G, KHP, ABASE)                                                          \
    {                                                                                 \
        const __half* s_ = g_Wh + ((size_t)(G) * 512 + mh * 128) * 128 + (KHP) * 64;  \
        _Pragma("unroll") for (int i_ = 0; i_ < 2; i_++) {                            \
            int ii_ = tid + i_ * 512;                                                 \
            int row_ = ii_ >> 3, cg_ = ii_ & 7;                                       \
            CPA(sb + (ABASE) + row_ * 144 + cg_ * 16, s_ + (size_t)row_ * 128 + cg_ * 8); \
        }                                                                             \
        CPA_COMMIT();                                                                 \
    }

    uint4 ha_, hb_;
#define LDGP(P, IT)                                                                   \
    {                                                                                 \
        int idx_ = tid + (IT) * 512;                                                  \
        int e_ = idx_ >> 4, cq_ = idx_ & 15;                                          \
        int4 nn_ = nidx[e_];                                                          \
        int na_ = (P) ? nn_.y : nn_.x;                                                \
        int nc_ = (P) ? nn_.w : nn_.z;                                                \
        ha_ = *(const uint4*)&XtH[(size_t)na_ * 128 + cq_ * 8];                       \
        hb_ = *(const uint4*)&XtH[(size_t)nc_ * 128 + cq_ * 8];                       \
    }
#define PSTP(SUMB, DIFB, IT)                                                          \
    {                                                                                 \
        int idx_ = tid + (IT) * 512;                                                  \
        int e_ = idx_ >> 4, cq_ = idx_ & 15;                                          \
        uint4 so_, do_;                                                               \
        __half2* pa_ = (__half2*)&ha_;                                                \
        __half2* pb_ = (__half2*)&hb_;                                                \
        __half2* ps_ = (__half2*)&so_;                                                \
        __half2* pd_ = (__half2*)&do_;                                                \
        _Pragma("unroll") for (int j_ = 0; j_ < 4; j_++) {                            \
            ps_[j_] = __hadd2(pa_[j_], pb_[j_]);                                      \
            pd_[j_] = __habs2(__hsub2(pa_[j_], pb_[j_]));                             \
        }                                                                             \
        *(uint4*)(sm2 + (SUMB) + e_ * 272 + cq_ * 16) = so_;                          \
        *(uint4*)(sm2 + (DIFB) + e_ * 272 + cq_ * 16) = do_;                          \
    }

#define MMA_STEP(ABASE, BBASE, KBA, KBB)                                              \
    {                                                                                 \
        uint32_t ah_[2][4], bh_[4][2];                                                \
        _Pragma("unroll") for (int mi = 0; mi < 2; mi++)                              \
            ldsm4(ah_[mi], sb + (ABASE) + aOff + mi * (16 * 144) + (KBA));            \
        _Pragma("unroll") for (int ni = 0; ni < 4; ni++)                              \
            ldsm2(bh_[ni], sb + (BBASE) + bOff + ni * (8 * 272) + (KBB));             \
        _Pragma("unroll") for (int mi = 0; mi < 2; mi++)                              \
            _Pragma("unroll") for (int ni = 0; ni < 4; ni++)                          \
                mma_f16(acc[mi][ni], ah_[mi], bh_[ni]);                               \
    }

    // ---- prologue: A(feat0,kh0)->A0; nidx; self tile -> BA via cp.async ----
    CPA_A(0, 0, SM_A0);
    if (tid < 128) nidx[tid] = ((const int4*)gemm)[(size_t)b * NE + e0 + tid];
#pragma unroll
    for (int it = 0; it < 4; it++) {
        int ii = tid + it * 512;
        int e = ii >> 4, cq = ii & 15;
        CPA(sb + SM_BA + e * 272 + cq * 16, XtH + (size_t)(e0 + e) * 128 + cq * 8);
    }
    CPA_COMMIT();
    CPA_WAIT();
    __syncthreads();

#define PHASE(PRE, BBASE, KH, G0, G1, G2, G3)                                         \
    PRE                                                                               \
    G0                                                                                \
    MMA_STEP((KH) ? SM_A1 : SM_A0, BBASE, 0, ((KH) * 4 + 0) * 32);                    \
    MMA_STEP((KH) ? SM_A1 : SM_A0, BBASE, 32, ((KH) * 4 + 1) * 32);                   \
    G1 G2                                                                             \
    MMA_STEP((KH) ? SM_A1 : SM_A0, BBASE, 64, ((KH) * 4 + 2) * 32);                   \
    MMA_STEP((KH) ? SM_A1 : SM_A0, BBASE, 96, ((KH) * 4 + 3) * 32);                   \
    G3                                                                                \
    CPA_WAIT();                                                                       \
    __syncthreads();

    // P1-P2: self (W0); gather pair0 -> BB(sum), BC(diff)
    PHASE(CPA_A(0, 1, SM_A1);, SM_BA, 0,
          LDGP(0, 0);, PSTP(SM_BB, SM_BC, 0);, LDGP(0, 1);, PSTP(SM_BB, SM_BC, 1);)
    PHASE(CPA_A(1, 0, SM_A0);, SM_BA, 1,
          LDGP(0, 2);, PSTP(SM_BB, SM_BC, 2);, LDGP(0, 3);, PSTP(SM_BB, SM_BC, 3);)
    // P3-P4: sum0 (W1); gather pair1 -> BD(sum), BA(diff; BA free after P2)
    PHASE(CPA_A(1, 1, SM_A1);, SM_BB, 0,
          LDGP(1, 0);, PSTP(SM_BD, SM_BA, 0);, LDGP(1, 1);, PSTP(SM_BD, SM_BA, 1);)
    PHASE(CPA_A(3, 0, SM_A0);, SM_BB, 1,
          LDGP(1, 2);, PSTP(SM_BD, SM_BA, 2);, LDGP(1, 3);, PSTP(SM_BD, SM_BA, 3);)
    // P5-P6: diff0 (W3)
    PHASE(CPA_A(3, 1, SM_A1);, SM_BC, 0, ;, ;, ;, ;)
    PHASE(CPA_A(2, 0, SM_A0);, SM_BC, 1, ;, ;, ;, ;)
    // P7-P8: sum1 (W2)
    PHASE(CPA_A(2, 1, SM_A1);, SM_BD, 0, ;, ;, ;, ;)
    PHASE(CPA_A(4, 0, SM_A0);, SM_BD, 1, ;, ;, ;, ;)
    // P9-P10: diff1 (W4, in BA)
    PHASE(CPA_A(4, 1, SM_A1);, SM_BA, 0, ;, ;, ;, ;)
    PHASE(;, SM_BA, 1, ;, ;, ;, ;)

    // ---- epilogue: bias + fp16 store + row stats ----
    float* sAcc = (float*)sm2;  // reuse nidx region
    for (int i = tid; i < 256; i += 512) sAcc[i] = 0.f;
    __syncthreads();

    int rbase = mh * 128 + wm * 32;
    int colLocal = wn * 32 + (lane & 3) * 2;
#pragma unroll
    for (int mi = 0; mi < 2; mi++) {
        int r0 = rbase + mi * 16 + (lane >> 2);
        int r1 = r0 + 8;
        float c0 = g_Cf[r0], c1 = g_Cf[r1];
        __half* d0 = g_preH + ((size_t)b * 512 + r0) * NE + e0 + colLocal;
        __half* d1 = g_preH + ((size_t)b * 512 + r1) * NE + e0 + colLocal;
        float s0 = 0.f, q0 = 0.f, s1 = 0.f, q1 = 0.f;
#pragma unroll
        for (int ni = 0; ni < 4; ni++) {
            float v00 = acc[mi][ni][0] + c0, v01 = acc[mi][ni][1] + c0;
            float v10 = acc[mi][ni][2] + c1, v11 = acc[mi][ni][3] + c1;
            *(__half2*)(d0 + ni * 8) = __floats2half2_rn(v00, v01);
            *(__half2*)(d1 + ni * 8) = __floats2half2_rn(v10, v11);
            s0 += v00 + v01; q0 += v00 * v00 + v01 * v01;
            s1 += v10 + v11; q1 += v10 * v10 + v11 * v11;
        }
#pragma unroll
        for (int o = 1; o <= 2; o <<= 1) {
            s0 += __shfl_xor_sync(0xFFFFFFFFu, s0, o);
            q0 += __shfl_xor_sync(0xFFFFFFFFu, q0, o);
            s1 += __shfl_xor_sync(0xFFFFFFFFu, s1, o);
            q1 += __shfl_xor_sync(0xFFFFFFFFu, q1, o);
        }
        if ((lane & 3) == 0) {
            int rl0 = wm * 32 + mi * 16 + (lane >> 2);
            atomicAdd(&sAcc[rl0 * 2], s0);
            atomicAdd(&sAcc[rl0 * 2 + 1], q0);
            atomicAdd(&sAcc[(rl0 + 8) * 2], s1);
            atomicAdd(&sAcc[(rl0 + 8) * 2 + 1], q1);
        }
    }
    __syncthreads();
    for (int i = tid; i < 256; i += 512) {
        int rowl = i >> 1;
        int gidx = b * 512 + mh * 128 + rowl;
        if (i & 1) atomicAdd(&g_S2[gidx], sAcc[i]);
        else       atomicAdd(&g_S[gidx], sAcc[i]);
    }
}

// ---------------- kernel 3: finalize instance-norm stats ----------------
__global__ void stats_finalize() {
    int i = blockIdx.x * 256 + threadIdx.x;  // 0..1023
    float mean = g_S[i] / (float)NE;
    float var = g_S2[i] / (float)NE - mean * mean;
    g_mean[i] = mean;
    g_rstd[i] = rsqrtf(var + 1e-5f);
}

// ---------------- kernel 4: fused norm + sigmoid + softmax blend ----------------
__global__ __launch_bounds__(256) void final_kernel(const float* __restrict__ x0,
                                                    const float* __restrict__ x1,
                                                    float* __restrict__ out) {
    size_t idx = (size_t)blockIdx.x * 256 + threadIdx.x;  // float4 index
    int e4 = (int)(idx & (NE / 4 - 1));
    int c = (int)((idx >> 14) & 255);
    int b = (int)(idx >> 22);

    uint2 pau = *(const uint2*)&g_preH[((size_t)b * 512 + c) * NE + e4 * 4];
    uint2 pbu = *(const uint2*)&g_preH[((size_t)b * 512 + 256 + c) * NE + e4 * 4];
    float2 pa01 = __half22float2(*(__half2*)&pau.x);
    float2 pa23 = __half22float2(*(__half2*)&pau.y);
    float2 pb01 = __half22float2(*(__half2*)&pbu.x);
    float2 pb23 = __half22float2(*(__half2*)&pbu.y);
    float4 pa = make_float4(pa01.x, pa01.y, pa23.x, pa23.y);
    float4 pb = make_float4(pb01.x, pb01.y, pb23.x, pb23.y);
    float4 a0 = ((const float4*)x0)[idx];
    float4 a1 = ((const float4*)x1)[idx];

    float ma = g_mean[b * 512 + c], ra = g_rstd[b * 512 + c];
    float mb = g_mean[b * 512 + 256 + c], rb = g_rstd[b * 512 + 256 + c];

    float4 o;
#define BLEND(fld)                                              \
    {                                                           \
        float za = (pa.fld - ma) * ra;                          \
        float zb = (pb.fld - mb) * rb;                          \
        float wa = 1.f / (1.f + expf(-za));                     \
        float wb = 1.f / (1.f + expf(-zb));                     \
        float w0 = 1.f / (1.f + expf(wb - wa));                 \
        o.fld = a0.fld * w0 + a1.fld * (1.f - w0);              \
    }
    BLEND(x); BLEND(y); BLEND(z); BLEND(w);
#undef BLEND
    ((float4*)out)[idx] = o;
}

// ---------------- launch ----------------
extern "C" void kernel_launch(void* const* d_in, const int* in_sizes, int n_in,
                              void* d_out, int out_size) {
    const float* x0  = (const float*)d_in[0];
    const float* x1  = (const float*)d_in[1];
    const int*   gm  = (const int*)d_in[2];
    const float* Wa  = (const float*)d_in[3];
    const float* ba  = (const float*)d_in[4];
    const float* Wb  = (const float*)d_in[5];
    const float* bb  = (const float*)d_in[6];
    const float* Wal = (const float*)d_in[7];
    const float* bal = (const float*)d_in[8];
    const float* Wbl = (const float*)d_in[9];
    const float* bbl = (const float*)d_in[10];
    const float* Wat = (const float*)d_in[11];
    const float* bat = (const float*)d_in[12];
    const float* Wbt = (const float*)d_in[13];
    const float* bbt = (const float*)d_in[14];
    const float* Waf = (const float*)d_in[15];
    const float* baf = (const float*)d_in[16];
    const float* Wbf = (const float*)d_in[17];
    const float* bbf = (const float*)d_in[18];
    float* out = (float*)d_out;

    fold_w_kernel<<<512, 128>>>(Waf, Wal, Wat, Wbf, Wbl, Wbt);
    fold_c_kernel<<<1, 512>>>(Waf, bal, bat, baf, Wbf, bbl, bbt, bbf);

    cudaFuncSetAttribute(stage1_kernel, cudaFuncAttributeMaxDynamicSharedMemorySize, S1_TOT);
    stage1_kernel<<<dim3(NE / 128, NB, 2), 256, S1_TOT>>>(x0, x1, Wa, ba, Wb, bb);

    cudaFuncSetAttribute(stage2_kernel, cudaFuncAttributeMaxDynamicSharedMemorySize, SM_TOT);
    stage2_kernel<<<dim3(NE / 128, NB, 4), 512, SM_TOT>>>(gm);

    stats_finalize<<<4, 256>>>();

    final_kernel<<<(NB * 256 * (NE / 4)) / 256, 256>>>(x0, x1, out);
}

// round 11
// speedup vs baseline: 5.1065x; 1.1048x over previous
#include <cuda_runtime.h>
#include <cuda_fp16.h>
#include <math.h>
#include <stdint.h>

// Problem constants: B=2, C=256, N=65536.
#define NE 65536
#define NB 2

// ---------------- scratch (device globals; no allocations) ----------------
__device__ __align__(16) __half g_XtH[(size_t)NB * NE * 128];   // x_all transposed fp16 [b][e][c]
__device__ __align__(16) __half g_preH[(size_t)NB * 512 * NE];  // pre-activations fp16 [b][r][e]
__device__ __align__(16) __half g_Wh[5 * 512 * 128];            // folded W fp16
__device__ float g_Cf[512];
__device__ float g_S[NB * 512];
__device__ float g_S2[NB * 512];
__device__ float g_mean[NB * 512];
__device__ float g_rstd[NB * 512];

// ================= helpers =================
__device__ __forceinline__ uint32_t smem_u32(const void* p) {
    uint32_t a;
    asm("{ .reg .u64 t; cvta.to.shared.u64 t, %1; cvt.u32.u64 %0, t; }" : "=r"(a) : "l"(p));
    return a;
}
__device__ __forceinline__ void ldsm4(uint32_t* r, uint32_t addr) {
    asm volatile("ldmatrix.sync.aligned.m8n8.x4.shared.b16 {%0, %1, %2, %3}, [%4];"
                 : "=r"(r[0]), "=r"(r[1]), "=r"(r[2]), "=r"(r[3]) : "r"(addr));
}
__device__ __forceinline__ void ldsm2(uint32_t* r, uint32_t addr) {
    asm volatile("ldmatrix.sync.aligned.m8n8.x2.shared.b16 {%0, %1}, [%2];"
                 : "=r"(r[0]), "=r"(r[1]) : "r"(addr));
}
__device__ __forceinline__ void mma_f16(float* d, const uint32_t* a, const uint32_t* b) {
    asm volatile(
        "mma.sync.aligned.m16n8k16.row.col.f32.f16.f16.f32 "
        "{%0,%1,%2,%3}, {%4,%5,%6,%7}, {%8,%9}, {%0,%1,%2,%3};"
        : "+f"(d[0]), "+f"(d[1]), "+f"(d[2]), "+f"(d[3])
        : "r"(a[0]), "r"(a[1]), "r"(a[2]), "r"(a[3]), "r"(b[0]), "r"(b[1]));
}
#define CPA(dst, src) \
    asm volatile("cp.async.ca.shared.global [%0], [%1], 16;" :: "r"(dst), "l"(src))
#define CPA_COMMIT() asm volatile("cp.async.commit_group;" ::: "memory")
#define CPA_WAIT() asm volatile("cp.async.wait_group 0;" ::: "memory")

// pack 8 floats -> 8 fp16 (one uint4)
__device__ __forceinline__ uint4 pack8h(const float* f) {
    uint4 o;
    __half2 h;
    h = __floats2half2_rn(f[0], f[1]); o.x = *reinterpret_cast<unsigned*>(&h);
    h = __floats2half2_rn(f[2], f[3]); o.y = *reinterpret_cast<unsigned*>(&h);
    h = __floats2half2_rn(f[4], f[5]); o.z = *reinterpret_cast<unsigned*>(&h);
    h = __floats2half2_rn(f[6], f[7]); o.w = *reinterpret_cast<unsigned*>(&h);
    return o;
}

// ---------------- kernel 0a: fold weight matrices (emit fp16) ----------------
__global__ void fold_w_kernel(const float* __restrict__ Waf, const float* __restrict__ Wal,
                              const float* __restrict__ Wat,
                              const float* __restrict__ Wbf, const float* __restrict__ Wbl,
                              const float* __restrict__ Wbt) {
    int r = blockIdx.x;
    int c = threadIdx.x;
    const float *F, *L, *T;
    if (r < 256) { F = Waf; L = Wal; T = Wat; } else { F = Wbf; L = Wbl; T = Wbt; }
    int rr = r & 255;
    float a[5] = {0.f, 0.f, 0.f, 0.f, 0.f};
    for (int j = 0; j < 128; j++) {
        float fl = F[rr * 256 + j];
        float fr = F[rr * 256 + 128 + j];
        a[0] += fl * L[j * 128 + c];
        const float* t = &T[(j * 128 + c) * 5];
        a[0] += fr * t[0];
        a[1] += fr * t[1];
        a[2] += fr * t[2];
        a[3] += fr * t[3];
        a[4] += fr * t[4];
    }
#pragma unroll
    for (int g = 0; g < 5; g++)
        g_Wh[(g * 512 + r) * 128 + c] = __float2half_rn(a[g]);
}

// ---------------- kernel 0b: fold bias + zero stats accumulators ----------------
__global__ void fold_c_kernel(const float* __restrict__ Waf, const float* __restrict__ bal,
                              const float* __restrict__ bat, const float* __restrict__ baf,
                              const float* __restrict__ Wbf, const float* __restrict__ bbl,
                              const float* __restrict__ bbt, const float* __restrict__ bbf) {
    int r = threadIdx.x;
    const float *F, *lb, *tb, *fb;
    if (r < 256) { F = Waf; lb = bal; tb = bat; fb = baf; }
    else         { F = Wbf; lb = bbl; tb = bbt; fb = bbf; }
    int rr = r & 255;
    float s = fb[rr];
    for (int j = 0; j < 128; j++)
        s += F[rr * 256 + j] * lb[j] + F[rr * 256 + 128 + j] * tb[j];
    g_Cf[r] = s;
    g_S[r] = 0.f; g_S[r + 512] = 0.f;
    g_S2[r] = 0.f; g_S2[r + 512] = 0.f;
}

// ---------------- kernel 1: x_all via mma.sync fp16, stored transposed fp16 ----------------
// Block 256 (8 warps 2x4). Tile M=64 rows x N=128 edges, K=256 in 4 chunks of 64.
#define S1_AH  0            // 64 x 528B
#define S1_B0  33792        // 128 x 144B
#define S1_B1  52224
#define S1_TOT 70656

__global__ __launch_bounds__(256) void stage1_kernel(
    const float* __restrict__ x0, const float* __restrict__ x1,
    const float* __restrict__ Wa, const float* __restrict__ ba,
    const float* __restrict__ Wb, const float* __restrict__ bb) {
    extern __shared__ char sm1[];
    uint32_t sb = smem_u32(sm1);
    int tid = threadIdx.x;
    int lane = tid & 31, wid = tid >> 5;
    int wm = wid >> 2, wn = wid & 3;
    int e0 = blockIdx.x * 128;
    int b = blockIdx.y, half = blockIdx.z;
    const float* X = ((half == 0) ? x0 : x1) + (size_t)b * 256 * NE;
    const float* W = (half == 0) ? Wa : Wb;
    const float* bias = (half == 0) ? ba : bb;

    int eIdx = tid & 127;
    int kbase = (tid >> 7) * 32;

    float acc[2][4][4];
#pragma unroll
    for (int mi = 0; mi < 2; mi++)
#pragma unroll
        for (int ni = 0; ni < 4; ni++)
#pragma unroll
            for (int j = 0; j < 4; j++) acc[mi][ni][j] = 0.f;

    uint32_t aOff = (uint32_t)((wm * 32 + (lane & 15)) * 528 + (lane >> 4) * 16);
    uint32_t bOff = (uint32_t)((wn * 32 + (lane & 7)) * 144 + ((lane >> 3) & 1) * 16);

    // prologue: A (weights) fp16
    for (int i = tid; i < 2048; i += 256) {
        int r = i >> 5, kq = i & 31;
        float f[8];
        *(float4*)f = *(const float4*)&W[r * 256 + kq * 8];
        *(float4*)(f + 4) = *(const float4*)&W[r * 256 + kq * 8 + 4];
        *(uint4*)(sm1 + S1_AH + r * 528 + kq * 16) = pack8h(f);
    }

#define S1_LDG(KC, G, DST)                                                            \
    {                                                                                 \
        _Pragma("unroll") for (int j = 0; j < 8; j++)                                 \
            DST[j] = X[(size_t)((KC) * 64 + kbase + (G) * 8 + j) * NE + e0 + eIdx];   \
    }
#define S1_PST(BH, G, SRC)                                                            \
    {                                                                                 \
        int k0_ = kbase + (G) * 8;                                                    \
        *(uint4*)(sm1 + (BH) + eIdx * 144 + k0_ * 2) = pack8h(SRC);                   \
    }
#define S1_MMA(BH, KC, KK)                                                            \
    {                                                                                 \
        uint32_t ah_[2][4], bh_[4][2];                                                \
        _Pragma("unroll") for (int mi = 0; mi < 2; mi++)                              \
            ldsm4(ah_[mi], sb + S1_AH + aOff + mi * (16 * 528) + (KC) * 128 + (KK) * 32); \
        _Pragma("unroll") for (int ni = 0; ni < 4; ni++)                              \
            ldsm2(bh_[ni], sb + (BH) + bOff + ni * (8 * 144) + (KK) * 32);            \
        _Pragma("unroll") for (int mi = 0; mi < 2; mi++)                              \
            _Pragma("unroll") for (int ni = 0; ni < 4; ni++)                          \
                mma_f16(acc[mi][ni], ah_[mi], bh_[ni]);                               \
    }

    // prologue: B chunk 0
    {
        float gf[8];
#pragma unroll
        for (int g = 0; g < 4; g++) {
            S1_LDG(0, g, gf);
            S1_PST(S1_B0, g, gf);
        }
    }
    __syncthreads();

    float gfA[8], gfB[8];
#pragma unroll
    for (int kc = 0; kc < 4; kc++) {
        uint32_t BH = (kc & 1) ? S1_B1 : S1_B0;
        uint32_t BnH = (kc & 1) ? S1_B0 : S1_B1;
        if (kc < 3) { S1_LDG(kc + 1, 0, gfA); S1_LDG(kc + 1, 1, gfB); }
        S1_MMA(BH, kc, 0);
        S1_MMA(BH, kc, 1);
        if (kc < 3) {
            S1_PST(BnH, 0, gfA); S1_PST(BnH, 1, gfB);
            S1_LDG(kc + 1, 2, gfA); S1_LDG(kc + 1, 3, gfB);
        }
        S1_MMA(BH, kc, 2);
        S1_MMA(BH, kc, 3);
        if (kc < 3) { S1_PST(BnH, 2, gfA); S1_PST(BnH, 3, gfB); }
        __syncthreads();
    }

    // epilogue: bias, transpose through smem (fp32), pack fp16, coalesced store
    float* T = (float*)(sm1 + S1_B0);  // [r][e] stride 132 floats
#pragma unroll
    for (int mi = 0; mi < 2; mi++) {
        int r0 = wm * 32 + mi * 16 + (lane >> 2);
        int r1 = r0 + 8;
        float c0 = bias[r0], c1 = bias[r1];
#pragma unroll
        for (int ni = 0; ni < 4; ni++) {
            int ecol = wn * 32 + ni * 8 + (lane & 3) * 2;
            T[r0 * 132 + ecol] = acc[mi][ni][0] + c0;
            T[r0 * 132 + ecol + 1] = acc[mi][ni][1] + c0;
            T[r1 * 132 + ecol] = acc[mi][ni][2] + c1;
            T[r1 * 132 + ecol + 1] = acc[mi][ni][3] + c1;
        }
    }
    __syncthreads();
    __half* dst = g_XtH + (size_t)b * NE * 128;
    for (int i = tid; i < 1024; i += 256) {
        int e = i >> 3, seg = i & 7;
        float v[8];
#pragma unroll
        for (int j = 0; j < 8; j++) v[j] = T[(seg * 8 + j) * 132 + e];
        *(uint4*)&dst[(size_t)(e0 + e) * 128 + half * 64 + seg * 8] = pack8h(v);
    }
}

// ---------------- kernel 2: pipelined fused GEMM + stats (fp16, M=256 tile) ----------------
// Block 512 (16 warps 4m x 4n, warp tile 64x32). Tile M=256 (z half of 512) x N=128 edges.
// 10 phases (5 features x 2 khalves). B fragments via ldmatrix.x4 pairs.
#define SM_NIDX 0
#define SM_A0   2048
#define SM_A1   38912
#define SM_BA   75776
#define SM_BB   110592
#define SM_BC   145408
#define SM_BD   180224
#define SM_TOT  215040

__global__ __launch_bounds__(512, 1) void stage2_kernel(const int* __restrict__ gemm) {
    extern __shared__ char sm2[];
    uint32_t sb = smem_u32(sm2);
    int tid = threadIdx.x;
    int lane = tid & 31, wid = tid >> 5;
    int wm = wid >> 2, wn = wid & 3;
    int e0 = blockIdx.x * 128;
    int b = blockIdx.y, z = blockIdx.z;   // z: half of the 512 output rows (256 each)

    int4* nidx = (int4*)(sm2 + SM_NIDX);
    const __half* XtH = g_XtH + (size_t)b * NE * 128;

    float acc[4][4][4];
#pragma unroll
    for (int mi = 0; mi < 4; mi++)
#pragma unroll
        for (int ni = 0; ni < 4; ni++)
#pragma unroll
            for (int j = 0; j < 4; j++) acc[mi][ni][j] = 0.f;

    uint32_t aOff = (uint32_t)((wm * 64 + (lane & 15)) * 144 + (lane >> 4) * 16);
    // B via ldsm4: lanes 0-7 -> n-rows +0 (k+0), 8-15 -> same rows (k+16B), 16-23 -> rows+8 (k+0), 24-31 -> rows+8 (k+16B)
    uint32_t bOff = (uint32_t)((wn * 32 + ((lane >> 4) << 3) + (lane & 7)) * 272 +
                               ((lane >> 3) & 1) * 16);

#define CPA_A(G, KHP, ABASE)                                                          \
    {                                                                                 \
        const __half* s_ = g_Wh + ((size_t)(G) * 512 + z * 256) * 128 + (KHP) * 64;   \
        _Pragma("unroll") for (int i_ = 0; i_ < 4; i_++) {                            \
            int ii_ = tid + i_ * 512;                                                 \
            int row_ = ii_ >> 3, cg_ = ii_ & 7;                                       \
            CPA(sb + (ABASE) + row_ * 144 + cg_ * 16, s_ + (size_t)row_ * 128 + cg_ * 8); \
        }                                                                             \
        CPA_COMMIT();                                                                 \
    }

    uint4 ha_, hb_;
#define LDGP(P, IT)                                                                   \
    {                                                                                 \
        int idx_ = tid + (IT) * 512;                                                  \
        int e_ = idx_ >> 4, cq_ = idx_ & 15;                                          \
        int4 nn_ = nidx[e_];                                                          \
        int na_ = (P) ? nn_.y : nn_.x;                                                \
        int nc_ = (P) ? nn_.w : nn_.z;                                                \
        ha_ = *(const uint4*)&XtH[(size_t)na_ * 128 + cq_ * 8];                       \
        hb_ = *(const uint4*)&XtH[(size_t)nc_ * 128 + cq_ * 8];                       \
    }
#define PSTP(SUMB, DIFB, IT)                                                          \
    {                                                                                 \
        int idx_ = tid + (IT) * 512;                                                  \
        int e_ = idx_ >> 4, cq_ = idx_ & 15;                                          \
        uint4 so_, do_;                                                               \
        __half2* pa_ = (__half2*)&ha_;                                                \
        __half2* pb_ = (__half2*)&hb_;                                                \
        __half2* ps_ = (__half2*)&so_;                                                \
        __half2* pd_ = (__half2*)&do_;                                                \
        _Pragma("unroll") for (int j_ = 0; j_ < 4; j_++) {                            \
            ps_[j_] = __hadd2(pa_[j_], pb_[j_]);                                      \
            pd_[j_] = __habs2(__hsub2(pa_[j_], pb_[j_]));                             \
        }                                                                             \
        *(uint4*)(sm2 + (SUMB) + e_ * 272 + cq_ * 16) = so_;                          \
        *(uint4*)(sm2 + (DIFB) + e_ * 272 + cq_ * 16) = do_;                          \
    }

#define MMA_STEP(ABASE, BBASE, KBA, KBB)                                              \
    {                                                                                 \
        uint32_t ah_[4][4], bb_[2][4];                                                \
        _Pragma("unroll") for (int mi = 0; mi < 4; mi++)                              \
            ldsm4(ah_[mi], sb + (ABASE) + aOff + mi * (16 * 144) + (KBA));            \
        _Pragma("unroll") for (int p = 0; p < 2; p++)                                 \
            ldsm4(bb_[p], sb + (BBASE) + bOff + p * (16 * 272) + (KBB));              \
        _Pragma("unroll") for (int mi = 0; mi < 4; mi++)                              \
            _Pragma("unroll") for (int ni = 0; ni < 4; ni++)                          \
                mma_f16(acc[mi][ni], ah_[mi], &bb_[ni >> 1][(ni & 1) * 2]);           \
    }

    // ---- prologue: A(feat0,kh0)->A0; nidx; self tile -> BA via cp.async ----
    CPA_A(0, 0, SM_A0);
    if (tid < 128) nidx[tid] = ((const int4*)gemm)[(size_t)b * NE + e0 + tid];
#pragma unroll
    for (int it = 0; it < 4; it++) {
        int ii = tid + it * 512;
        int e = ii >> 4, cq = ii & 15;
        CPA(sb + SM_BA + e * 272 + cq * 16, XtH + (size_t)(e0 + e) * 128 + cq * 8);
    }
    CPA_COMMIT();
    CPA_WAIT();
    __syncthreads();

#define PHASE(PRE, BBASE, KH, G0, G1, G2, G3)                                         \
    PRE                                                                               \
    G0                                                                                \
    MMA_STEP((KH) ? SM_A1 : SM_A0, BBASE, 0, ((KH) * 4 + 0) * 32);                    \
    MMA_STEP((KH) ? SM_A1 : SM_A0, BBASE, 32, ((KH) * 4 + 1) * 32);                   \
    G1 G2                                                                             \
    MMA_STEP((KH) ? SM_A1 : SM_A0, BBASE, 64, ((KH) * 4 + 2) * 32);                   \
    MMA_STEP((KH) ? SM_A1 : SM_A0, BBASE, 96, ((KH) * 4 + 3) * 32);                   \
    G3                                                                                \
    CPA_WAIT();                                                                       \
    __syncthreads();

    // P1-P2: self (W0); gather pair0 -> BB(sum), BC(diff)
    PHASE(CPA_A(0, 1, SM_A1);, SM_BA, 0,
          LDGP(0, 0);, PSTP(SM_BB, SM_BC, 0);, LDGP(0, 1);, PSTP(SM_BB, SM_BC, 1);)
    PHASE(CPA_A(1, 0, SM_A0);, SM_BA, 1,
          LDGP(0, 2);, PSTP(SM_BB, SM_BC, 2);, LDGP(0, 3);, PSTP(SM_BB, SM_BC, 3);)
    // P3-P4: sum0 (W1); gather pair1 -> BD(sum), BA(diff; BA free after P2)
    PHASE(CPA_A(1, 1, SM_A1);, SM_BB, 0,
          LDGP(1, 0);, PSTP(SM_BD, SM_BA, 0);, LDGP(1, 1);, PSTP(SM_BD, SM_BA, 1);)
    PHASE(CPA_A(3, 0, SM_A0);, SM_BB, 1,
          LDGP(1, 2);, PSTP(SM_BD, SM_BA, 2);, LDGP(1, 3);, PSTP(SM_BD, SM_BA, 3);)
    // P5-P6: diff0 (W3)
    PHASE(CPA_A(3, 1, SM_A1);, SM_BC, 0, ;, ;, ;, ;)
    PHASE(CPA_A(2, 0, SM_A0);, SM_BC, 1, ;, ;, ;, ;)
    // P7-P8: sum1 (W2)
    PHASE(CPA_A(2, 1, SM_A1);, SM_BD, 0, ;, ;, ;, ;)
    PHASE(CPA_A(4, 0, SM_A0);, SM_BD, 1, ;, ;, ;, ;)
    // P9-P10: diff1 (W4, in BA)
    PHASE(CPA_A(4, 1, SM_A1);, SM_BA, 0, ;, ;, ;, ;)
    PHASE(;, SM_BA, 1, ;, ;, ;, ;)

    // ---- epilogue: bias + fp16 store + row stats ----
    float* sAcc = (float*)sm2;  // reuse nidx region: 256 rows x {sum, sumsq} = 2048B
    for (int i = tid; i < 512; i += 512) sAcc[i] = 0.f;
    __syncthreads();

    int rbase = z * 256 + wm * 64;
    int colLocal = wn * 32 + (lane & 3) * 2;
#pragma unroll
    for (int mi = 0; mi < 4; mi++) {
        int r0 = rbase + mi * 16 + (lane >> 2);
        int r1 = r0 + 8;
        float c0 = g_Cf[r0], c1 = g_Cf[r1];
        __half* d0 = g_preH + ((size_t)b * 512 + r0) * NE + e0 + colLocal;
        __half* d1 = g_preH + ((size_t)b * 512 + r1) * NE + e0 + colLocal;
        float s0 = 0.f, q0 = 0.f, s1 = 0.f, q1 = 0.f;
#pragma unroll
        for (int ni = 0; ni < 4; ni++) {
            float v00 = acc[mi][ni][0] + c0, v01 = acc[mi][ni][1] + c0;
            float v10 = acc[mi][ni][2] + c1, v11 = acc[mi][ni][3] + c1;
            *(__half2*)(d0 + ni * 8) = __floats2half2_rn(v00, v01);
            *(__half2*)(d1 + ni * 8) = __floats2half2_rn(v10, v11);
            s0 += v00 + v01; q0 += v00 * v00 + v01 * v01;
            s1 += v10 + v11; q1 += v10 * v10 + v11 * v11;
        }
#pragma unroll
        for (int o = 1; o <= 2; o <<= 1) {
            s0 += __shfl_xor_sync(0xFFFFFFFFu, s0, o);
            q0 += __shfl_xor_sync(0xFFFFFFFFu, q0, o);
            s1 += __shfl_xor_sync(0xFFFFFFFFu, s1, o);
            q1 += __shfl_xor_sync(0xFFFFFFFFu, q1, o);
        }
        if ((lane & 3) == 0) {
            int rl0 = wm * 64 + mi * 16 + (lane >> 2);
            atomicAdd(&sAcc[rl0 * 2], s0);
            atomicAdd(&sAcc[rl0 * 2 + 1], q0);
            atomicAdd(&sAcc[(rl0 + 8) * 2], s1);
            atomicAdd(&sAcc[(rl0 + 8) * 2 + 1], q1);
        }
    }
    __syncthreads();
    for (int i = tid; i < 512; i += 512) {
        int rowl = i >> 1;
        int gidx = b * 512 + z * 256 + rowl;
        if (i & 1) atomicAdd(&g_S2[gidx], sAcc[i]);
        else       atomicAdd(&g_S[gidx], sAcc[i]);
    }
}

// ---------------- kernel 3: finalize instance-norm stats ----------------
__global__ void stats_finalize() {
    int i = blockIdx.x * 256 + threadIdx.x;  // 0..1023
    float mean = g_S[i] / (float)NE;
    float var = g_S2[i] / (float)NE - mean * mean;
    g_mean[i] = mean;
    g_rstd[i] = rsqrtf(var + 1e-5f);
}

// ---------------- kernel 4: fused norm + sigmoid + softmax blend ----------------
__global__ __launch_bounds__(256) void final_kernel(const float* __restrict__ x0,
                                                    const float* __restrict__ x1,
                                                    float* __restrict__ out) {
    size_t idx = (size_t)blockIdx.x * 256 + threadIdx.x;  // float4 index
    int e4 = (int)(idx & (NE / 4 - 1));
    int c = (int)((idx >> 14) & 255);
    int b = (int)(idx >> 22);

    uint2 pau = *(const uint2*)&g_preH[((size_t)b * 512 + c) * NE + e4 * 4];
    uint2 pbu = *(const uint2*)&g_preH[((size_t)b * 512 + 256 + c) * NE + e4 * 4];
    float2 pa01 = __half22float2(*(__half2*)&pau.x);
    float2 pa23 = __half22float2(*(__half2*)&pau.y);
    float2 pb01 = __half22float2(*(__half2*)&pbu.x);
    float2 pb23 = __half22float2(*(__half2*)&pbu.y);
    float4 pa = make_float4(pa01.x, pa01.y, pa23.x, pa23.y);
    float4 pb = make_float4(pb01.x, pb01.y, pb23.x, pb23.y);
    float4 a0 = ((const float4*)x0)[idx];
    float4 a1 = ((const float4*)x1)[idx];

    float ma = g_mean[b * 512 + c], ra = g_rstd[b * 512 + c];
    float mb = g_mean[b * 512 + 256 + c], rb = g_rstd[b * 512 + 256 + c];

    float4 o;
#define BLEND(fld)                                              \
    {                                                           \
        float za = (pa.fld - ma) * ra;                          \
        float zb = (pb.fld - mb) * rb;                          \
        float wa = 1.f / (1.f + expf(-za));                     \
        float wb = 1.f / (1.f + expf(-zb));                     \
        float w0 = 1.f / (1.f + expf(wb - wa));                 \
        o.fld = a0.fld * w0 + a1.fld * (1.f - w0);              \
    }
    BLEND(x); BLEND(y); BLEND(z); BLEND(w);
#undef BLEND
    ((float4*)out)[idx] = o;
}

// ---------------- launch ----------------
extern "C" void kernel_launch(void* const* d_in, const int* in_sizes, int n_in,
                              void* d_out, int out_size) {
    const float* x0  = (const float*)d_in[0];
    const float* x1  = (const float*)d_in[1];
    const int*   gm  = (const int*)d_in[2];
    const float* Wa  = (const float*)d_in[3];
    const float* ba  = (const float*)d_in[4];
    const float* Wb  = (const float*)d_in[5];
    const float* bb  = (const float*)d_in[6];
    const float* Wal = (const float*)d_in[7];
    const float* bal = (const float*)d_in[8];
    const float* Wbl = (const float*)d_in[9];
    const float* bbl = (const float*)d_in[10];
    const float* Wat = (const float*)d_in[11];
    const float* bat = (const float*)d_in[12];
    const float* Wbt = (const float*)d_in[13];
    const float* bbt = (const float*)d_in[14];
    const float* Waf = (const float*)d_in[15];
    const float* baf = (const float*)d_in[16];
    const float* Wbf = (const float*)d_in[17];
    const float* bbf = (const float*)d_in[18];
    float* out = (float*)d_out;

    fold_w_kernel<<<512, 128>>>(Waf, Wal, Wat, Wbf, Wbl, Wbt);
    fold_c_kernel<<<1, 512>>>(Waf, bal, bat, baf, Wbf, bbl, bbt, bbf);

    cudaFuncSetAttribute(stage1_kernel, cudaFuncAttributeMaxDynamicSharedMemorySize, S1_TOT);
    stage1_kernel<<<dim3(NE / 128, NB, 2), 256, S1_TOT>>>(x0, x1, Wa, ba, Wb, bb);

    cudaFuncSetAttribute(stage2_kernel, cudaFuncAttributeMaxDynamicSharedMemorySize, SM_TOT);
    stage2_kernel<<<dim3(NE / 128, NB, 2), 512, SM_TOT>>>(gm);

    stats_finalize<<<4, 256>>>();

    final_kernel<<<(NB * 256 * (NE / 4)) / 256, 256>>>(x0, x1, out);
}

// round 12
// speedup vs baseline: 5.5156x; 1.0801x over previous
#include <cuda_runtime.h>
#include <cuda_fp16.h>
#include <math.h>
#include <stdint.h>

// Problem constants: B=2, C=256, N=65536.
#define NE 65536
#define NB 2

// ---------------- scratch (device globals; no allocations) ----------------
__device__ __align__(16) __half g_XtH[(size_t)NB * NE * 128];   // x_all transposed fp16 [b][e][c]
__device__ __align__(16) __half g_preH[(size_t)NB * 512 * NE];  // pre-activations fp16 [b][r][e]
__device__ __align__(16) __half g_Wh[5 * 512 * 128];            // folded W fp16
__device__ float g_Cf[512];
__device__ float g_S[NB * 512];
__device__ float g_S2[NB * 512];
__device__ float g_mean[NB * 512];
__device__ float g_rstd[NB * 512];

// ================= helpers =================
__device__ __forceinline__ uint32_t smem_u32(const void* p) {
    uint32_t a;
    asm("{ .reg .u64 t; cvta.to.shared.u64 t, %1; cvt.u32.u64 %0, t; }" : "=r"(a) : "l"(p));
    return a;
}
__device__ __forceinline__ void ldsm4(uint32_t* r, uint32_t addr) {
    asm volatile("ldmatrix.sync.aligned.m8n8.x4.shared.b16 {%0, %1, %2, %3}, [%4];"
                 : "=r"(r[0]), "=r"(r[1]), "=r"(r[2]), "=r"(r[3]) : "r"(addr));
}
__device__ __forceinline__ void ldsm2(uint32_t* r, uint32_t addr) {
    asm volatile("ldmatrix.sync.aligned.m8n8.x2.shared.b16 {%0, %1}, [%2];"
                 : "=r"(r[0]), "=r"(r[1]) : "r"(addr));
}
__device__ __forceinline__ void mma_f16(float* d, const uint32_t* a, const uint32_t* b) {
    asm volatile(
        "mma.sync.aligned.m16n8k16.row.col.f32.f16.f16.f32 "
        "{%0,%1,%2,%3}, {%4,%5,%6,%7}, {%8,%9}, {%0,%1,%2,%3};"
        : "+f"(d[0]), "+f"(d[1]), "+f"(d[2]), "+f"(d[3])
        : "r"(a[0]), "r"(a[1]), "r"(a[2]), "r"(a[3]), "r"(b[0]), "r"(b[1]));
}
#define CPA(dst, src) \
    asm volatile("cp.async.ca.shared.global [%0], [%1], 16;" :: "r"(dst), "l"(src))
#define CPA_COMMIT() asm volatile("cp.async.commit_group;" ::: "memory")
#define CPA_WAIT() asm volatile("cp.async.wait_group 0;" ::: "memory")

// pack 8 floats -> 8 fp16 (one uint4)
__device__ __forceinline__ uint4 pack8h(const float* f) {
    uint4 o;
    __half2 h;
    h = __floats2half2_rn(f[0], f[1]); o.x = *reinterpret_cast<unsigned*>(&h);
    h = __floats2half2_rn(f[2], f[3]); o.y = *reinterpret_cast<unsigned*>(&h);
    h = __floats2half2_rn(f[4], f[5]); o.z = *reinterpret_cast<unsigned*>(&h);
    h = __floats2half2_rn(f[6], f[7]); o.w = *reinterpret_cast<unsigned*>(&h);
    return o;
}

// ---------------- kernel 0a: fold weight matrices (emit fp16) ----------------
__global__ void fold_w_kernel(const float* __restrict__ Waf, const float* __restrict__ Wal,
                              const float* __restrict__ Wat,
                              const float* __restrict__ Wbf, const float* __restrict__ Wbl,
                              const float* __restrict__ Wbt) {
    int r = blockIdx.x;
    int c = threadIdx.x;
    const float *F, *L, *T;
    if (r < 256) { F = Waf; L = Wal; T = Wat; } else { F = Wbf; L = Wbl; T = Wbt; }
    int rr = r & 255;
    float a[5] = {0.f, 0.f, 0.f, 0.f, 0.f};
    for (int j = 0; j < 128; j++) {
        float fl = F[rr * 256 + j];
        float fr = F[rr * 256 + 128 + j];
        a[0] += fl * L[j * 128 + c];
        const float* t = &T[(j * 128 + c) * 5];
        a[0] += fr * t[0];
        a[1] += fr * t[1];
        a[2] += fr * t[2];
        a[3] += fr * t[3];
        a[4] += fr * t[4];
    }
#pragma unroll
    for (int g = 0; g < 5; g++)
        g_Wh[(g * 512 + r) * 128 + c] = __float2half_rn(a[g]);
}

// ---------------- kernel 0b: fold bias (parallel) + zero stats accumulators ----------------
__global__ void fold_c_kernel(const float* __restrict__ Waf, const float* __restrict__ bal,
                              const float* __restrict__ bat, const float* __restrict__ baf,
                              const float* __restrict__ Wbf, const float* __restrict__ bbl,
                              const float* __restrict__ bbt, const float* __restrict__ bbf) {
    int r = blockIdx.x;   // 0..511
    int t = threadIdx.x;  // 0..127
    const float *F, *lb, *tb, *fb;
    if (r < 256) { F = Waf; lb = bal; tb = bat; fb = baf; }
    else         { F = Wbf; lb = bbl; tb = bbt; fb = bbf; }
    int rr = r & 255;
    float s = F[rr * 256 + t] * lb[t] + F[rr * 256 + 128 + t] * tb[t];
    __shared__ float red[128];
    red[t] = s;
    __syncthreads();
    for (int st = 64; st > 0; st >>= 1) {
        if (t < st) red[t] += red[t + st];
        __syncthreads();
    }
    if (t == 0) {
        g_Cf[r] = red[0] + fb[rr];
        g_S[r] = 0.f; g_S[r + 512] = 0.f;
        g_S2[r] = 0.f; g_S2[r + 512] = 0.f;
    }
}

// ---------------- kernel 1: x_all via mma.sync fp16, stored transposed fp16 ----------------
// Block 256 (8 warps 2x4). Tile M=64 rows x N=128 edges, K=256 in 4 chunks of 64.
#define S1_AH  0            // 64 x 528B
#define S1_B0  33792        // 128 x 144B
#define S1_B1  52224
#define S1_TOT 70656

__global__ __launch_bounds__(256) void stage1_kernel(
    const float* __restrict__ x0, const float* __restrict__ x1,
    const float* __restrict__ Wa, const float* __restrict__ ba,
    const float* __restrict__ Wb, const float* __restrict__ bb) {
    extern __shared__ char sm1[];
    uint32_t sb = smem_u32(sm1);
    int tid = threadIdx.x;
    int lane = tid & 31, wid = tid >> 5;
    int wm = wid >> 2, wn = wid & 3;
    int e0 = blockIdx.x * 128;
    int b = blockIdx.y, half = blockIdx.z;
    const float* X = ((half == 0) ? x0 : x1) + (size_t)b * 256 * NE;
    const float* W = (half == 0) ? Wa : Wb;
    const float* bias = (half == 0) ? ba : bb;

    int eIdx = tid & 127;
    int kbase = (tid >> 7) * 32;

    float acc[2][4][4];
#pragma unroll
    for (int mi = 0; mi < 2; mi++)
#pragma unroll
        for (int ni = 0; ni < 4; ni++)
#pragma unroll
            for (int j = 0; j < 4; j++) acc[mi][ni][j] = 0.f;

    uint32_t aOff = (uint32_t)((wm * 32 + (lane & 15)) * 528 + (lane >> 4) * 16);
    uint32_t bOff = (uint32_t)((wn * 32 + (lane & 7)) * 144 + ((lane >> 3) & 1) * 16);

    // prologue: A (weights) fp16
    for (int i = tid; i < 2048; i += 256) {
        int r = i >> 5, kq = i & 31;
        float f[8];
        *(float4*)f = *(const float4*)&W[r * 256 + kq * 8];
        *(float4*)(f + 4) = *(const float4*)&W[r * 256 + kq * 8 + 4];
        *(uint4*)(sm1 + S1_AH + r * 528 + kq * 16) = pack8h(f);
    }

#define S1_LDG(KC, G, DST)                                                            \
    {                                                                                 \
        _Pragma("unroll") for (int j = 0; j < 8; j++)                                 \
            DST[j] = X[(size_t)((KC) * 64 + kbase + (G) * 8 + j) * NE + e0 + eIdx];   \
    }
#define S1_PST(BH, G, SRC)                                                            \
    {                                                                                 \
        int k0_ = kbase + (G) * 8;                                                    \
        *(uint4*)(sm1 + (BH) + eIdx * 144 + k0_ * 2) = pack8h(SRC);                   \
    }
#define S1_MMA(BH, KC, KK)                                                            \
    {                                                                                 \
        uint32_t ah_[2][4], bh_[4][2];                                                \
        _Pragma("unroll") for (int mi = 0; mi < 2; mi++)                              \
            ldsm4(ah_[mi], sb + S1_AH + aOff + mi * (16 * 528) + (KC) * 128 + (KK) * 32); \
        _Pragma("unroll") for (int ni = 0; ni < 4; ni++)                              \
            ldsm2(bh_[ni], sb + (BH) + bOff + ni * (8 * 144) + (KK) * 32);            \
        _Pragma("unroll") for (int mi = 0; mi < 2; mi++)                              \
            _Pragma("unroll") for (int ni = 0; ni < 4; ni++)                          \
                mma_f16(acc[mi][ni], ah_[mi], bh_[ni]);                               \
    }

    // prologue: B chunk 0
    {
        float gf[8];
#pragma unroll
        for (int g = 0; g < 4; g++) {
            S1_LDG(0, g, gf);
            S1_PST(S1_B0, g, gf);
        }
    }
    __syncthreads();

    float gfA[8], gfB[8];
#pragma unroll
    for (int kc = 0; kc < 4; kc++) {
        uint32_t BH = (kc & 1) ? S1_B1 : S1_B0;
        uint32_t BnH = (kc & 1) ? S1_B0 : S1_B1;
        if (kc < 3) { S1_LDG(kc + 1, 0, gfA); S1_LDG(kc + 1, 1, gfB); }
        S1_MMA(BH, kc, 0);
        S1_MMA(BH, kc, 1);
        if (kc < 3) {
            S1_PST(BnH, 0, gfA); S1_PST(BnH, 1, gfB);
            S1_LDG(kc + 1, 2, gfA); S1_LDG(kc + 1, 3, gfB);
        }
        S1_MMA(BH, kc, 2);
        S1_MMA(BH, kc, 3);
        if (kc < 3) { S1_PST(BnH, 2, gfA); S1_PST(BnH, 3, gfB); }
        __syncthreads();
    }

    // epilogue: bias, transpose through smem (fp32), pack fp16, coalesced store
    float* T = (float*)(sm1 + S1_B0);  // [r][e] stride 132 floats
#pragma unroll
    for (int mi = 0; mi < 2; mi++) {
        int r0 = wm * 32 + mi * 16 + (lane >> 2);
        int r1 = r0 + 8;
        float c0 = bias[r0], c1 = bias[r1];
#pragma unroll
        for (int ni = 0; ni < 4; ni++) {
            int ecol = wn * 32 + ni * 8 + (lane & 3) * 2;
            T[r0 * 132 + ecol] = acc[mi][ni][0] + c0;
            T[r0 * 132 + ecol + 1] = acc[mi][ni][1] + c0;
            T[r1 * 132 + ecol] = acc[mi][ni][2] + c1;
            T[r1 * 132 + ecol + 1] = acc[mi][ni][3] + c1;
        }
    }
    __syncthreads();
    __half* dst = g_XtH + (size_t)b * NE * 128;
    for (int i = tid; i < 1024; i += 256) {
        int e = i >> 3, seg = i & 7;
        float v[8];
#pragma unroll
        for (int j = 0; j < 8; j++) v[j] = T[(seg * 8 + j) * 132 + e];
        *(uint4*)&dst[(size_t)(e0 + e) * 128 + half * 64 + seg * 8] = pack8h(v);
    }
}

// ---------------- kernel 2: fused GEMM + stats (fp16, M=256 tile, XOR-swizzled, 6 syncs) ---
// Block 512 (16 warps 4m x 4n, warp tile 64x32). Tile M=256 (z half) x N=128 edges.
// 5 features, one sync each. Full-K A tiles (64KB, XOR swizzle) double-buffered;
// 3 B buffers (32KB each, XOR swizzle): BA self->diff1, BB sum0->sum1, BC diff0.
// Swizzle: 16B chunks, phys = chunk ^ (row & 7); row bases multiple of 8 -> row&7 == lane&7.
#define SM_NIDX 0
#define SM_A0   2048
#define SM_A1   67584
#define SM_BA   133120
#define SM_BB   165888
#define SM_BC   198656
#define SM_TOT  231424

__global__ __launch_bounds__(512, 1) void stage2_kernel(const int* __restrict__ gemm) {
    extern __shared__ char sm2[];
    uint32_t sb = smem_u32(sm2);
    int tid = threadIdx.x;
    int lane = tid & 31, wid = tid >> 5;
    int wm = wid >> 2, wn = wid & 3;
    int e0 = blockIdx.x * 128;
    int b = blockIdx.y, z = blockIdx.z;

    int4* nidx = (int4*)(sm2 + SM_NIDX);
    const __half* XtH = g_XtH + (size_t)b * NE * 128;

    float acc[4][4][4];
#pragma unroll
    for (int mi = 0; mi < 4; mi++)
#pragma unroll
        for (int ni = 0; ni < 4; ni++)
#pragma unroll
            for (int j = 0; j < 4; j++) acc[mi][ni][j] = 0.f;

    // per-lane fragment addressing constants
    uint32_t rm = lane & 7;
    uint32_t hiA = lane >> 4;          // A: lanes 0-15 chunk-even, 16-31 chunk-odd
    uint32_t hiB = (lane >> 3) & 1;    // B: +16B within k16
    uint32_t aRbase = (uint32_t)((wm * 64 + (lane & 15)) * 256);
    uint32_t bRbase = (uint32_t)((wn * 32 + ((lane >> 4) << 3) + (lane & 7)) * 256);

#define CPA_A(G, ABASE)                                                               \
    {                                                                                 \
        const __half* s_ = g_Wh + ((size_t)(G) * 512 + z * 256) * 128;                \
        _Pragma("unroll") for (int i_ = 0; i_ < 8; i_++) {                            \
            int ii_ = tid + i_ * 512;                                                 \
            int row_ = ii_ >> 4, c_ = ii_ & 15;                                       \
            CPA(sb + (ABASE) + row_ * 256 + (((c_) ^ (row_ & 7)) << 4),               \
                s_ + (size_t)row_ * 128 + c_ * 8);                                    \
        }                                                                             \
        CPA_COMMIT();                                                                 \
    }

    uint4 ha_, hb_;
#define LDGP(P, IT)                                                                   \
    {                                                                                 \
        int idx_ = tid + (IT) * 512;                                                  \
        int e_ = idx_ >> 4, cq_ = idx_ & 15;                                          \
        int4 nn_ = nidx[e_];                                                          \
        int na_ = (P) ? nn_.y : nn_.x;                                                \
        int nc_ = (P) ? nn_.w : nn_.z;                                                \
        ha_ = *(const uint4*)&XtH[(size_t)na_ * 128 + cq_ * 8];                       \
        hb_ = *(const uint4*)&XtH[(size_t)nc_ * 128 + cq_ * 8];                       \
    }
#define PSTP(SUMB, DIFB, IT)                                                          \
    {                                                                                 \
        int idx_ = tid + (IT) * 512;                                                  \
        int e_ = idx_ >> 4, cq_ = idx_ & 15;                                          \
        uint32_t so_ = e_ * 256 + ((cq_ ^ (e_ & 7)) << 4);                            \
        uint4 sv_, dv_;                                                               \
        __half2* pa_ = (__half2*)&ha_;                                                \
        __half2* pb_ = (__half2*)&hb_;                                                \
        __half2* ps_ = (__half2*)&sv_;                                                \
        __half2* pd_ = (__half2*)&dv_;                                                \
        _Pragma("unroll") for (int j_ = 0; j_ < 4; j_++) {                            \
            ps_[j_] = __hadd2(pa_[j_], pb_[j_]);                                      \
            pd_[j_] = __habs2(__hsub2(pa_[j_], pb_[j_]));                             \
        }                                                                             \
        *(uint4*)(sm2 + (SUMB) + so_) = sv_;                                          \
        *(uint4*)(sm2 + (DIFB) + so_) = dv_;                                          \
    }

#define MMA_STEP(ABASE, BBASE, K16)                                                   \
    {                                                                                 \
        uint32_t offA_ = (((K16) * 2 + hiA) ^ rm) << 4;                               \
        uint32_t offB_ = (((K16) * 2 + hiB) ^ rm) << 4;                               \
        uint32_t ah_[4][4], bb_[2][4];                                                \
        _Pragma("unroll") for (int mi = 0; mi < 4; mi++)                              \
            ldsm4(ah_[mi], sb + (ABASE) + aRbase + mi * 4096 + offA_);                \
        _Pragma("unroll") for (int p = 0; p < 2; p++)                                 \
            ldsm4(bb_[p], sb + (BBASE) + bRbase + p * 4096 + offB_);                  \
        _Pragma("unroll") for (int mi = 0; mi < 4; mi++)                              \
            _Pragma("unroll") for (int ni = 0; ni < 4; ni++)                          \
                mma_f16(acc[mi][ni], ah_[mi], &bb_[ni >> 1][(ni & 1) * 2]);           \
    }

    // ---- prologue: A(W0)->A0; nidx; self tile -> BA (swizzled) via cp.async ----
    CPA_A(0, SM_A0);
    if (tid < 128) nidx[tid] = ((const int4*)gemm)[(size_t)b * NE + e0 + tid];
#pragma unroll
    for (int it = 0; it < 4; it++) {
        int ii = tid + it * 512;
        int e = ii >> 4, cq = ii & 15;
        CPA(sb + SM_BA + e * 256 + ((cq ^ (e & 7)) << 4),
            XtH + (size_t)(e0 + e) * 128 + cq * 8);
    }
    CPA_COMMIT();
    CPA_WAIT();
    __syncthreads();

#define FEATURE(PRE, ABASE, BBASE, G0, G1, G2, G3, G4, G5, G6, G7)                    \
    PRE                                                                               \
    G0                                                                                \
    MMA_STEP(ABASE, BBASE, 0);                                                        \
    MMA_STEP(ABASE, BBASE, 1);                                                        \
    G1 G2                                                                             \
    MMA_STEP(ABASE, BBASE, 2);                                                        \
    MMA_STEP(ABASE, BBASE, 3);                                                        \
    G3 G4                                                                             \
    MMA_STEP(ABASE, BBASE, 4);                                                        \
    MMA_STEP(ABASE, BBASE, 5);                                                        \
    G5 G6                                                                             \
    MMA_STEP(ABASE, BBASE, 6);                                                        \
    MMA_STEP(ABASE, BBASE, 7);                                                        \
    G7                                                                                \
    CPA_WAIT();                                                                       \
    __syncthreads();

    // F0: self (W0 in A0, BA); prefetch W1->A1; gather pair0 -> BB(sum0), BC(diff0)
    FEATURE(CPA_A(1, SM_A1);, SM_A0, SM_BA,
            LDGP(0, 0);, PSTP(SM_BB, SM_BC, 0);, LDGP(0, 1);, PSTP(SM_BB, SM_BC, 1);,
            LDGP(0, 2);, PSTP(SM_BB, SM_BC, 2);, LDGP(0, 3);, PSTP(SM_BB, SM_BC, 3);)
    // F1: sum0 (W1 in A1, BB); prefetch W3->A0
    FEATURE(CPA_A(3, SM_A0);, SM_A1, SM_BB, ;, ;, ;, ;, ;, ;, ;, ;)
    // F2: diff0 (W3 in A0, BC); prefetch W2->A1; gather pair1 -> BB(sum1), BA(diff1)
    FEATURE(CPA_A(2, SM_A1);, SM_A0, SM_BC,
            LDGP(1, 0);, PSTP(SM_BB, SM_BA, 0);, LDGP(1, 1);, PSTP(SM_BB, SM_BA, 1);,
            LDGP(1, 2);, PSTP(SM_BB, SM_BA, 2);, LDGP(1, 3);, PSTP(SM_BB, SM_BA, 3);)
    // F3: sum1 (W2 in A1, BB); prefetch W4->A0
    FEATURE(CPA_A(4, SM_A0);, SM_A1, SM_BB, ;, ;, ;, ;, ;, ;, ;, ;)
    // F4: diff1 (W4 in A0, BA)
    FEATURE(;, SM_A0, SM_BA, ;, ;, ;, ;, ;, ;, ;, ;)

    // ---- epilogue: bias + fp16 store + row stats ----
    float* sAcc = (float*)sm2;  // reuse nidx region: 256 rows x {sum, sumsq} = 2048B
    for (int i = tid; i < 512; i += 512) sAcc[i] = 0.f;
    __syncthreads();

    int rbase = z * 256 + wm * 64;
    int colLocal = wn * 32 + (lane & 3) * 2;
#pragma unroll
    for (int mi = 0; mi < 4; mi++) {
        int r0 = rbase + mi * 16 + (lane >> 2);
        int r1 = r0 + 8;
        float c0 = g_Cf[r0], c1 = g_Cf[r1];
        __half* d0 = g_preH + ((size_t)b * 512 + r0) * NE + e0 + colLocal;
        __half* d1 = g_preH + ((size_t)b * 512 + r1) * NE + e0 + colLocal;
        float s0 = 0.f, q0 = 0.f, s1 = 0.f, q1 = 0.f;
#pragma unroll
        for (int ni = 0; ni < 4; ni++) {
            float v00 = acc[mi][ni][0] + c0, v01 = acc[mi][ni][1] + c0;
            float v10 = acc[mi][ni][2] + c1, v11 = acc[mi][ni][3] + c1;
            *(__half2*)(d0 + ni * 8) = __floats2half2_rn(v00, v01);
            *(__half2*)(d1 + ni * 8) = __floats2half2_rn(v10, v11);
            s0 += v00 + v01; q0 += v00 * v00 + v01 * v01;
            s1 += v10 + v11; q1 += v10 * v10 + v11 * v11;
        }
#pragma unroll
        for (int o = 1; o <= 2; o <<= 1) {
            s0 += __shfl_xor_sync(0xFFFFFFFFu, s0, o);
            q0 += __shfl_xor_sync(0xFFFFFFFFu, q0, o);
            s1 += __shfl_xor_sync(0xFFFFFFFFu, s1, o);
            q1 += __shfl_xor_sync(0xFFFFFFFFu, q1, o);
        }
        if ((lane & 3) == 0) {
            int rl0 = wm * 64 + mi * 16 + (lane >> 2);
            atomicAdd(&sAcc[rl0 * 2], s0);
            atomicAdd(&sAcc[rl0 * 2 + 1], q0);
            atomicAdd(&sAcc[(rl0 + 8) * 2], s1);
            atomicAdd(&sAcc[(rl0 + 8) * 2 + 1], q1);
        }
    }
    __syncthreads();
    for (int i = tid; i < 512; i += 512) {
        int rowl = i >> 1;
        int gidx = b * 512 + z * 256 + rowl;
        if (i & 1) atomicAdd(&g_S2[gidx], sAcc[i]);
        else       atomicAdd(&g_S[gidx], sAcc[i]);
    }
}

// ---------------- kernel 3: finalize instance-norm stats ----------------
__global__ void stats_finalize() {
    int i = blockIdx.x * 256 + threadIdx.x;  // 0..1023
    float mean = g_S[i] / (float)NE;
    float var = g_S2[i] / (float)NE - mean * mean;
    g_mean[i] = mean;
    g_rstd[i] = rsqrtf(var + 1e-5f);
}

// ---------------- kernel 4: fused norm + sigmoid + softmax blend ----------------
__global__ __launch_bounds__(256) void final_kernel(const float* __restrict__ x0,
                                                    const float* __restrict__ x1,
                                                    float* __restrict__ out) {
    size_t idx = (size_t)blockIdx.x * 256 + threadIdx.x;  // float4 index
    int e4 = (int)(idx & (NE / 4 - 1));
    int c = (int)((idx >> 14) & 255);
    int b = (int)(idx >> 22);

    uint2 pau = *(const uint2*)&g_preH[((size_t)b * 512 + c) * NE + e4 * 4];
    uint2 pbu = *(const uint2*)&g_preH[((size_t)b * 512 + 256 + c) * NE + e4 * 4];
    float2 pa01 = __half22float2(*(__half2*)&pau.x);
    float2 pa23 = __half22float2(*(__half2*)&pau.y);
    float2 pb01 = __half22float2(*(__half2*)&pbu.x);
    float2 pb23 = __half22float2(*(__half2*)&pbu.y);
    float4 pa = make_float4(pa01.x, pa01.y, pa23.x, pa23.y);
    float4 pb = make_float4(pb01.x, pb01.y, pb23.x, pb23.y);
    float4 a0 = ((const float4*)x0)[idx];
    float4 a1 = ((const float4*)x1)[idx];

    float ma = g_mean[b * 512 + c], ra = g_rstd[b * 512 + c];
    float mb = g_mean[b * 512 + 256 + c], rb = g_rstd[b * 512 + 256 + c];

    float4 o;
#define BLEND(fld)                                              \
    {                                                           \
        float za = (pa.fld - ma) * ra;                          \
        float zb = (pb.fld - mb) * rb;                          \
        float wa = 1.f / (1.f + expf(-za));                     \
        float wb = 1.f / (1.f + expf(-zb));                     \
        float w0 = 1.f / (1.f + expf(wb - wa));                 \
        o.fld = a0.fld * w0 + a1.fld * (1.f - w0);              \
    }
    BLEND(x); BLEND(y); BLEND(z); BLEND(w);
#undef BLEND
    ((float4*)out)[idx] = o;
}

// ---------------- launch ----------------
extern "C" void kernel_launch(void* const* d_in, const int* in_sizes, int n_in,
                              void* d_out, int out_size) {
    const float* x0  = (const float*)d_in[0];
    const float* x1  = (const float*)d_in[1];
    const int*   gm  = (const int*)d_in[2];
    const float* Wa  = (const float*)d_in[3];
    const float* ba  = (const float*)d_in[4];
    const float* Wb  = (const float*)d_in[5];
    const float* bb  = (const float*)d_in[6];
    const float* Wal = (const float*)d_in[7];
    const float* bal = (const float*)d_in[8];
    const float* Wbl = (const float*)d_in[9];
    const float* bbl = (const float*)d_in[10];
    const float* Wat = (const float*)d_in[11];
    const float* bat = (const float*)d_in[12];
    const float* Wbt = (const float*)d_in[13];
    const float* bbt = (const float*)d_in[14];
    const float* Waf = (const float*)d_in[15];
    const float* baf = (const float*)d_in[16];
    const float* Wbf = (const float*)d_in[17];
    const float* bbf = (const float*)d_in[18];
    float* out = (float*)d_out;

    fold_w_kernel<<<512, 128>>>(Waf, Wal, Wat, Wbf, Wbl, Wbt);
    fold_c_kernel<<<512, 128>>>(Waf, bal, bat, baf, Wbf, bbl, bbt, bbf);

    cudaFuncSetAttribute(stage1_kernel, cudaFuncAttributeMaxDynamicSharedMemorySize, S1_TOT);
    stage1_kernel<<<dim3(NE / 128, NB, 2), 256, S1_TOT>>>(x0, x1, Wa, ba, Wb, bb);

    cudaFuncSetAttribute(stage2_kernel, cudaFuncAttributeMaxDynamicSharedMemorySize, SM_TOT);
    stage2_kernel<<<dim3(NE / 128, NB, 2), 512, SM_TOT>>>(gm);

    stats_finalize<<<4, 256>>>();

    final_kernel<<<(NB * 256 * (NE / 4)) / 256, 256>>>(x0, x1, out);
}

// round 15
// speedup vs baseline: 5.7695x; 1.0460x over previous
#include <cuda_runtime.h>
#include <cuda_fp16.h>
#include <math.h>
#include <stdint.h>

// Problem constants: B=2, C=256, N=65536.
#define NE 65536
#define NB 2

// ---------------- scratch (device globals; no allocations) ----------------
__device__ __align__(16) __half g_XtH[(size_t)NB * NE * 128];   // x_all transposed fp16 [b][e][c]
__device__ __align__(16) __half g_preH[(size_t)NB * 512 * NE];  // pre-activations fp16 [b][r][e]
__device__ __align__(16) __half g_Wh[5 * 512 * 128];            // folded W fp16
__device__ float g_Cf[512];
__device__ float g_S[NB * 512];
__device__ float g_S2[NB * 512];
__device__ float g_mean[NB * 512];
__device__ float g_rstd[NB * 512];

// ================= helpers =================
__device__ __forceinline__ uint32_t smem_u32(const void* p) {
    uint32_t a;
    asm("{ .reg .u64 t; cvta.to.shared.u64 t, %1; cvt.u32.u64 %0, t; }" : "=r"(a) : "l"(p));
    return a;
}
__device__ __forceinline__ void ldsm4(uint32_t* r, uint32_t addr) {
    asm volatile("ldmatrix.sync.aligned.m8n8.x4.shared.b16 {%0, %1, %2, %3}, [%4];"
                 : "=r"(r[0]), "=r"(r[1]), "=r"(r[2]), "=r"(r[3]) : "r"(addr));
}
__device__ __forceinline__ void ldsm2(uint32_t* r, uint32_t addr) {
    asm volatile("ldmatrix.sync.aligned.m8n8.x2.shared.b16 {%0, %1}, [%2];"
                 : "=r"(r[0]), "=r"(r[1]) : "r"(addr));
}
__device__ __forceinline__ void mma_f16(float* d, const uint32_t* a, const uint32_t* b) {
    asm volatile(
        "mma.sync.aligned.m16n8k16.row.col.f32.f16.f16.f32 "
        "{%0,%1,%2,%3}, {%4,%5,%6,%7}, {%8,%9}, {%0,%1,%2,%3};"
        : "+f"(d[0]), "+f"(d[1]), "+f"(d[2]), "+f"(d[3])
        : "r"(a[0]), "r"(a[1]), "r"(a[2]), "r"(a[3]), "r"(b[0]), "r"(b[1]));
}
#define CPA(dst, src) \
    asm volatile("cp.async.ca.shared.global [%0], [%1], 16;" :: "r"(dst), "l"(src))
#define CPA_COMMIT() asm volatile("cp.async.commit_group;" ::: "memory")
#define CPA_WAIT() asm volatile("cp.async.wait_group 0;" ::: "memory")

// pack 8 floats -> 8 fp16 (one uint4)
__device__ __forceinline__ uint4 pack8h(const float* f) {
    uint4 o;
    __half2 h;
    h = __floats2half2_rn(f[0], f[1]); o.x = *reinterpret_cast<unsigned*>(&h);
    h = __floats2half2_rn(f[2], f[3]); o.y = *reinterpret_cast<unsigned*>(&h);
    h = __floats2half2_rn(f[4], f[5]); o.z = *reinterpret_cast<unsigned*>(&h);
    h = __floats2half2_rn(f[6], f[7]); o.w = *reinterpret_cast<unsigned*>(&h);
    return o;
}

// ---------------- kernel 0a: fold weight matrices (emit fp16) ----------------
__global__ void fold_w_kernel(const float* __restrict__ Waf, const float* __restrict__ Wal,
                              const float* __restrict__ Wat,
                              const float* __restrict__ Wbf, const float* __restrict__ Wbl,
                              const float* __restrict__ Wbt) {
    int r = blockIdx.x;
    int c = threadIdx.x;
    const float *F, *L, *T;
    if (r < 256) { F = Waf; L = Wal; T = Wat; } else { F = Wbf; L = Wbl; T = Wbt; }
    int rr = r & 255;
    float a[5] = {0.f, 0.f, 0.f, 0.f, 0.f};
    for (int j = 0; j < 128; j++) {
        float fl = F[rr * 256 + j];
        float fr = F[rr * 256 + 128 + j];
        a[0] += fl * L[j * 128 + c];
        const float* t = &T[(j * 128 + c) * 5];
        a[0] += fr * t[0];
        a[1] += fr * t[1];
        a[2] += fr * t[2];
        a[3] += fr * t[3];
        a[4] += fr * t[4];
    }
#pragma unroll
    for (int g = 0; g < 5; g++)
        g_Wh[(g * 512 + r) * 128 + c] = __float2half_rn(a[g]);
}

// ---------------- kernel 0b: fold bias (parallel) + zero stats accumulators ----------------
__global__ void fold_c_kernel(const float* __restrict__ Waf, const float* __restrict__ bal,
                              const float* __restrict__ bat, const float* __restrict__ baf,
                              const float* __restrict__ Wbf, const float* __restrict__ bbl,
                              const float* __restrict__ bbt, const float* __restrict__ bbf) {
    int r = blockIdx.x;   // 0..511
    int t = threadIdx.x;  // 0..127
    const float *F, *lb, *tb, *fb;
    if (r < 256) { F = Waf; lb = bal; tb = bat; fb = baf; }
    else         { F = Wbf; lb = bbl; tb = bbt; fb = bbf; }
    int rr = r & 255;
    float s = F[rr * 256 + t] * lb[t] + F[rr * 256 + 128 + t] * tb[t];
    __shared__ float red[128];
    red[t] = s;
    __syncthreads();
    for (int st = 64; st > 0; st >>= 1) {
        if (t < st) red[t] += red[t + st];
        __syncthreads();
    }
    if (t == 0) {
        g_Cf[r] = red[0] + fb[rr];
        g_S[r] = 0.f; g_S[r + 512] = 0.f;
        g_S2[r] = 0.f; g_S2[r + 512] = 0.f;
    }
}

// ---------------- kernel 1: x_all via mma.sync fp16, stored transposed fp16 ----------------
// Block 256 (8 warps 2x4). Tile M=64 rows x N=128 edges, K=256 in 4 chunks of 64.
#define S1_AH  0            // 64 x 528B
#define S1_B0  33792        // 128 x 144B
#define S1_B1  52224
#define S1_TOT 70656

__global__ __launch_bounds__(256) void stage1_kernel(
    const float* __restrict__ x0, const float* __restrict__ x1,
    const float* __restrict__ Wa, const float* __restrict__ ba,
    const float* __restrict__ Wb, const float* __restrict__ bb) {
    extern __shared__ char sm1[];
    uint32_t sb = smem_u32(sm1);
    int tid = threadIdx.x;
    int lane = tid & 31, wid = tid >> 5;
    int wm = wid >> 2, wn = wid & 3;
    int e0 = blockIdx.x * 128;
    int b = blockIdx.y, half = blockIdx.z;
    const float* X = ((half == 0) ? x0 : x1) + (size_t)b * 256 * NE;
    const float* W = (half == 0) ? Wa : Wb;
    const float* bias = (half == 0) ? ba : bb;

    int eIdx = tid & 127;
    int kbase = (tid >> 7) * 32;

    float acc[2][4][4];
#pragma unroll
    for (int mi = 0; mi < 2; mi++)
#pragma unroll
        for (int ni = 0; ni < 4; ni++)
#pragma unroll
            for (int j = 0; j < 4; j++) acc[mi][ni][j] = 0.f;

    uint32_t aOff = (uint32_t)((wm * 32 + (lane & 15)) * 528 + (lane >> 4) * 16);
    uint32_t bOff = (uint32_t)((wn * 32 + (lane & 7)) * 144 + ((lane >> 3) & 1) * 16);

    // prologue: A (weights) fp16
    for (int i = tid; i < 2048; i += 256) {
        int r = i >> 5, kq = i & 31;
        float f[8];
        *(float4*)f = *(const float4*)&W[r * 256 + kq * 8];
        *(float4*)(f + 4) = *(const float4*)&W[r * 256 + kq * 8 + 4];
        *(uint4*)(sm1 + S1_AH + r * 528 + kq * 16) = pack8h(f);
    }

#define S1_LDG(KC, G, DST)                                                            \
    {                                                                                 \
        _Pragma("unroll") for (int j = 0; j < 8; j++)                                 \
            DST[j] = X[(size_t)((KC) * 64 + kbase + (G) * 8 + j) * NE + e0 + eIdx];   \
    }
#define S1_PST(BH, G, SRC)                                                            \
    {                                                                                 \
        int k0_ = kbase + (G) * 8;                                                    \
        *(uint4*)(sm1 + (BH) + eIdx * 144 + k0_ * 2) = pack8h(SRC);                   \
    }
#define S1_MMA(BH, KC, KK)                                                            \
    {                                                                                 \
        uint32_t ah_[2][4], bh_[4][2];                                                \
        _Pragma("unroll") for (int mi = 0; mi < 2; mi++)                              \
            ldsm4(ah_[mi], sb + S1_AH + aOff + mi * (16 * 528) + (KC) * 128 + (KK) * 32); \
        _Pragma("unroll") for (int ni = 0; ni < 4; ni++)                              \
            ldsm2(bh_[ni], sb + (BH) + bOff + ni * (8 * 144) + (KK) * 32);            \
        _Pragma("unroll") for (int mi = 0; mi < 2; mi++)                              \
            _Pragma("unroll") for (int ni = 0; ni < 4; ni++)                          \
                mma_f16(acc[mi][ni], ah_[mi], bh_[ni]);                               \
    }

    // prologue: B chunk 0
    {
        float gf[8];
#pragma unroll
        for (int g = 0; g < 4; g++) {
            S1_LDG(0, g, gf);
            S1_PST(S1_B0, g, gf);
        }
    }
    __syncthreads();

    float gfA[8], gfB[8];
#pragma unroll
    for (int kc = 0; kc < 4; kc++) {
        uint32_t BH = (kc & 1) ? S1_B1 : S1_B0;
        uint32_t BnH = (kc & 1) ? S1_B0 : S1_B1;
        if (kc < 3) { S1_LDG(kc + 1, 0, gfA); S1_LDG(kc + 1, 1, gfB); }
        S1_MMA(BH, kc, 0);
        S1_MMA(BH, kc, 1);
        if (kc < 3) {
            S1_PST(BnH, 0, gfA); S1_PST(BnH, 1, gfB);
            S1_LDG(kc + 1, 2, gfA); S1_LDG(kc + 1, 3, gfB);
        }
        S1_MMA(BH, kc, 2);
        S1_MMA(BH, kc, 3);
        if (kc < 3) { S1_PST(BnH, 2, gfA); S1_PST(BnH, 3, gfB); }
        __syncthreads();
    }

    // epilogue: bias, transpose through smem (fp32), pack fp16, coalesced store
    float* T = (float*)(sm1 + S1_B0);  // [r][e] stride 132 floats
#pragma unroll
    for (int mi = 0; mi < 2; mi++) {
        int r0 = wm * 32 + mi * 16 + (lane >> 2);
        int r1 = r0 + 8;
        float c0 = bias[r0], c1 = bias[r1];
#pragma unroll
        for (int ni = 0; ni < 4; ni++) {
            int ecol = wn * 32 + ni * 8 + (lane & 3) * 2;
            T[r0 * 132 + ecol] = acc[mi][ni][0] + c0;
            T[r0 * 132 + ecol + 1] = acc[mi][ni][1] + c0;
            T[r1 * 132 + ecol] = acc[mi][ni][2] + c1;
            T[r1 * 132 + ecol + 1] = acc[mi][ni][3] + c1;
        }
    }
    __syncthreads();
    __half* dst = g_XtH + (size_t)b * NE * 128;
    for (int i = tid; i < 1024; i += 256) {
        int e = i >> 3, seg = i & 7;
        float v[8];
#pragma unroll
        for (int j = 0; j < 8; j++) v[j] = T[(seg * 8 + j) * 132 + e];
        *(uint4*)&dst[(size_t)(e0 + e) * 128 + half * 64 + seg * 8] = pack8h(v);
    }
}

// ---------------- kernel 2: pipelined fused GEMM + stats (fp16, M=256 tile) ----------------
// Block 512 (16 warps 4m x 4n, warp tile 64x32). Tile M=256 (z half of 512) x N=128 edges.
// 10 phases (5 features x 2 khalves). B fragments via ldmatrix.x4 pairs.
// (R11 measured-295us version: padded strides, immediate ldsm offsets.)
#define SM_NIDX 0
#define SM_A0   2048
#define SM_A1   38912
#define SM_BA   75776
#define SM_BB   110592
#define SM_BC   145408
#define SM_BD   180224
#define SM_TOT  215040

__global__ __launch_bounds__(512, 1) void stage2_kernel(const int* __restrict__ gemm) {
    extern __shared__ char sm2[];
    uint32_t sb = smem_u32(sm2);
    int tid = threadIdx.x;
    int lane = tid & 31, wid = tid >> 5;
    int wm = wid >> 2, wn = wid & 3;
    int e0 = blockIdx.x * 128;
    int b = blockIdx.y, z = blockIdx.z;   // z: half of the 512 output rows (256 each)

    int4* nidx = (int4*)(sm2 + SM_NIDX);
    const __half* XtH = g_XtH + (size_t)b * NE * 128;

    float acc[4][4][4];
#pragma unroll
    for (int mi = 0; mi < 4; mi++)
#pragma unroll
        for (int ni = 0; ni < 4; ni++)
#pragma unroll
            for (int j = 0; j < 4; j++) acc[mi][ni][j] = 0.f;

    uint32_t aOff = (uint32_t)((wm * 64 + (lane & 15)) * 144 + (lane >> 4) * 16);
    // B via ldsm4: lanes 0-7 -> n-rows +0 (k+0), 8-15 -> same rows (k+16B), 16-23 -> rows+8 (k+0), 24-31 -> rows+8 (k+16B)
    uint32_t bOff = (uint32_t)((wn * 32 + ((lane >> 4) << 3) + (lane & 7)) * 272 +
                               ((lane >> 3) & 1) * 16);

#define CPA_A(G, KHP, ABASE)                                                          \
    {                                                                                 \
        const __half* s_ = g_Wh + ((size_t)(G) * 512 + z * 256) * 128 + (KHP) * 64;   \
        _Pragma("unroll") for (int i_ = 0; i_ < 4; i_++) {                            \
            int ii_ = tid + i_ * 512;                                                 \
            int row_ = ii_ >> 3, cg_ = ii_ & 7;                                       \
            CPA(sb + (ABASE) + row_ * 144 + cg_ * 16, s_ + (size_t)row_ * 128 + cg_ * 8); \
        }                                                                             \
        CPA_COMMIT();                                                                 \
    }

    uint4 ha_, hb_;
#define LDGP(P, IT)                                                                   \
    {                                                                                 \
        int idx_ = tid + (IT) * 512;                                                  \
        int e_ = idx_ >> 4, cq_ = idx_ & 15;                                          \
        int4 nn_ = nidx[e_];                                                          \
        int na_ = (P) ? nn_.y : nn_.x;                                                \
        int nc_ = (P) ? nn_.w : nn_.z;                                                \
        ha_ = *(const uint4*)&XtH[(size_t)na_ * 128 + cq_ * 8];                       \
        hb_ = *(const uint4*)&XtH[(size_t)nc_ * 128 + cq_ * 8];                       \
    }
#define PSTP(SUMB, DIFB, IT)                                                          \
    {                                                                                 \
        int idx_ = tid + (IT) * 512;                                                  \
        int e_ = idx_ >> 4, cq_ = idx_ & 15;                                          \
        uint4 so_, do_;                                                               \
        __half2* pa_ = (__half2*)&ha_;                                                \
        __half2* pb_ = (__half2*)&hb_;                                                \
        __half2* ps_ = (__half2*)&so_;                                                \
        __half2* pd_ = (__half2*)&do_;                                                \
        _Pragma("unroll") for (int j_ = 0; j_ < 4; j_++) {                            \
            ps_[j_] = __hadd2(pa_[j_], pb_[j_]);                                      \
            pd_[j_] = __habs2(__hsub2(pa_[j_], pb_[j_]));                             \
        }                                                                             \
        *(uint4*)(sm2 + (SUMB) + e_ * 272 + cq_ * 16) = so_;                          \
        *(uint4*)(sm2 + (DIFB) + e_ * 272 + cq_ * 16) = do_;                          \
    }

#define MMA_STEP(ABASE, BBASE, KBA, KBB)                                              \
    {                                                                                 \
        uint32_t ah_[4][4], bb_[2][4];                                                \
        _Pragma("unroll") for (int mi = 0; mi < 4; mi++)                              \
            ldsm4(ah_[mi], sb + (ABASE) + aOff + mi * (16 * 144) + (KBA));            \
        _Pragma("unroll") for (int p = 0; p < 2; p++)                                 \
            ldsm4(bb_[p], sb + (BBASE) + bOff + p * (16 * 272) + (KBB));              \
        _Pragma("unroll") for (int mi = 0; mi < 4; mi++)                              \
            _Pragma("unroll") for (int ni = 0; ni < 4; ni++)                          \
                mma_f16(acc[mi][ni], ah_[mi], &bb_[ni >> 1][(ni & 1) * 2]);           \
    }

    // ---- prologue: A(feat0,kh0)->A0; nidx; self tile -> BA via cp.async ----
    CPA_A(0, 0, SM_A0);
    if (tid < 128) nidx[tid] = ((const int4*)gemm)[(size_t)b * NE + e0 + tid];
#pragma unroll
    for (int it = 0; it < 4; it++) {
        int ii = tid + it * 512;
        int e = ii >> 4, cq = ii & 15;
        CPA(sb + SM_BA + e * 272 + cq * 16, XtH + (size_t)(e0 + e) * 128 + cq * 8);
    }
    CPA_COMMIT();
    CPA_WAIT();
    __syncthreads();

#define PHASE(PRE, BBASE, KH, G0, G1, G2, G3)                                         \
    PRE                                                                               \
    G0                                                                                \
    MMA_STEP((KH) ? SM_A1 : SM_A0, BBASE, 0, ((KH) * 4 + 0) * 32);                    \
    MMA_STEP((KH) ? SM_A1 : SM_A0, BBASE, 32, ((KH) * 4 + 1) * 32);                   \
    G1 G2                                                                             \
    MMA_STEP((KH) ? SM_A1 : SM_A0, BBASE, 64, ((KH) * 4 + 2) * 32);                   \
    MMA_STEP((KH) ? SM_A1 : SM_A0, BBASE, 96, ((KH) * 4 + 3) * 32);                   \
    G3                                                                                \
    CPA_WAIT();                                                                       \
    __syncthreads();

    // P1-P2: self (W0); gather pair0 -> BB(sum), BC(diff)
    PHASE(CPA_A(0, 1, SM_A1);, SM_BA, 0,
          LDGP(0, 0);, PSTP(SM_BB, SM_BC, 0);, LDGP(0, 1);, PSTP(SM_BB, SM_BC, 1);)
    PHASE(CPA_A(1, 0, SM_A0);, SM_BA, 1,
          LDGP(0, 2);, PSTP(SM_BB, SM_BC, 2);, LDGP(0, 3);, PSTP(SM_BB, SM_BC, 3);)
    // P3-P4: sum0 (W1); gather pair1 -> BD(sum), BA(diff; BA free after P2)
    PHASE(CPA_A(1, 1, SM_A1);, SM_BB, 0,
          LDGP(1, 0);, PSTP(SM_BD, SM_BA, 0);, LDGP(1, 1);, PSTP(SM_BD, SM_BA, 1);)
    PHASE(CPA_A(3, 0, SM_A0);, SM_BB, 1,
          LDGP(1, 2);, PSTP(SM_BD, SM_BA, 2);, LDGP(1, 3);, PSTP(SM_BD, SM_BA, 3);)
    // P5-P6: diff0 (W3)
    PHASE(CPA_A(3, 1, SM_A1);, SM_BC, 0, ;, ;, ;, ;)
    PHASE(CPA_A(2, 0, SM_A0);, SM_BC, 1, ;, ;, ;, ;)
    // P7-P8: sum1 (W2)
    PHASE(CPA_A(2, 1, SM_A1);, SM_BD, 0, ;, ;, ;, ;)
    PHASE(CPA_A(4, 0, SM_A0);, SM_BD, 1, ;, ;, ;, ;)
    // P9-P10: diff1 (W4, in BA)
    PHASE(CPA_A(4, 1, SM_A1);, SM_BA, 0, ;, ;, ;, ;)
    PHASE(;, SM_BA, 1, ;, ;, ;, ;)

    // ---- epilogue: bias + fp16 store + row stats ----
    float* sAcc = (float*)sm2;  // reuse nidx region: 256 rows x {sum, sumsq} = 2048B
    for (int i = tid; i < 512; i += 512) sAcc[i] = 0.f;
    __syncthreads();

    int rbase = z * 256 + wm * 64;
    int colLocal = wn * 32 + (lane & 3) * 2;
#pragma unroll
    for (int mi = 0; mi < 4; mi++) {
        int r0 = rbase + mi * 16 + (lane >> 2);
        int r1 = r0 + 8;
        float c0 = g_Cf[r0], c1 = g_Cf[r1];
        __half* d0 = g_preH + ((size_t)b * 512 + r0) * NE + e0 + colLocal;
        __half* d1 = g_preH + ((size_t)b * 512 + r1) * NE + e0 + colLocal;
        float s0 = 0.f, q0 = 0.f, s1 = 0.f, q1 = 0.f;
#pragma unroll
        for (int ni = 0; ni < 4; ni++) {
            float v00 = acc[mi][ni][0] + c0, v01 = acc[mi][ni][1] + c0;
            float v10 = acc[mi][ni][2] + c1, v11 = acc[mi][ni][3] + c1;
            *(__half2*)(d0 + ni * 8) = __floats2half2_rn(v00, v01);
            *(__half2*)(d1 + ni * 8) = __floats2half2_rn(v10, v11);
            s0 += v00 + v01; q0 += v00 * v00 + v01 * v01;
            s1 += v10 + v11; q1 += v10 * v10 + v11 * v11;
        }
#pragma unroll
        for (int o = 1; o <= 2; o <<= 1) {
            s0 += __shfl_xor_sync(0xFFFFFFFFu, s0, o);
            q0 += __shfl_xor_sync(0xFFFFFFFFu, q0, o);
            s1 += __shfl_xor_sync(0xFFFFFFFFu, s1, o);
            q1 += __shfl_xor_sync(0xFFFFFFFFu, q1, o);
        }
        if ((lane & 3) == 0) {
            int rl0 = wm * 64 + mi * 16 + (lane >> 2);
            atomicAdd(&sAcc[rl0 * 2], s0);
            atomicAdd(&sAcc[rl0 * 2 + 1], q0);
            atomicAdd(&sAcc[(rl0 + 8) * 2], s1);
            atomicAdd(&sAcc[(rl0 + 8) * 2 + 1], q1);
        }
    }
    __syncthreads();
    for (int i = tid; i < 512; i += 512) {
        int rowl = i >> 1;
        int gidx = b * 512 + z * 256 + rowl;
        if (i & 1) atomicAdd(&g_S2[gidx], sAcc[i]);
        else       atomicAdd(&g_S[gidx], sAcc[i]);
    }
}

// ---------------- kernel 3: finalize instance-norm stats ----------------
__global__ void stats_finalize() {
    int i = blockIdx.x * 256 + threadIdx.x;  // 0..1023
    float mean = g_S[i] / (float)NE;
    float var = g_S2[i] / (float)NE - mean * mean;
    g_mean[i] = mean;
    g_rstd[i] = rsqrtf(var + 1e-5f);
}

// ---------------- kernel 4: fused norm + sigmoid + softmax blend ----------------
__global__ __launch_bounds__(256) void final_kernel(const float* __restrict__ x0,
                                                    const float* __restrict__ x1,
                                                    float* __restrict__ out) {
    size_t idx = (size_t)blockIdx.x * 256 + threadIdx.x;  // float4 index
    int e4 = (int)(idx & (NE / 4 - 1));
    int c = (int)((idx >> 14) & 255);
    int b = (int)(idx >> 22);

    uint2 pau = *(const uint2*)&g_preH[((size_t)b * 512 + c) * NE + e4 * 4];
    uint2 pbu = *(const uint2*)&g_preH[((size_t)b * 512 + 256 + c) * NE + e4 * 4];
    float2 pa01 = __half22float2(*(__half2*)&pau.x);
    float2 pa23 = __half22float2(*(__half2*)&pau.y);
    float2 pb01 = __half22float2(*(__half2*)&pbu.x);
    float2 pb23 = __half22float2(*(__half2*)&pbu.y);
    float4 pa = make_float4(pa01.x, pa01.y, pa23.x, pa23.y);
    float4 pb = make_float4(pb01.x, pb01.y, pb23.x, pb23.y);
    float4 a0 = ((const float4*)x0)[idx];
    float4 a1 = ((const float4*)x1)[idx];

    float ma = g_mean[b * 512 + c], ra = g_rstd[b * 512 + c];
    float mb = g_mean[b * 512 + 256 + c], rb = g_rstd[b * 512 + 256 + c];

    float4 o;
#define BLEND(fld)                                              \
    {                                                           \
        float za = (pa.fld - ma) * ra;                          \
        float zb = (pb.fld - mb) * rb;                          \
        float wa = 1.f / (1.f + expf(-za));                     \
        float wb = 1.f / (1.f + expf(-zb));                     \
        float w0 = 1.f / (1.f + expf(wb - wa));                 \
        o.fld = a0.fld * w0 + a1.fld * (1.f - w0);              \
    }
    BLEND(x); BLEND(y); BLEND(z); BLEND(w);
#undef BLEND
    ((float4*)out)[idx] = o;
}

// ---------------- launch ----------------
extern "C" void kernel_launch(void* const* d_in, const int* in_sizes, int n_in,
                              void* d_out, int out_size) {
    const float* x0  = (const float*)d_in[0];
    const float* x1  = (const float*)d_in[1];
    const int*   gm  = (const int*)d_in[2];
    const float* Wa  = (const float*)d_in[3];
    const float* ba  = (const float*)d_in[4];
    const float* Wb  = (const float*)d_in[5];
    const float* bb  = (const float*)d_in[6];
    const float* Wal = (const float*)d_in[7];
    const float* bal = (const float*)d_in[8];
    const float* Wbl = (const float*)d_in[9];
    const float* bbl = (const float*)d_in[10];
    const float* Wat = (const float*)d_in[11];
    const float* bat = (const float*)d_in[12];
    const float* Wbt = (const float*)d_in[13];
    const float* bbt = (const float*)d_in[14];
    const float* Waf = (const float*)d_in[15];
    const float* baf = (const float*)d_in[16];
    const float* Wbf = (const float*)d_in[17];
    const float* bbf = (const float*)d_in[18];
    float* out = (float*)d_out;

    fold_w_kernel<<<512, 128>>>(Waf, Wal, Wat, Wbf, Wbl, Wbt);
    fold_c_kernel<<<512, 128>>>(Waf, bal, bat, baf, Wbf, bbl, bbt, bbf);

    cudaFuncSetAttribute(stage1_kernel, cudaFuncAttributeMaxDynamicSharedMemorySize, S1_TOT);
    stage1_kernel<<<dim3(NE / 128, NB, 2), 256, S1_TOT>>>(x0, x1, Wa, ba, Wb, bb);

    cudaFuncSetAttribute(stage2_kernel, cudaFuncAttributeMaxDynamicSharedMemorySize, SM_TOT);
    stage2_kernel<<<dim3(NE / 128, NB, 2), 512, SM_TOT>>>(gm);

    stats_finalize<<<4, 256>>>();

    final_kernel<<<(NB * 256 * (NE / 4)) / 256, 256>>>(x0, x1, out);
}

// round 16
// speedup vs baseline: 5.8814x; 1.0194x over previous
#include <cuda_runtime.h>
#include <cuda_fp16.h>
#include <math.h>
#include <stdint.h>

// Problem constants: B=2, C=256, N=65536.
#define NE 65536
#define NB 2

// ---------------- scratch (device globals; no allocations) ----------------
__device__ __align__(16) __half g_XtH[(size_t)NB * NE * 128];   // x_all transposed fp16 [b][e][c]
__device__ __align__(16) __half g_preH[(size_t)NB * 512 * NE];  // pre-activations fp16 [b][r][e]
__device__ __align__(16) __half g_Wh[5 * 512 * 128];            // folded W fp16
__device__ __align__(16) __half g_W1h[2 * 64 * 256];            // stage1 weights fp16 [half][r][k]
__device__ float g_Cf[512];
__device__ float g_S[NB * 512];
__device__ float g_S2[NB * 512];
__device__ float g_mean[NB * 512];
__device__ float g_rstd[NB * 512];

// ================= helpers =================
__device__ __forceinline__ uint32_t smem_u32(const void* p) {
    uint32_t a;
    asm("{ .reg .u64 t; cvta.to.shared.u64 t, %1; cvt.u32.u64 %0, t; }" : "=r"(a) : "l"(p));
    return a;
}
__device__ __forceinline__ void ldsm4(uint32_t* r, uint32_t addr) {
    asm volatile("ldmatrix.sync.aligned.m8n8.x4.shared.b16 {%0, %1, %2, %3}, [%4];"
                 : "=r"(r[0]), "=r"(r[1]), "=r"(r[2]), "=r"(r[3]) : "r"(addr));
}
__device__ __forceinline__ void ldsm2(uint32_t* r, uint32_t addr) {
    asm volatile("ldmatrix.sync.aligned.m8n8.x2.shared.b16 {%0, %1}, [%2];"
                 : "=r"(r[0]), "=r"(r[1]) : "r"(addr));
}
__device__ __forceinline__ void mma_f16(float* d, const uint32_t* a, const uint32_t* b) {
    asm volatile(
        "mma.sync.aligned.m16n8k16.row.col.f32.f16.f16.f32 "
        "{%0,%1,%2,%3}, {%4,%5,%6,%7}, {%8,%9}, {%0,%1,%2,%3};"
        : "+f"(d[0]), "+f"(d[1]), "+f"(d[2]), "+f"(d[3])
        : "r"(a[0]), "r"(a[1]), "r"(a[2]), "r"(a[3]), "r"(b[0]), "r"(b[1]));
}
#define CPA(dst, src) \
    asm volatile("cp.async.ca.shared.global [%0], [%1], 16;" :: "r"(dst), "l"(src))
#define CPA_COMMIT() asm volatile("cp.async.commit_group;" ::: "memory")
#define CPA_WAIT() asm volatile("cp.async.wait_group 0;" ::: "memory")

// pack 8 floats -> 8 fp16 (one uint4)
__device__ __forceinline__ uint4 pack8h(const float* f) {
    uint4 o;
    __half2 h;
    h = __floats2half2_rn(f[0], f[1]); o.x = *reinterpret_cast<unsigned*>(&h);
    h = __floats2half2_rn(f[2], f[3]); o.y = *reinterpret_cast<unsigned*>(&h);
    h = __floats2half2_rn(f[4], f[5]); o.z = *reinterpret_cast<unsigned*>(&h);
    h = __floats2half2_rn(f[6], f[7]); o.w = *reinterpret_cast<unsigned*>(&h);
    return o;
}

// ---------------- kernel 0a: fold weight matrices (emit fp16) ----------------
__global__ void fold_w_kernel(const float* __restrict__ Waf, const float* __restrict__ Wal,
                              const float* __restrict__ Wat,
                              const float* __restrict__ Wbf, const float* __restrict__ Wbl,
                              const float* __restrict__ Wbt) {
    int r = blockIdx.x;
    int c = threadIdx.x;
    const float *F, *L, *T;
    if (r < 256) { F = Waf; L = Wal; T = Wat; } else { F = Wbf; L = Wbl; T = Wbt; }
    int rr = r & 255;
    float a[5] = {0.f, 0.f, 0.f, 0.f, 0.f};
    for (int j = 0; j < 128; j++) {
        float fl = F[rr * 256 + j];
        float fr = F[rr * 256 + 128 + j];
        a[0] += fl * L[j * 128 + c];
        const float* t = &T[(j * 128 + c) * 5];
        a[0] += fr * t[0];
        a[1] += fr * t[1];
        a[2] += fr * t[2];
        a[3] += fr * t[3];
        a[4] += fr * t[4];
    }
#pragma unroll
    for (int g = 0; g < 5; g++)
        g_Wh[(g * 512 + r) * 128 + c] = __float2half_rn(a[g]);
}

// ---------------- kernel 0b: fold bias (parallel) + zero stats accumulators ----------------
__global__ void fold_c_kernel(const float* __restrict__ Waf, const float* __restrict__ bal,
                              const float* __restrict__ bat, const float* __restrict__ baf,
                              const float* __restrict__ Wbf, const float* __restrict__ bbl,
                              const float* __restrict__ bbt, const float* __restrict__ bbf) {
    int r = blockIdx.x;   // 0..511
    int t = threadIdx.x;  // 0..127
    const float *F, *lb, *tb, *fb;
    if (r < 256) { F = Waf; lb = bal; tb = bat; fb = baf; }
    else         { F = Wbf; lb = bbl; tb = bbt; fb = bbf; }
    int rr = r & 255;
    float s = F[rr * 256 + t] * lb[t] + F[rr * 256 + 128 + t] * tb[t];
    __shared__ float red[128];
    red[t] = s;
    __syncthreads();
    for (int st = 64; st > 0; st >>= 1) {
        if (t < st) red[t] += red[t + st];
        __syncthreads();
    }
    if (t == 0) {
        g_Cf[r] = red[0] + fb[rr];
        g_S[r] = 0.f; g_S[r + 512] = 0.f;
        g_S2[r] = 0.f; g_S2[r + 512] = 0.f;
    }
}

// ---------------- kernel 0c: convert stage1 weights to fp16 ----------------
__global__ void conv_w1_kernel(const float* __restrict__ Wa, const float* __restrict__ Wb) {
    int i = blockIdx.x * 256 + threadIdx.x;  // 0..32767
    const float* src = (i < 16384) ? Wa : Wb;
    g_W1h[i] = __float2half_rn(src[i & 16383]);
}

// ---------------- kernel 1: x_all via mma.sync fp16, stored transposed fp16 ----------------
// Block 256 (8 warps 2x4). Tile M=64 rows x N=128 edges, K=256 in 4 chunks of 64.
// A tile loaded via cp.async from pre-converted fp16 weights, overlapped with B chunk0 gather.
#define S1_AH  0            // 64 x 528B
#define S1_B0  33792        // 128 x 144B
#define S1_B1  52224
#define S1_TOT 70656

__global__ __launch_bounds__(256) void stage1_kernel(
    const float* __restrict__ x0, const float* __restrict__ x1,
    const float* __restrict__ ba, const float* __restrict__ bb) {
    extern __shared__ char sm1[];
    uint32_t sb = smem_u32(sm1);
    int tid = threadIdx.x;
    int lane = tid & 31, wid = tid >> 5;
    int wm = wid >> 2, wn = wid & 3;
    int e0 = blockIdx.x * 128;
    int b = blockIdx.y, half = blockIdx.z;
    const float* X = ((half == 0) ? x0 : x1) + (size_t)b * 256 * NE;
    const float* bias = (half == 0) ? ba : bb;

    int eIdx = tid & 127;
    int kbase = (tid >> 7) * 32;

    float acc[2][4][4];
#pragma unroll
    for (int mi = 0; mi < 2; mi++)
#pragma unroll
        for (int ni = 0; ni < 4; ni++)
#pragma unroll
            for (int j = 0; j < 4; j++) acc[mi][ni][j] = 0.f;

    uint32_t aOff = (uint32_t)((wm * 32 + (lane & 15)) * 528 + (lane >> 4) * 16);
    uint32_t bOff = (uint32_t)((wn * 32 + (lane & 7)) * 144 + ((lane >> 3) & 1) * 16);

    // prologue: A (weights) via cp.async from pre-converted fp16
    {
        const __half* Wh = g_W1h + (size_t)half * (64 * 256);
        for (int i = tid; i < 2048; i += 256) {
            int r = i >> 5, cq = i & 31;
            CPA(sb + S1_AH + r * 528 + cq * 16, Wh + r * 256 + cq * 8);
        }
        CPA_COMMIT();
    }

#define S1_LDG(KC, G, DST)                                                            \
    {                                                                                 \
        _Pragma("unroll") for (int j = 0; j < 8; j++)                                 \
            DST[j] = X[(size_t)((KC) * 64 + kbase + (G) * 8 + j) * NE + e0 + eIdx];   \
    }
#define S1_PST(BH, G, SRC)                                                            \
    {                                                                                 \
        int k0_ = kbase + (G) * 8;                                                    \
        *(uint4*)(sm1 + (BH) + eIdx * 144 + k0_ * 2) = pack8h(SRC);                   \
    }
#define S1_MMA(BH, KC, KK)                                                            \
    {                                                                                 \
        uint32_t ah_[2][4], bh_[4][2];                                                \
        _Pragma("unroll") for (int mi = 0; mi < 2; mi++)                              \
            ldsm4(ah_[mi], sb + S1_AH + aOff + mi * (16 * 528) + (KC) * 128 + (KK) * 32); \
        _Pragma("unroll") for (int ni = 0; ni < 4; ni++)                              \
            ldsm2(bh_[ni], sb + (BH) + bOff + ni * (8 * 144) + (KK) * 32);            \
        _Pragma("unroll") for (int mi = 0; mi < 2; mi++)                              \
            _Pragma("unroll") for (int ni = 0; ni < 4; ni++)                          \
                mma_f16(acc[mi][ni], ah_[mi], bh_[ni]);                               \
    }

    // prologue: B chunk 0 (overlaps the A cp.async)
    {
        float gf[8];
#pragma unroll
        for (int g = 0; g < 4; g++) {
            S1_LDG(0, g, gf);
            S1_PST(S1_B0, g, gf);
        }
    }
    CPA_WAIT();
    __syncthreads();

    float gfA[8], gfB[8];
#pragma unroll
    for (int kc = 0; kc < 4; kc++) {
        uint32_t BH = (kc & 1) ? S1_B1 : S1_B0;
        uint32_t BnH = (kc & 1) ? S1_B0 : S1_B1;
        if (kc < 3) { S1_LDG(kc + 1, 0, gfA); S1_LDG(kc + 1, 1, gfB); }
        S1_MMA(BH, kc, 0);
        S1_MMA(BH, kc, 1);
        if (kc < 3) {
            S1_PST(BnH, 0, gfA); S1_PST(BnH, 1, gfB);
            S1_LDG(kc + 1, 2, gfA); S1_LDG(kc + 1, 3, gfB);
        }
        S1_MMA(BH, kc, 2);
        S1_MMA(BH, kc, 3);
        if (kc < 3) { S1_PST(BnH, 2, gfA); S1_PST(BnH, 3, gfB); }
        __syncthreads();
    }

    // epilogue: bias, transpose through smem (fp32), pack fp16, coalesced store
    float* T = (float*)(sm1 + S1_B0);  // [r][e] stride 132 floats
#pragma unroll
    for (int mi = 0; mi < 2; mi++) {
        int r0 = wm * 32 + mi * 16 + (lane >> 2);
        int r1 = r0 + 8;
        float c0 = bias[r0], c1 = bias[r1];
#pragma unroll
        for (int ni = 0; ni < 4; ni++) {
            int ecol = wn * 32 + ni * 8 + (lane & 3) * 2;
            T[r0 * 132 + ecol] = acc[mi][ni][0] + c0;
            T[r0 * 132 + ecol + 1] = acc[mi][ni][1] + c0;
            T[r1 * 132 + ecol] = acc[mi][ni][2] + c1;
            T[r1 * 132 + ecol + 1] = acc[mi][ni][3] + c1;
        }
    }
    __syncthreads();
    __half* dst = g_XtH + (size_t)b * NE * 128;
    for (int i = tid; i < 1024; i += 256) {
        int e = i >> 3, seg = i & 7;
        float v[8];
#pragma unroll
        for (int j = 0; j < 8; j++) v[j] = T[(seg * 8 + j) * 132 + e];
        *(uint4*)&dst[(size_t)(e0 + e) * 128 + half * 64 + seg * 8] = pack8h(v);
    }
}

// ---------------- kernel 2: pipelined fused GEMM + stats (fp16, M=256 tile) ----------------
// Block 512 (16 warps 4m x 4n, warp tile 64x32). Tile M=256 (z half) x N=128 edges.
// 10 phases. Gathers double-loaded per phase (2 register sets), stores deferred for
// deeper LDG latency cover (legal: stores only must land before the reader's sync).
#define SM_NIDX 0
#define SM_A0   2048
#define SM_A1   38912
#define SM_BA   75776
#define SM_BB   110592
#define SM_BC   145408
#define SM_BD   180224
#define SM_TOT  215040

__global__ __launch_bounds__(512, 1) void stage2_kernel(const int* __restrict__ gemm) {
    extern __shared__ char sm2[];
    uint32_t sb = smem_u32(sm2);
    int tid = threadIdx.x;
    int lane = tid & 31, wid = tid >> 5;
    int wm = wid >> 2, wn = wid & 3;
    int e0 = blockIdx.x * 128;
    int b = blockIdx.y, z = blockIdx.z;

    int4* nidx = (int4*)(sm2 + SM_NIDX);
    const __half* XtH = g_XtH + (size_t)b * NE * 128;

    float acc[4][4][4];
#pragma unroll
    for (int mi = 0; mi < 4; mi++)
#pragma unroll
        for (int ni = 0; ni < 4; ni++)
#pragma unroll
            for (int j = 0; j < 4; j++) acc[mi][ni][j] = 0.f;

    uint32_t aOff = (uint32_t)((wm * 64 + (lane & 15)) * 144 + (lane >> 4) * 16);
    uint32_t bOff = (uint32_t)((wn * 32 + ((lane >> 4) << 3) + (lane & 7)) * 272 +
                               ((lane >> 3) & 1) * 16);

#define CPA_A(G, KHP, ABASE)                                                          \
    {                                                                                 \
        const __half* s_ = g_Wh + ((size_t)(G) * 512 + z * 256) * 128 + (KHP) * 64;   \
        _Pragma("unroll") for (int i_ = 0; i_ < 4; i_++) {                            \
            int ii_ = tid + i_ * 512;                                                 \
            int row_ = ii_ >> 3, cg_ = ii_ & 7;                                       \
            CPA(sb + (ABASE) + row_ * 144 + cg_ * 16, s_ + (size_t)row_ * 128 + cg_ * 8); \
        }                                                                             \
        CPA_COMMIT();                                                                 \
    }

    uint4 ha_, hb_, hc_, hd_;
#define LDGP_A(P, IT)                                                                 \
    {                                                                                 \
        int idx_ = tid + (IT) * 512;                                                  \
        int e_ = idx_ >> 4, cq_ = idx_ & 15;                                          \
        int4 nn_ = nidx[e_];                                                          \
        int na_ = (P) ? nn_.y : nn_.x;                                                \
        int nc_ = (P) ? nn_.w : nn_.z;                                                \
        ha_ = *(const uint4*)&XtH[(size_t)na_ * 128 + cq_ * 8];                       \
        hb_ = *(const uint4*)&XtH[(size_t)nc_ * 128 + cq_ * 8];                       \
    }
#define LDGP_B(P, IT)                                                                 \
    {                                                                                 \
        int idx_ = tid + (IT) * 512;                                                  \
        int e_ = idx_ >> 4, cq_ = idx_ & 15;                                          \
        int4 nn_ = nidx[e_];                                                          \
        int na_ = (P) ? nn_.y : nn_.x;                                                \
        int nc_ = (P) ? nn_.w : nn_.z;                                                \
        hc_ = *(const uint4*)&XtH[(size_t)na_ * 128 + cq_ * 8];                       \
        hd_ = *(const uint4*)&XtH[(size_t)nc_ * 128 + cq_ * 8];                       \
    }
#define PSTP_X(SUMB, DIFB, IT, RA, RB)                                                \
    {                                                                                 \
        int idx_ = tid + (IT) * 512;                                                  \
        int e_ = idx_ >> 4, cq_ = idx_ & 15;                                          \
        uint4 so_, do_;                                                               \
        __half2* pa_ = (__half2*)&RA;                                                 \
        __half2* pb_ = (__half2*)&RB;                                                 \
        __half2* ps_ = (__half2*)&so_;                                                \
        __half2* pd_ = (__half2*)&do_;                                                \
        _Pragma("unroll") for (int j_ = 0; j_ < 4; j_++) {                            \
            ps_[j_] = __hadd2(pa_[j_], pb_[j_]);                                      \
            pd_[j_] = __habs2(__hsub2(pa_[j_], pb_[j_]));                             \
        }                                                                             \
        *(uint4*)(sm2 + (SUMB) + e_ * 272 + cq_ * 16) = so_;                          \
        *(uint4*)(sm2 + (DIFB) + e_ * 272 + cq_ * 16) = do_;                          \
    }
#define PSTP_A(SUMB, DIFB, IT) PSTP_X(SUMB, DIFB, IT, ha_, hb_)
#define PSTP_B(SUMB, DIFB, IT) PSTP_X(SUMB, DIFB, IT, hc_, hd_)

#define MMA_STEP(ABASE, BBASE, KBA, KBB)                                              \
    {                                                                                 \
        uint32_t ah_[4][4], bb_[2][4];                                                \
        _Pragma("unroll") for (int mi = 0; mi < 4; mi++)                              \
            ldsm4(ah_[mi], sb + (ABASE) + aOff + mi * (16 * 144) + (KBA));            \
        _Pragma("unroll") for (int p = 0; p < 2; p++)                                 \
            ldsm4(bb_[p], sb + (BBASE) + bOff + p * (16 * 272) + (KBB));              \
        _Pragma("unroll") for (int mi = 0; mi < 4; mi++)                              \
            _Pragma("unroll") for (int ni = 0; ni < 4; ni++)                          \
                mma_f16(acc[mi][ni], ah_[mi], &bb_[ni >> 1][(ni & 1) * 2]);           \
    }

    // ---- prologue: A(feat0,kh0)->A0; nidx; self tile -> BA via cp.async ----
    CPA_A(0, 0, SM_A0);
    if (tid < 128) nidx[tid] = ((const int4*)gemm)[(size_t)b * NE + e0 + tid];
#pragma unroll
    for (int it = 0; it < 4; it++) {
        int ii = tid + it * 512;
        int e = ii >> 4, cq = ii & 15;
        CPA(sb + SM_BA + e * 272 + cq * 16, XtH + (size_t)(e0 + e) * 128 + cq * 8);
    }
    CPA_COMMIT();
    CPA_WAIT();
    __syncthreads();

#define PHASE(PRE, BBASE, KH, G0, G1, G2, G3)                                         \
    PRE                                                                               \
    G0                                                                                \
    MMA_STEP((KH) ? SM_A1 : SM_A0, BBASE, 0, ((KH) * 4 + 0) * 32);                    \
    MMA_STEP((KH) ? SM_A1 : SM_A0, BBASE, 32, ((KH) * 4 + 1) * 32);                   \
    G1 G2                                                                             \
    MMA_STEP((KH) ? SM_A1 : SM_A0, BBASE, 64, ((KH) * 4 + 2) * 32);                   \
    MMA_STEP((KH) ? SM_A1 : SM_A0, BBASE, 96, ((KH) * 4 + 3) * 32);                   \
    G3                                                                                \
    CPA_WAIT();                                                                       \
    __syncthreads();

    // P1-P2: self (W0); gather pair0 -> BB(sum), BC(diff); deferred stores
    PHASE(CPA_A(0, 1, SM_A1);, SM_BA, 0,
          LDGP_A(0, 0); LDGP_B(0, 1);, ;, ;, PSTP_A(SM_BB, SM_BC, 0);)
    PHASE(CPA_A(1, 0, SM_A0);, SM_BA, 1,
          PSTP_B(SM_BB, SM_BC, 1); LDGP_A(0, 2); LDGP_B(0, 3);, ;,
          PSTP_A(SM_BB, SM_BC, 2);, PSTP_B(SM_BB, SM_BC, 3);)
    // P3-P4: sum0 (W1); gather pair1 -> BD(sum), BA(diff)
    PHASE(CPA_A(1, 1, SM_A1);, SM_BB, 0,
          LDGP_A(1, 0); LDGP_B(1, 1);, ;, ;, PSTP_A(SM_BD, SM_BA, 0);)
    PHASE(CPA_A(3, 0, SM_A0);, SM_BB, 1,
          PSTP_B(SM_BD, SM_BA, 1); LDGP_A(1, 2); LDGP_B(1, 3);, ;,
          PSTP_A(SM_BD, SM_BA, 2);, PSTP_B(SM_BD, SM_BA, 3);)
    // P5-P6: diff0 (W3)
    PHASE(CPA_A(3, 1, SM_A1);, SM_BC, 0, ;, ;, ;, ;)
    PHASE(CPA_A(2, 0, SM_A0);, SM_BC, 1, ;, ;, ;, ;)
    // P7-P8: sum1 (W2)
    PHASE(CPA_A(2, 1, SM_A1);, SM_BD, 0, ;, ;, ;, ;)
    PHASE(CPA_A(4, 0, SM_A0);, SM_BD, 1, ;, ;, ;, ;)
    // P9-P10: diff1 (W4, in BA)
    PHASE(CPA_A(4, 1, SM_A1);, SM_BA, 0, ;, ;, ;, ;)
    PHASE(;, SM_BA, 1, ;, ;, ;, ;)

    // ---- epilogue: bias + fp16 store + row stats ----
    float* sAcc = (float*)sm2;
    for (int i = tid; i < 512; i += 512) sAcc[i] = 0.f;
    __syncthreads();

    int rbase = z * 256 + wm * 64;
    int colLocal = wn * 32 + (lane & 3) * 2;
#pragma unroll
    for (int mi = 0; mi < 4; mi++) {
        int r0 = rbase + mi * 16 + (lane >> 2);
        int r1 = r0 + 8;
        float c0 = g_Cf[r0], c1 = g_Cf[r1];
        __half* d0 = g_preH + ((size_t)b * 512 + r0) * NE + e0 + colLocal;
        __half* d1 = g_preH + ((size_t)b * 512 + r1) * NE + e0 + colLocal;
        float s0 = 0.f, q0 = 0.f, s1 = 0.f, q1 = 0.f;
#pragma unroll
        for (int ni = 0; ni < 4; ni++) {
            float v00 = acc[mi][ni][0] + c0, v01 = acc[mi][ni][1] + c0;
            float v10 = acc[mi][ni][2] + c1, v11 = acc[mi][ni][3] + c1;
            *(__half2*)(d0 + ni * 8) = __floats2half2_rn(v00, v01);
            *(__half2*)(d1 + ni * 8) = __floats2half2_rn(v10, v11);
            s0 += v00 + v01; q0 += v00 * v00 + v01 * v01;
            s1 += v10 + v11; q1 += v10 * v10 + v11 * v11;
        }
#pragma unroll
        for (int o = 1; o <= 2; o <<= 1) {
            s0 += __shfl_xor_sync(0xFFFFFFFFu, s0, o);
            q0 += __shfl_xor_sync(0xFFFFFFFFu, q0, o);
            s1 += __shfl_xor_sync(0xFFFFFFFFu, s1, o);
            q1 += __shfl_xor_sync(0xFFFFFFFFu, q1, o);
        }
        if ((lane & 3) == 0) {
            int rl0 = wm * 64 + mi * 16 + (lane >> 2);
            atomicAdd(&sAcc[rl0 * 2], s0);
            atomicAdd(&sAcc[rl0 * 2 + 1], q0);
            atomicAdd(&sAcc[(rl0 + 8) * 2], s1);
            atomicAdd(&sAcc[(rl0 + 8) * 2 + 1], q1);
        }
    }
    __syncthreads();
    for (int i = tid; i < 512; i += 512) {
        int rowl = i >> 1;
        int gidx = b * 512 + z * 256 + rowl;
        if (i & 1) atomicAdd(&g_S2[gidx], sAcc[i]);
        else       atomicAdd(&g_S[gidx], sAcc[i]);
    }
}

// ---------------- kernel 3: finalize instance-norm stats ----------------
__global__ void stats_finalize() {
    int i = blockIdx.x * 256 + threadIdx.x;
    float mean = g_S[i] / (float)NE;
    float var = g_S2[i] / (float)NE - mean * mean;
    g_mean[i] = mean;
    g_rstd[i] = rsqrtf(var + 1e-5f);
}

// ---------------- kernel 4: fused norm + sigmoid + softmax blend ----------------
__global__ __launch_bounds__(256) void final_kernel(const float* __restrict__ x0,
                                                    const float* __restrict__ x1,
                                                    float* __restrict__ out) {
    size_t idx = (size_t)blockIdx.x * 256 + threadIdx.x;
    int e4 = (int)(idx & (NE / 4 - 1));
    int c = (int)((idx >> 14) & 255);
    int b = (int)(idx >> 22);

    uint2 pau = *(const uint2*)&g_preH[((size_t)b * 512 + c) * NE + e4 * 4];
    uint2 pbu = *(const uint2*)&g_preH[((size_t)b * 512 + 256 + c) * NE + e4 * 4];
    float2 pa01 = __half22float2(*(__half2*)&pau.x);
    float2 pa23 = __half22float2(*(__half2*)&pau.y);
    float2 pb01 = __half22float2(*(__half2*)&pbu.x);
    float2 pb23 = __half22float2(*(__half2*)&pbu.y);
    float4 pa = make_float4(pa01.x, pa01.y, pa23.x, pa23.y);
    float4 pb = make_float4(pb01.x, pb01.y, pb23.x, pb23.y);
    float4 a0 = ((const float4*)x0)[idx];
    float4 a1 = ((const float4*)x1)[idx];

    float ma = g_mean[b * 512 + c], ra = g_rstd[b * 512 + c];
    float mb = g_mean[b * 512 + 256 + c], rb = g_rstd[b * 512 + 256 + c];

    float4 o;
#define BLEND(fld)                                              \
    {                                                           \
        float za = (pa.fld - ma) * ra;                          \
        float zb = (pb.fld - mb) * rb;                          \
        float wa = 1.f / (1.f + expf(-za));                     \
        float wb = 1.f / (1.f + expf(-zb));                     \
        float w0 = 1.f / (1.f + expf(wb - wa));                 \
        o.fld = a0.fld * w0 + a1.fld * (1.f - w0);              \
    }
    BLEND(x); BLEND(y); BLEND(z); BLEND(w);
#undef BLEND
    ((float4*)out)[idx] = o;
}

// ---------------- launch ----------------
extern "C" void kernel_launch(void* const* d_in, const int* in_sizes, int n_in,
                              void* d_out, int out_size) {
    const float* x0  = (const float*)d_in[0];
    const float* x1  = (const float*)d_in[1];
    const int*   gm  = (const int*)d_in[2];
    const float* Wa  = (const float*)d_in[3];
    const float* ba  = (const float*)d_in[4];
    const float* Wb  = (const float*)d_in[5];
    const float* bb  = (const float*)d_in[6];
    const float* Wal = (const float*)d_in[7];
    const float* bal = (const float*)d_in[8];
    const float* Wbl = (const float*)d_in[9];
    const float* bbl = (const float*)d_in[10];
    const float* Wat = (const float*)d_in[11];
    const float* bat = (const float*)d_in[12];
    const float* Wbt = (const float*)d_in[13];
    const float* bbt = (const float*)d_in[14];
    const float* Waf = (const float*)d_in[15];
    const float* baf = (const float*)d_in[16];
    const float* Wbf = (const float*)d_in[17];
    const float* bbf = (const float*)d_in[18];
    float* out = (float*)d_out;

    conv_w1_kernel<<<128, 256>>>(Wa, Wb);
    fold_w_kernel<<<512, 128>>>(Waf, Wal, Wat, Wbf, Wbl, Wbt);
    fold_c_kernel<<<512, 128>>>(Waf, bal, bat, baf, Wbf, bbl, bbt, bbf);

    cudaFuncSetAttribute(stage1_kernel, cudaFuncAttributeMaxDynamicSharedMemorySize, S1_TOT);
    stage1_kernel<<<dim3(NE / 128, NB, 2), 256, S1_TOT>>>(x0, x1, ba, bb);

    cudaFuncSetAttribute(stage2_kernel, cudaFuncAttributeMaxDynamicSharedMemorySize, SM_TOT);
    stage2_kernel<<<dim3(NE / 128, NB, 2), 512, SM_TOT>>>(gm);

    stats_finalize<<<4, 256>>>();

    final_kernel<<<(NB * 256 * (NE / 4)) / 256, 256>>>(x0, x1, out);
}